// round 2
// baseline (speedup 1.0000x reference)
#include <cuda_runtime.h>
#include <math.h>

// Problem constants
#define B_  4
#define T_  2048
#define C_  1024
#define H_  16
#define HS_ 64
#define M_  (B_*T_)      // 8192 rows
#define NT_ (T_/64)      // 32 tiles of 64

// ---------------------------------------------------------------------------
// Scratch (device globals; no runtime allocation allowed)
// ---------------------------------------------------------------------------
__device__ float g_h   [M_*C_];            // LN output (reused for LN1 and LN2)
__device__ float g_qkv [M_*3*C_];          // QKV
__device__ float g_y   [M_*C_];            // attention output (B,T,C)
__device__ float g_m   [B_*H_*T_];         // per-row softmax max (scaled scores)
__device__ float g_l   [B_*H_*T_];         // per-row softmax denom
__device__ float g_impH[B_*H_*T_];         // per-head importance column sums
__device__ float g_cm  [M_];               // combined mask per token
__device__ float g_xres[M_*C_];            // x after attn residual + prune mask
__device__ float g_fc  [M_*4*C_];          // MLP hidden

// ---------------------------------------------------------------------------
// LayerNorm: one block (256 thr) per row of C=1024, 4 elems/thread
// ---------------------------------------------------------------------------
__global__ __launch_bounds__(256) void ln_kernel(
    const float* __restrict__ x, const float* __restrict__ w,
    const float* __restrict__ bias, float* __restrict__ out)
{
    int row = blockIdx.x;
    int tid = threadIdx.x;
    const float* xr = x + (size_t)row * C_;
    float4 v = *(const float4*)(xr + tid * 4);
    float s1 = v.x + v.y + v.z + v.w;
    float s2 = v.x*v.x + v.y*v.y + v.z*v.z + v.w*v.w;
#pragma unroll
    for (int o = 16; o; o >>= 1) {
        s1 += __shfl_xor_sync(0xffffffffu, s1, o);
        s2 += __shfl_xor_sync(0xffffffffu, s2, o);
    }
    __shared__ float sh1[8], sh2[8];
    int wi = tid >> 5;
    if ((tid & 31) == 0) { sh1[wi] = s1; sh2[wi] = s2; }
    __syncthreads();
    float t1 = 0.f, t2 = 0.f;
#pragma unroll
    for (int i = 0; i < 8; i++) { t1 += sh1[i]; t2 += sh2[i]; }
    float mean = t1 * (1.f / C_);
    float var  = t2 * (1.f / C_) - mean * mean;
    float inv  = rsqrtf(var + 1e-5f);
    float4 wv = *(const float4*)(w + tid * 4);
    float4 bv = *(const float4*)(bias + tid * 4);
    float4 o;
    o.x = (v.x - mean) * inv * wv.x + bv.x;
    o.y = (v.y - mean) * inv * wv.y + bv.y;
    o.z = (v.z - mean) * inv * wv.z + bv.z;
    o.w = (v.w - mean) * inv * wv.w + bv.w;
    *(float4*)(out + (size_t)row * C_ + tid * 4) = o;
}

// ---------------------------------------------------------------------------
// NT GEMM: Out[M,N] = A[M,K] @ W[N,K]^T (+bias, + epilogue)
// EPI 0: bias only
// EPI 1: bias + exact GELU
// EPI 2: (res + bias + acc) * rowmask[row]          (attn residual + prune)
// EPI 3: res + bias + acc                            (MLP residual -> d_out)
// 128x128 block tile, BK=16, 256 threads, 8x8 per thread.
// All dims assumed multiples of 128/16 (true here).
// ---------------------------------------------------------------------------
template<int EPI>
__global__ __launch_bounds__(256) void gemm_nt(
    const float* __restrict__ A, const float* __restrict__ W,
    const float* __restrict__ bias, float* __restrict__ Out,
    int Ndim, int Kdim,
    const float* __restrict__ res, const float* __restrict__ rowmask)
{
    __shared__ __align__(16) float As[16][132];
    __shared__ __align__(16) float Ws[16][132];
    const int tid = threadIdx.x;
    const int tx = tid & 15, ty = tid >> 4;
    const int row0 = blockIdx.y * 128, col0 = blockIdx.x * 128;

    float acc[8][8];
#pragma unroll
    for (int i = 0; i < 8; i++)
#pragma unroll
        for (int j = 0; j < 8; j++) acc[i][j] = 0.f;

    for (int k0 = 0; k0 < Kdim; k0 += 16) {
#pragma unroll
        for (int i = 0; i < 2; i++) {
            int e  = i * 256 + tid;        // 0..511 float4 slots
            int r  = e >> 2;               // 0..127 tile row
            int cg = (e & 3) << 2;         // 0,4,8,12 k-subcol
            float4 va = *(const float4*)(A + (size_t)(row0 + r) * Kdim + k0 + cg);
            As[cg+0][r] = va.x; As[cg+1][r] = va.y; As[cg+2][r] = va.z; As[cg+3][r] = va.w;
            float4 vw = *(const float4*)(W + (size_t)(col0 + r) * Kdim + k0 + cg);
            Ws[cg+0][r] = vw.x; Ws[cg+1][r] = vw.y; Ws[cg+2][r] = vw.z; Ws[cg+3][r] = vw.w;
        }
        __syncthreads();
#pragma unroll
        for (int k = 0; k < 16; k++) {
            float a[8], w[8];
            *(float4*)&a[0] = *(const float4*)&As[k][ty * 8];
            *(float4*)&a[4] = *(const float4*)&As[k][ty * 8 + 4];
            *(float4*)&w[0] = *(const float4*)&Ws[k][tx * 8];
            *(float4*)&w[4] = *(const float4*)&Ws[k][tx * 8 + 4];
#pragma unroll
            for (int i = 0; i < 8; i++)
#pragma unroll
                for (int j = 0; j < 8; j++) acc[i][j] += a[i] * w[j];
        }
        __syncthreads();
    }

#pragma unroll
    for (int i = 0; i < 8; i++) {
        int r = row0 + ty * 8 + i;
        float rmv = (EPI == 2) ? rowmask[r] : 0.f;
#pragma unroll
        for (int jj = 0; jj < 8; jj += 4) {
            int c = col0 + tx * 8 + jj;
            float4 bb = *(const float4*)(bias + c);
            float4 o;
            o.x = acc[i][jj+0] + bb.x;
            o.y = acc[i][jj+1] + bb.y;
            o.z = acc[i][jj+2] + bb.z;
            o.w = acc[i][jj+3] + bb.w;
            if (EPI == 1) {
                o.x = 0.5f * o.x * (1.f + erff(o.x * 0.7071067811865476f));
                o.y = 0.5f * o.y * (1.f + erff(o.y * 0.7071067811865476f));
                o.z = 0.5f * o.z * (1.f + erff(o.z * 0.7071067811865476f));
                o.w = 0.5f * o.w * (1.f + erff(o.w * 0.7071067811865476f));
            } else if (EPI == 2) {
                float4 rr = *(const float4*)(res + (size_t)r * Ndim + c);
                o.x = (rr.x + o.x) * rmv;
                o.y = (rr.y + o.y) * rmv;
                o.z = (rr.z + o.z) * rmv;
                o.w = (rr.w + o.w) * rmv;
            } else if (EPI == 3) {
                float4 rr = *(const float4*)(res + (size_t)r * Ndim + c);
                o.x += rr.x; o.y += rr.y; o.z += rr.z; o.w += rr.w;
            }
            *(float4*)(Out + (size_t)r * Ndim + c) = o;
        }
    }
}

// ---------------------------------------------------------------------------
// Tile loaders for attention (64 rows x 64 dims)
// load_tile_T: stores transposed [d][row] with row-stride 68
// ---------------------------------------------------------------------------
__device__ __forceinline__ void load_tile_T(const float* __restrict__ g, int rowStride,
                                            float* __restrict__ sdst, int tid)
{
#pragma unroll
    for (int i = 0; i < 4; i++) {
        int e  = i * 256 + tid;        // 0..1023 float4 slots
        int r  = e >> 4;               // tile row 0..63
        int dg = (e & 15) << 2;        // dim group 0..60
        float4 v = *(const float4*)(g + (size_t)r * rowStride + dg);
        sdst[(dg+0)*68 + r] = v.x;
        sdst[(dg+1)*68 + r] = v.y;
        sdst[(dg+2)*68 + r] = v.z;
        sdst[(dg+3)*68 + r] = v.w;
    }
}

// ---------------------------------------------------------------------------
// Flash attention (one pass): block = 64 queries for one (b,h).
// 256 threads as 16x16 grid; each thread owns 4 q-rows x 4 cols.
// Stores y into (B,T,C) layout and per-row (m,l) for the importance pass.
// ---------------------------------------------------------------------------
__global__ __launch_bounds__(256) void attn_kernel(
    const float* __restrict__ qkv, const float* __restrict__ attmask,
    float* __restrict__ y, float* __restrict__ gm, float* __restrict__ gl)
{
    extern __shared__ __align__(16) float sm[];
    float* Qst = sm;                  // [64 d][68] (transposed)
    float* Kst = sm + 64 * 68;        // [64 d][68] (transposed)
    float* Vs  = sm + 2 * 64 * 68;    // [64 k][68] (row-major)
    float* Ps  = sm + 3 * 64 * 68;    // [64 q][65]

    const int bh = blockIdx.y, b = bh >> 4, h = bh & 15;
    const int qt = blockIdx.x;
    const int tid = threadIdx.x;
    const int tx = tid & 15, ty = tid >> 4;
    const float scale = 0.125f;       // 1/sqrt(64)

    const float* qbase = qkv + ((size_t)(b * T_ + qt * 64)) * (3 * C_) + h * 64;
    load_tile_T(qbase, 3 * C_, Qst, tid);

    float m_[4], l_[4], acc[4][4];
#pragma unroll
    for (int i = 0; i < 4; i++) {
        m_[i] = -INFINITY; l_[i] = 0.f;
#pragma unroll
        for (int j = 0; j < 4; j++) acc[i][j] = 0.f;
    }

    for (int kt = 0; kt <= qt; kt++) {
        __syncthreads();
        const float* kb = qkv + ((size_t)(b * T_ + kt * 64)) * (3 * C_) + C_ + h * 64;
        const float* vb = kb + C_;
        load_tile_T(kb, 3 * C_, Kst, tid);
#pragma unroll
        for (int i2 = 0; i2 < 4; i2++) {
            int e = i2 * 256 + tid; int r = e >> 4; int dg = (e & 15) << 2;
            *(float4*)&Vs[r * 68 + dg] = *(const float4*)(vb + (size_t)r * (3 * C_) + dg);
        }
        __syncthreads();

        float s[4][4];
#pragma unroll
        for (int i = 0; i < 4; i++)
#pragma unroll
            for (int j = 0; j < 4; j++) s[i][j] = 0.f;
#pragma unroll 8
        for (int d = 0; d < 64; d++) {
            float4 qv = *(const float4*)&Qst[d * 68 + ty * 4];
            float4 kv = *(const float4*)&Kst[d * 68 + tx * 4];
            float qa[4] = {qv.x, qv.y, qv.z, qv.w};
            float ka[4] = {kv.x, kv.y, kv.z, kv.w};
#pragma unroll
            for (int i = 0; i < 4; i++)
#pragma unroll
                for (int j = 0; j < 4; j++) s[i][j] += qa[i] * ka[j];
        }

        float am[4];
#pragma unroll
        for (int j = 0; j < 4; j++) am[j] = attmask[b * T_ + kt * 64 + tx * 4 + j];
#pragma unroll
        for (int i = 0; i < 4; i++) {
            int qg = qt * 64 + ty * 4 + i;
#pragma unroll
            for (int j = 0; j < 4; j++) {
                int kg = kt * 64 + tx * 4 + j;
                float sv = s[i][j] * scale;
                if (kg > qg || am[j] == 0.f) sv = -INFINITY;
                s[i][j] = sv;
            }
        }
#pragma unroll
        for (int i = 0; i < 4; i++) {
            float rm = fmaxf(fmaxf(s[i][0], s[i][1]), fmaxf(s[i][2], s[i][3]));
#pragma unroll
            for (int o = 1; o < 16; o <<= 1)
                rm = fmaxf(rm, __shfl_xor_sync(0xffffffffu, rm, o, 16));
            float mn = fmaxf(m_[i], rm);
            float alpha = (mn > m_[i]) ? __expf(m_[i] - mn) : 1.f;
            float psum = 0.f;
#pragma unroll
            for (int j = 0; j < 4; j++) {
                float p = (s[i][j] == -INFINITY) ? 0.f : __expf(s[i][j] - mn);
                Ps[(ty * 4 + i) * 65 + tx * 4 + j] = p;
                psum += p;
            }
#pragma unroll
            for (int o = 1; o < 16; o <<= 1)
                psum += __shfl_xor_sync(0xffffffffu, psum, o, 16);
            l_[i] = l_[i] * alpha + psum;
            m_[i] = mn;
#pragma unroll
            for (int j = 0; j < 4; j++) acc[i][j] *= alpha;
        }
        __syncthreads();

#pragma unroll 8
        for (int k = 0; k < 64; k++) {
            float4 vv = *(const float4*)&Vs[k * 68 + tx * 4];
#pragma unroll
            for (int i = 0; i < 4; i++) {
                float p = Ps[(ty * 4 + i) * 65 + k];
                acc[i][0] += p * vv.x; acc[i][1] += p * vv.y;
                acc[i][2] += p * vv.z; acc[i][3] += p * vv.w;
            }
        }
    }

#pragma unroll
    for (int i = 0; i < 4; i++) {
        int qg = qt * 64 + ty * 4 + i;
        float inv = 1.f / l_[i];
        float* yo = y + ((size_t)(b * T_ + qg)) * C_ + h * 64 + tx * 4;
        yo[0] = acc[i][0] * inv; yo[1] = acc[i][1] * inv;
        yo[2] = acc[i][2] * inv; yo[3] = acc[i][3] * inv;
        if (tx == 0) { gm[bh * T_ + qg] = m_[i]; gl[bh * T_ + qg] = l_[i]; }
    }
}

// ---------------------------------------------------------------------------
// Importance pass: for each (b,h,k-tile) recompute scores against all q>=k,
// normalize with stored (m,l), accumulate column sums DETERMINISTICALLY
// (each block owns 64 distinct k; heads summed later in fixed order).
// ---------------------------------------------------------------------------
__global__ __launch_bounds__(256) void imp_kernel(
    const float* __restrict__ qkv, const float* __restrict__ attmask,
    const float* __restrict__ gm, const float* __restrict__ gl,
    float* __restrict__ impH)
{
    __shared__ __align__(16) float Kst[64 * 68];
    __shared__ __align__(16) float Qst[64 * 68];
    const int bh = blockIdx.y, b = bh >> 4, h = bh & 15;
    const int kt = blockIdx.x;
    const int tid = threadIdx.x, tx = tid & 15, ty = tid >> 4;
    const float scale = 0.125f;

    const float* kb = qkv + ((size_t)(b * T_ + kt * 64)) * (3 * C_) + C_ + h * 64;
    load_tile_T(kb, 3 * C_, Kst, tid);

    float am[4];
#pragma unroll
    for (int i = 0; i < 4; i++) am[i] = attmask[b * T_ + kt * 64 + ty * 4 + i];
    float impacc[4] = {0.f, 0.f, 0.f, 0.f};

    for (int qt = kt; qt < NT_; qt++) {
        __syncthreads();
        load_tile_T(qkv + ((size_t)(b * T_ + qt * 64)) * (3 * C_) + h * 64, 3 * C_, Qst, tid);
        __syncthreads();

        float s[4][4];
#pragma unroll
        for (int i = 0; i < 4; i++)
#pragma unroll
            for (int j = 0; j < 4; j++) s[i][j] = 0.f;
#pragma unroll 8
        for (int d = 0; d < 64; d++) {
            float4 kv = *(const float4*)&Kst[d * 68 + ty * 4];
            float4 qv = *(const float4*)&Qst[d * 68 + tx * 4];
            float ka[4] = {kv.x, kv.y, kv.z, kv.w};
            float qa[4] = {qv.x, qv.y, qv.z, qv.w};
#pragma unroll
            for (int i = 0; i < 4; i++)
#pragma unroll
                for (int j = 0; j < 4; j++) s[i][j] += ka[i] * qa[j];
        }
        float mq[4], lq[4];
#pragma unroll
        for (int j = 0; j < 4; j++) {
            int qg = qt * 64 + tx * 4 + j;
            mq[j] = gm[bh * T_ + qg];
            lq[j] = gl[bh * T_ + qg];
        }
#pragma unroll
        for (int i = 0; i < 4; i++) {
            int kg = kt * 64 + ty * 4 + i;
            if (am[i] == 0.f) continue;
#pragma unroll
            for (int j = 0; j < 4; j++) {
                int qg = qt * 64 + tx * 4 + j;
                if (qg >= kg)
                    impacc[i] += __expf(s[i][j] * scale - mq[j]) / lq[j];
            }
        }
    }
#pragma unroll
    for (int i = 0; i < 4; i++) {
#pragma unroll
        for (int o = 1; o < 16; o <<= 1)
            impacc[i] += __shfl_xor_sync(0xffffffffu, impacc[i], o, 16);
    }
    if (tx == 0) {
#pragma unroll
        for (int i = 0; i < 4; i++)
            impH[bh * T_ + kt * 64 + ty * 4 + i] = impacc[i];
    }
}

// ---------------------------------------------------------------------------
// Finalize pruning mask (deterministic head sum), write mask + loss to output
// ---------------------------------------------------------------------------
__global__ __launch_bounds__(256) void finalize_mask(
    const float* __restrict__ impH, const float* __restrict__ attmask,
    const float* __restrict__ prot, const float* __restrict__ thresh,
    float* __restrict__ cm, float* __restrict__ out_mask,
    float* __restrict__ out_loss)
{
    int i = blockIdx.x * 256 + threadIdx.x;
    int b = i / T_, t = i % T_;
    float s = 0.f;
#pragma unroll
    for (int h = 0; h < H_; h++) s += impH[(b * H_ + h) * T_ + t];
    float imp = s * (1.f / ((float)H_ * (float)T_));
    float pm = (imp >= thresh[0]) ? 1.f : 0.f;
    if (prot[i] > 0.f) pm = 1.f;
    float c = attmask[i] * pm;
    cm[i] = c;
    out_mask[i] = c;
    if (i == 0) out_loss[0] = 0.f;
}

// ---------------------------------------------------------------------------
// Launch
// ---------------------------------------------------------------------------
extern "C" void kernel_launch(void* const* d_in, const int* in_sizes, int n_in,
                              void* d_out, int out_size)
{
    const float* x              = (const float*)d_in[0];
    const float* attention_mask = (const float*)d_in[1];
    const float* protected_mask = (const float*)d_in[2];
    const float* ln1_w          = (const float*)d_in[3];
    const float* ln1_b          = (const float*)d_in[4];
    const float* c_attn_w       = (const float*)d_in[5];
    const float* c_attn_b       = (const float*)d_in[6];
    const float* c_proj_w       = (const float*)d_in[7];
    const float* c_proj_b       = (const float*)d_in[8];
    const float* ln2_w          = (const float*)d_in[9];
    const float* ln2_b          = (const float*)d_in[10];
    const float* fc_w           = (const float*)d_in[11];
    const float* fc_b           = (const float*)d_in[12];
    const float* fcproj_w       = (const float*)d_in[13];
    const float* fcproj_b       = (const float*)d_in[14];
    const float* threshold      = (const float*)d_in[15];

    float* out      = (float*)d_out;
    float* out_mask = out + (size_t)M_ * C_;
    float* out_loss = out_mask + M_;

    float *p_h, *p_qkv, *p_y, *p_m, *p_l, *p_imp, *p_cm, *p_xres, *p_fc;
    cudaGetSymbolAddress((void**)&p_h,    g_h);
    cudaGetSymbolAddress((void**)&p_qkv,  g_qkv);
    cudaGetSymbolAddress((void**)&p_y,    g_y);
    cudaGetSymbolAddress((void**)&p_m,    g_m);
    cudaGetSymbolAddress((void**)&p_l,    g_l);
    cudaGetSymbolAddress((void**)&p_imp,  g_impH);
    cudaGetSymbolAddress((void**)&p_cm,   g_cm);
    cudaGetSymbolAddress((void**)&p_xres, g_xres);
    cudaGetSymbolAddress((void**)&p_fc,   g_fc);

    const size_t attn_smem = (size_t)(3 * 64 * 68 + 64 * 65) * sizeof(float); // 68864B
    cudaFuncSetAttribute(attn_kernel, cudaFuncAttributeMaxDynamicSharedMemorySize,
                         (int)attn_smem);

    // 1. LN1
    ln_kernel<<<M_, 256>>>(x, ln1_w, ln1_b, p_h);
    // 2. QKV = h @ c_attn_w^T + b   (8192 x 3072 x 1024)
    gemm_nt<0><<<dim3(3 * C_ / 128, M_ / 128), 256>>>(
        p_h, c_attn_w, c_attn_b, p_qkv, 3 * C_, C_, nullptr, nullptr);
    // 3. Flash attention -> y, (m,l)
    attn_kernel<<<dim3(NT_, B_ * H_), 256, attn_smem>>>(
        p_qkv, attention_mask, p_y, p_m, p_l);
    // 4. Importance column sums per head (deterministic)
    imp_kernel<<<dim3(NT_, B_ * H_), 256>>>(p_qkv, attention_mask, p_m, p_l, p_imp);
    // 5. Combined mask -> g_cm and output region
    finalize_mask<<<M_ / 256, 256>>>(p_imp, attention_mask, protected_mask,
                                     threshold, p_cm, out_mask, out_loss);
    // 6. proj + residual + prune mask: xres = (x + y@Wp^T + b) * cm[row]
    gemm_nt<2><<<dim3(C_ / 128, M_ / 128), 256>>>(
        p_y, c_proj_w, c_proj_b, p_xres, C_, C_, x, p_cm);
    // 7. LN2
    ln_kernel<<<M_, 256>>>(p_xres, ln2_w, ln2_b, p_h);
    // 8. fc + GELU  (8192 x 4096 x 1024)
    gemm_nt<1><<<dim3(4 * C_ / 128, M_ / 128), 256>>>(
        p_h, fc_w, fc_b, p_fc, 4 * C_, C_, nullptr, nullptr);
    // 9. fcproj + residual -> d_out x region  (8192 x 1024 x 4096)
    gemm_nt<3><<<dim3(C_ / 128, M_ / 128), 256>>>(
        p_fc, fcproj_w, fcproj_b, out, C_, 4 * C_, p_xres, nullptr);
}

// round 7
// speedup vs baseline: 1.5818x; 1.5818x over previous
#include <cuda_runtime.h>
#include <math.h>
#include <stdint.h>

// Problem constants
#define B_  4
#define T_  2048
#define C_  1024
#define H_  16
#define HS_ 64
#define M_  (B_*T_)      // 8192 rows
#define NT_ (T_/64)      // 32 tiles of 64

// ---------------------------------------------------------------------------
// Scratch (device globals; no runtime allocation allowed)
// ---------------------------------------------------------------------------
__device__ float g_h   [M_*C_];            // LN output (reused for LN1 and LN2)
__device__ float g_qkv [M_*3*C_];          // QKV
__device__ float g_y   [M_*C_];            // attention output (B,T,C)
__device__ float g_m   [B_*H_*T_];         // per-row softmax max (scaled scores)
__device__ float g_l   [B_*H_*T_];         // per-row softmax denom
__device__ float g_impH[B_*H_*T_];         // per-head importance column sums
__device__ float g_cm  [M_];               // combined mask per token
__device__ float g_xres[M_*C_];            // x after attn residual + prune mask
__device__ float g_fc  [M_*4*C_];          // MLP hidden

// ---------------------------------------------------------------------------
// LayerNorm: one block (256 thr) per row of C=1024, 4 elems/thread
// ---------------------------------------------------------------------------
__global__ __launch_bounds__(256) void ln_kernel(
    const float* __restrict__ x, const float* __restrict__ w,
    const float* __restrict__ bias, float* __restrict__ out)
{
    int row = blockIdx.x;
    int tid = threadIdx.x;
    const float* xr = x + (size_t)row * C_;
    float4 v = *(const float4*)(xr + tid * 4);
    float s1 = v.x + v.y + v.z + v.w;
    float s2 = v.x*v.x + v.y*v.y + v.z*v.z + v.w*v.w;
#pragma unroll
    for (int o = 16; o; o >>= 1) {
        s1 += __shfl_xor_sync(0xffffffffu, s1, o);
        s2 += __shfl_xor_sync(0xffffffffu, s2, o);
    }
    __shared__ float sh1[8], sh2[8];
    int wi = tid >> 5;
    if ((tid & 31) == 0) { sh1[wi] = s1; sh2[wi] = s2; }
    __syncthreads();
    float t1 = 0.f, t2 = 0.f;
#pragma unroll
    for (int i = 0; i < 8; i++) { t1 += sh1[i]; t2 += sh2[i]; }
    float mean = t1 * (1.f / C_);
    float var  = t2 * (1.f / C_) - mean * mean;
    float inv  = rsqrtf(var + 1e-5f);
    float4 wv = *(const float4*)(w + tid * 4);
    float4 bv = *(const float4*)(bias + tid * 4);
    float4 o;
    o.x = (v.x - mean) * inv * wv.x + bv.x;
    o.y = (v.y - mean) * inv * wv.y + bv.y;
    o.z = (v.z - mean) * inv * wv.z + bv.z;
    o.w = (v.w - mean) * inv * wv.w + bv.w;
    *(float4*)(out + (size_t)row * C_ + tid * 4) = o;
}

// ---------------------------------------------------------------------------
// Tensor-core TF32 GEMM helpers
// ---------------------------------------------------------------------------
__device__ __forceinline__ uint32_t cvt_tf32(float x) {
    uint32_t r; asm("cvt.rna.tf32.f32 %0, %1;" : "=r"(r) : "f"(x)); return r;
}
__device__ __forceinline__ void mma_tf32(float* c,
    uint32_t a0, uint32_t a1, uint32_t a2, uint32_t a3,
    uint32_t b0, uint32_t b1)
{
    asm volatile(
        "mma.sync.aligned.m16n8k8.row.col.f32.tf32.tf32.f32 "
        "{%0,%1,%2,%3}, {%4,%5,%6,%7}, {%8,%9}, {%0,%1,%2,%3};"
        : "+f"(c[0]), "+f"(c[1]), "+f"(c[2]), "+f"(c[3])
        : "r"(a0), "r"(a1), "r"(a2), "r"(a3), "r"(b0), "r"(b1));
}

// ---------------------------------------------------------------------------
// TF32 tensor-core GEMM: Out[M,N] = A[M,K] @ W[N,K]^T (+bias, +epilogue)
// EPI 0: bias only
// EPI 1: bias + exact GELU
// EPI 2: (res + bias + acc) * rowmask[row]
// EPI 3: res + bias + acc
// PREC 0: single TF32 (rna-converted)  | PREC 1: 3xTF32 split (~fp32 accuracy)
// 128x128 block, BK=32, 256 threads (8 warps, each 64x32 via m16n8k8).
// Synchronous smem loads (no cp.async), static shared memory only.
// ---------------------------------------------------------------------------
#define GSTRIDE 36

template<int EPI, int PREC>
__global__ __launch_bounds__(256) void gemm_tc(
    const float* __restrict__ A, const float* __restrict__ W,
    const float* __restrict__ bias, float* __restrict__ Out,
    int Ndim, int Kdim,
    const float* __restrict__ res, const float* __restrict__ rowmask)
{
    __shared__ __align__(16) float Sa[128 * GSTRIDE];
    __shared__ __align__(16) float Sw[128 * GSTRIDE];
    const int tid = threadIdx.x;
    const int row0 = blockIdx.y * 128, col0 = blockIdx.x * 128;

    const int wid  = tid >> 5, lane = tid & 31;
    const int g    = lane >> 2, tg = lane & 3;
    const int wr   = (wid >> 2) * 64;   // warp row offset: 0 / 64
    const int wc   = (wid & 3) * 32;    // warp col offset: 0/32/64/96

    float acc[4][4][4];
#pragma unroll
    for (int mt = 0; mt < 4; mt++)
#pragma unroll
        for (int nt = 0; nt < 4; nt++)
#pragma unroll
            for (int i = 0; i < 4; i++) acc[mt][nt][i] = 0.f;

    for (int k0 = 0; k0 < Kdim; k0 += 32) {
        // Synchronous tile load: 128 rows x 32 k, float4 granules
#pragma unroll
        for (int i = 0; i < 4; i++) {
            int slot = i * 256 + tid;          // 0..1023
            int r  = slot >> 3;                // 0..127
            int kg = (slot & 7) << 2;          // 0..28
            float4 va = *(const float4*)(A + (size_t)(row0 + r) * Kdim + k0 + kg);
            *(float4*)&Sa[r * GSTRIDE + kg] = va;
            float4 vw = *(const float4*)(W + (size_t)(col0 + r) * Kdim + k0 + kg);
            *(float4*)&Sw[r * GSTRIDE + kg] = vw;
        }
        __syncthreads();

#pragma unroll
        for (int ks = 0; ks < 4; ks++) {
            const int kk = ks * 8;
            uint32_t ah[4][4], bh[4][2];
            uint32_t al[4][4], bl[4][2];
#pragma unroll
            for (int mt = 0; mt < 4; mt++) {
                const float* p = Sa + (wr + mt * 16 + g) * GSTRIDE + kk + tg;
                float x0 = p[0];
                float x1 = p[8 * GSTRIDE];
                float x2 = p[4];
                float x3 = p[8 * GSTRIDE + 4];
                ah[mt][0] = cvt_tf32(x0); ah[mt][1] = cvt_tf32(x1);
                ah[mt][2] = cvt_tf32(x2); ah[mt][3] = cvt_tf32(x3);
                if (PREC == 1) {
                    al[mt][0] = __float_as_uint(x0 - __uint_as_float(ah[mt][0]));
                    al[mt][1] = __float_as_uint(x1 - __uint_as_float(ah[mt][1]));
                    al[mt][2] = __float_as_uint(x2 - __uint_as_float(ah[mt][2]));
                    al[mt][3] = __float_as_uint(x3 - __uint_as_float(ah[mt][3]));
                }
            }
#pragma unroll
            for (int nt = 0; nt < 4; nt++) {
                const float* p = Sw + (wc + nt * 8 + g) * GSTRIDE + kk + tg;
                float x0 = p[0];
                float x1 = p[4];
                bh[nt][0] = cvt_tf32(x0); bh[nt][1] = cvt_tf32(x1);
                if (PREC == 1) {
                    bl[nt][0] = __float_as_uint(x0 - __uint_as_float(bh[nt][0]));
                    bl[nt][1] = __float_as_uint(x1 - __uint_as_float(bh[nt][1]));
                }
            }
#pragma unroll
            for (int mt = 0; mt < 4; mt++)
#pragma unroll
                for (int nt = 0; nt < 4; nt++) {
                    if (PREC == 1) {
                        mma_tf32(acc[mt][nt], ah[mt][0], ah[mt][1], ah[mt][2], ah[mt][3],
                                 bl[nt][0], bl[nt][1]);
                        mma_tf32(acc[mt][nt], al[mt][0], al[mt][1], al[mt][2], al[mt][3],
                                 bh[nt][0], bh[nt][1]);
                    }
                    mma_tf32(acc[mt][nt], ah[mt][0], ah[mt][1], ah[mt][2], ah[mt][3],
                             bh[nt][0], bh[nt][1]);
                }
        }
        __syncthreads();
    }

    // Epilogue
#pragma unroll
    for (int mt = 0; mt < 4; mt++) {
#pragma unroll
        for (int half = 0; half < 2; half++) {
            int r = row0 + wr + mt * 16 + g + half * 8;
            float rmv = (EPI == 2) ? rowmask[r] : 0.f;
#pragma unroll
            for (int nt = 0; nt < 4; nt++) {
                int c = col0 + wc + nt * 8 + tg * 2;
                float o0 = acc[mt][nt][half * 2 + 0] + bias[c];
                float o1 = acc[mt][nt][half * 2 + 1] + bias[c + 1];
                if (EPI == 1) {
                    o0 = 0.5f * o0 * (1.f + erff(o0 * 0.7071067811865476f));
                    o1 = 0.5f * o1 * (1.f + erff(o1 * 0.7071067811865476f));
                } else if (EPI == 2) {
                    const float* rp = res + (size_t)r * Ndim + c;
                    o0 = (rp[0] + o0) * rmv;
                    o1 = (rp[1] + o1) * rmv;
                } else if (EPI == 3) {
                    const float* rp = res + (size_t)r * Ndim + c;
                    o0 += rp[0];
                    o1 += rp[1];
                }
                *(float2*)(Out + (size_t)r * Ndim + c) = make_float2(o0, o1);
            }
        }
    }
}

// ---------------------------------------------------------------------------
// Tile loaders for attention (64 rows x 64 dims)
// ---------------------------------------------------------------------------
__device__ __forceinline__ void load_tile_T(const float* __restrict__ g, int rowStride,
                                            float* __restrict__ sdst, int tid)
{
#pragma unroll
    for (int i = 0; i < 4; i++) {
        int e  = i * 256 + tid;
        int r  = e >> 4;
        int dg = (e & 15) << 2;
        float4 v = *(const float4*)(g + (size_t)r * rowStride + dg);
        sdst[(dg+0)*68 + r] = v.x;
        sdst[(dg+1)*68 + r] = v.y;
        sdst[(dg+2)*68 + r] = v.z;
        sdst[(dg+3)*68 + r] = v.w;
    }
}

// ---------------------------------------------------------------------------
// Flash attention (one pass) — fp32 (mask-flip safe)
// ---------------------------------------------------------------------------
__global__ __launch_bounds__(256) void attn_kernel(
    const float* __restrict__ qkv, const float* __restrict__ attmask,
    float* __restrict__ y, float* __restrict__ gm, float* __restrict__ gl)
{
    extern __shared__ __align__(16) float sm[];
    float* Qst = sm;
    float* Kst = sm + 64 * 68;
    float* Vs  = sm + 2 * 64 * 68;
    float* Ps  = sm + 3 * 64 * 68;

    const int bh = blockIdx.y, b = bh >> 4, h = bh & 15;
    const int qt = blockIdx.x;
    const int tid = threadIdx.x;
    const int tx = tid & 15, ty = tid >> 4;
    const float scale = 0.125f;

    const float* qbase = qkv + ((size_t)(b * T_ + qt * 64)) * (3 * C_) + h * 64;
    load_tile_T(qbase, 3 * C_, Qst, tid);

    float m_[4], l_[4], acc[4][4];
#pragma unroll
    for (int i = 0; i < 4; i++) {
        m_[i] = -INFINITY; l_[i] = 0.f;
#pragma unroll
        for (int j = 0; j < 4; j++) acc[i][j] = 0.f;
    }

    for (int kt = 0; kt <= qt; kt++) {
        __syncthreads();
        const float* kb = qkv + ((size_t)(b * T_ + kt * 64)) * (3 * C_) + C_ + h * 64;
        const float* vb = kb + C_;
        load_tile_T(kb, 3 * C_, Kst, tid);
#pragma unroll
        for (int i2 = 0; i2 < 4; i2++) {
            int e = i2 * 256 + tid; int r = e >> 4; int dg = (e & 15) << 2;
            *(float4*)&Vs[r * 68 + dg] = *(const float4*)(vb + (size_t)r * (3 * C_) + dg);
        }
        __syncthreads();

        float s[4][4];
#pragma unroll
        for (int i = 0; i < 4; i++)
#pragma unroll
            for (int j = 0; j < 4; j++) s[i][j] = 0.f;
#pragma unroll 8
        for (int d = 0; d < 64; d++) {
            float4 qv = *(const float4*)&Qst[d * 68 + ty * 4];
            float4 kv = *(const float4*)&Kst[d * 68 + tx * 4];
            float qa[4] = {qv.x, qv.y, qv.z, qv.w};
            float ka[4] = {kv.x, kv.y, kv.z, kv.w};
#pragma unroll
            for (int i = 0; i < 4; i++)
#pragma unroll
                for (int j = 0; j < 4; j++) s[i][j] += qa[i] * ka[j];
        }

        float am[4];
#pragma unroll
        for (int j = 0; j < 4; j++) am[j] = attmask[b * T_ + kt * 64 + tx * 4 + j];
#pragma unroll
        for (int i = 0; i < 4; i++) {
            int qg = qt * 64 + ty * 4 + i;
#pragma unroll
            for (int j = 0; j < 4; j++) {
                int kg = kt * 64 + tx * 4 + j;
                float sv = s[i][j] * scale;
                if (kg > qg || am[j] == 0.f) sv = -INFINITY;
                s[i][j] = sv;
            }
        }
#pragma unroll
        for (int i = 0; i < 4; i++) {
            float rm = fmaxf(fmaxf(s[i][0], s[i][1]), fmaxf(s[i][2], s[i][3]));
#pragma unroll
            for (int o = 1; o < 16; o <<= 1)
                rm = fmaxf(rm, __shfl_xor_sync(0xffffffffu, rm, o, 16));
            float mn = fmaxf(m_[i], rm);
            float alpha = (mn > m_[i]) ? __expf(m_[i] - mn) : 1.f;
            float psum = 0.f;
#pragma unroll
            for (int j = 0; j < 4; j++) {
                float p = (s[i][j] == -INFINITY) ? 0.f : __expf(s[i][j] - mn);
                Ps[(ty * 4 + i) * 65 + tx * 4 + j] = p;
                psum += p;
            }
#pragma unroll
            for (int o = 1; o < 16; o <<= 1)
                psum += __shfl_xor_sync(0xffffffffu, psum, o, 16);
            l_[i] = l_[i] * alpha + psum;
            m_[i] = mn;
#pragma unroll
            for (int j = 0; j < 4; j++) acc[i][j] *= alpha;
        }
        __syncthreads();

#pragma unroll 8
        for (int k = 0; k < 64; k++) {
            float4 vv = *(const float4*)&Vs[k * 68 + tx * 4];
#pragma unroll
            for (int i = 0; i < 4; i++) {
                float p = Ps[(ty * 4 + i) * 65 + k];
                acc[i][0] += p * vv.x; acc[i][1] += p * vv.y;
                acc[i][2] += p * vv.z; acc[i][3] += p * vv.w;
            }
        }
    }

#pragma unroll
    for (int i = 0; i < 4; i++) {
        int qg = qt * 64 + ty * 4 + i;
        float inv = 1.f / l_[i];
        float* yo = y + ((size_t)(b * T_ + qg)) * C_ + h * 64 + tx * 4;
        yo[0] = acc[i][0] * inv; yo[1] = acc[i][1] * inv;
        yo[2] = acc[i][2] * inv; yo[3] = acc[i][3] * inv;
        if (tx == 0) { gm[bh * T_ + qg] = m_[i]; gl[bh * T_ + qg] = l_[i]; }
    }
}

// ---------------------------------------------------------------------------
// Importance pass — fp32 (deterministic)
// ---------------------------------------------------------------------------
__global__ __launch_bounds__(256) void imp_kernel(
    const float* __restrict__ qkv, const float* __restrict__ attmask,
    const float* __restrict__ gm, const float* __restrict__ gl,
    float* __restrict__ impH)
{
    __shared__ __align__(16) float Kst[64 * 68];
    __shared__ __align__(16) float Qst[64 * 68];
    const int bh = blockIdx.y, b = bh >> 4, h = bh & 15;
    const int kt = blockIdx.x;
    const int tid = threadIdx.x, tx = tid & 15, ty = tid >> 4;
    const float scale = 0.125f;

    const float* kb = qkv + ((size_t)(b * T_ + kt * 64)) * (3 * C_) + C_ + h * 64;
    load_tile_T(kb, 3 * C_, Kst, tid);

    float am[4];
#pragma unroll
    for (int i = 0; i < 4; i++) am[i] = attmask[b * T_ + kt * 64 + ty * 4 + i];
    float impacc[4] = {0.f, 0.f, 0.f, 0.f};

    for (int qt = kt; qt < NT_; qt++) {
        __syncthreads();
        load_tile_T(qkv + ((size_t)(b * T_ + qt * 64)) * (3 * C_) + h * 64, 3 * C_, Qst, tid);
        __syncthreads();

        float s[4][4];
#pragma unroll
        for (int i = 0; i < 4; i++)
#pragma unroll
            for (int j = 0; j < 4; j++) s[i][j] = 0.f;
#pragma unroll 8
        for (int d = 0; d < 64; d++) {
            float4 kv = *(const float4*)&Kst[d * 68 + ty * 4];
            float4 qv = *(const float4*)&Qst[d * 68 + tx * 4];
            float ka[4] = {kv.x, kv.y, kv.z, kv.w};
            float qa[4] = {qv.x, qv.y, qv.z, qv.w};
#pragma unroll
            for (int i = 0; i < 4; i++)
#pragma unroll
                for (int j = 0; j < 4; j++) s[i][j] += ka[i] * qa[j];
        }
        float mq[4], lq[4];
#pragma unroll
        for (int j = 0; j < 4; j++) {
            int qg = qt * 64 + tx * 4 + j;
            mq[j] = gm[bh * T_ + qg];
            lq[j] = gl[bh * T_ + qg];
        }
#pragma unroll
        for (int i = 0; i < 4; i++) {
            int kg = kt * 64 + ty * 4 + i;
            if (am[i] == 0.f) continue;
#pragma unroll
            for (int j = 0; j < 4; j++) {
                int qg = qt * 64 + tx * 4 + j;
                if (qg >= kg)
                    impacc[i] += __expf(s[i][j] * scale - mq[j]) / lq[j];
            }
        }
    }
#pragma unroll
    for (int i = 0; i < 4; i++) {
#pragma unroll
        for (int o = 1; o < 16; o <<= 1)
            impacc[i] += __shfl_xor_sync(0xffffffffu, impacc[i], o, 16);
    }
    if (tx == 0) {
#pragma unroll
        for (int i = 0; i < 4; i++)
            impH[bh * T_ + kt * 64 + ty * 4 + i] = impacc[i];
    }
}

// ---------------------------------------------------------------------------
// Finalize pruning mask
// ---------------------------------------------------------------------------
__global__ __launch_bounds__(256) void finalize_mask(
    const float* __restrict__ impH, const float* __restrict__ attmask,
    const float* __restrict__ prot, const float* __restrict__ thresh,
    float* __restrict__ cm, float* __restrict__ out_mask,
    float* __restrict__ out_loss)
{
    int i = blockIdx.x * 256 + threadIdx.x;
    int b = i / T_, t = i % T_;
    float s = 0.f;
#pragma unroll
    for (int h = 0; h < H_; h++) s += impH[(b * H_ + h) * T_ + t];
    float imp = s * (1.f / ((float)H_ * (float)T_));
    float pm = (imp >= thresh[0]) ? 1.f : 0.f;
    if (prot[i] > 0.f) pm = 1.f;
    float c = attmask[i] * pm;
    cm[i] = c;
    out_mask[i] = c;
    if (i == 0) out_loss[0] = 0.f;
}

// ---------------------------------------------------------------------------
// Launch
// ---------------------------------------------------------------------------
extern "C" void kernel_launch(void* const* d_in, const int* in_sizes, int n_in,
                              void* d_out, int out_size)
{
    const float* x              = (const float*)d_in[0];
    const float* attention_mask = (const float*)d_in[1];
    const float* protected_mask = (const float*)d_in[2];
    const float* ln1_w          = (const float*)d_in[3];
    const float* ln1_b          = (const float*)d_in[4];
    const float* c_attn_w       = (const float*)d_in[5];
    const float* c_attn_b       = (const float*)d_in[6];
    const float* c_proj_w       = (const float*)d_in[7];
    const float* c_proj_b       = (const float*)d_in[8];
    const float* ln2_w          = (const float*)d_in[9];
    const float* ln2_b          = (const float*)d_in[10];
    const float* fc_w           = (const float*)d_in[11];
    const float* fc_b           = (const float*)d_in[12];
    const float* fcproj_w       = (const float*)d_in[13];
    const float* fcproj_b       = (const float*)d_in[14];
    const float* threshold      = (const float*)d_in[15];

    float* out      = (float*)d_out;
    float* out_mask = out + (size_t)M_ * C_;
    float* out_loss = out_mask + M_;

    float *p_h, *p_qkv, *p_y, *p_m, *p_l, *p_imp, *p_cm, *p_xres, *p_fc;
    cudaGetSymbolAddress((void**)&p_h,    g_h);
    cudaGetSymbolAddress((void**)&p_qkv,  g_qkv);
    cudaGetSymbolAddress((void**)&p_y,    g_y);
    cudaGetSymbolAddress((void**)&p_m,    g_m);
    cudaGetSymbolAddress((void**)&p_l,    g_l);
    cudaGetSymbolAddress((void**)&p_imp,  g_impH);
    cudaGetSymbolAddress((void**)&p_cm,   g_cm);
    cudaGetSymbolAddress((void**)&p_xres, g_xres);
    cudaGetSymbolAddress((void**)&p_fc,   g_fc);

    const size_t attn_smem = (size_t)(3 * 64 * 68 + 64 * 65) * sizeof(float); // 68864B
    cudaFuncSetAttribute(attn_kernel, cudaFuncAttributeMaxDynamicSharedMemorySize,
                         (int)attn_smem);

    // 1. LN1
    ln_kernel<<<M_, 256>>>(x, ln1_w, ln1_b, p_h);
    // 2. QKV = h @ c_attn_w^T + b   (8192 x 3072 x 1024), 3xTF32 (~fp32 accuracy)
    gemm_tc<0,1><<<dim3(3 * C_ / 128, M_ / 128), 256>>>(
        p_h, c_attn_w, c_attn_b, p_qkv, 3 * C_, C_, nullptr, nullptr);
    // 3. Flash attention -> y, (m,l)
    attn_kernel<<<dim3(NT_, B_ * H_), 256, attn_smem>>>(
        p_qkv, attention_mask, p_y, p_m, p_l);
    // 4. Importance column sums per head (deterministic)
    imp_kernel<<<dim3(NT_, B_ * H_), 256>>>(p_qkv, attention_mask, p_m, p_l, p_imp);
    // 5. Combined mask
    finalize_mask<<<M_ / 256, 256>>>(p_imp, attention_mask, protected_mask,
                                     threshold, p_cm, out_mask, out_loss);
    // 6. proj + residual + prune mask, TF32
    gemm_tc<2,0><<<dim3(C_ / 128, M_ / 128), 256>>>(
        p_y, c_proj_w, c_proj_b, p_xres, C_, C_, x, p_cm);
    // 7. LN2
    ln_kernel<<<M_, 256>>>(p_xres, ln2_w, ln2_b, p_h);
    // 8. fc + GELU  (8192 x 4096 x 1024), TF32
    gemm_tc<1,0><<<dim3(4 * C_ / 128, M_ / 128), 256>>>(
        p_h, fc_w, fc_b, p_fc, 4 * C_, C_, nullptr, nullptr);
    // 9. fcproj + residual -> d_out  (8192 x 1024 x 4096), TF32
    gemm_tc<3,0><<<dim3(C_ / 128, M_ / 128), 256>>>(
        p_fc, fcproj_w, fcproj_b, out, C_, 4 * C_, p_xres, nullptr);
}

// round 9
// speedup vs baseline: 1.7448x; 1.1031x over previous
#include <cuda_runtime.h>
#include <math.h>
#include <stdint.h>

// Problem constants
#define B_  4
#define T_  2048
#define C_  1024
#define H_  16
#define HS_ 64
#define M_  (B_*T_)      // 8192 rows
#define NT_ (T_/64)      // 32 tiles of 64

// ---------------------------------------------------------------------------
// Scratch (device globals; no runtime allocation allowed)
// ---------------------------------------------------------------------------
__device__ float g_h   [M_*C_];            // LN output (reused for LN1 and LN2)
__device__ float g_qkv [M_*3*C_];          // QKV
__device__ float g_y   [M_*C_];            // attention output (B,T,C)
__device__ float g_m   [B_*H_*T_];         // per-row softmax max (scaled scores)
__device__ float g_l   [B_*H_*T_];         // per-row 1/softmax-denominator
__device__ float g_impH[B_*H_*T_];         // per-head importance column sums
__device__ float g_cm  [M_];               // combined mask per token
__device__ float g_xres[M_*C_];            // x after attn residual + prune mask
__device__ float g_fc  [M_*4*C_];          // MLP hidden

// ---------------------------------------------------------------------------
// LayerNorm: one block (256 thr) per row of C=1024, 4 elems/thread
// ---------------------------------------------------------------------------
__global__ __launch_bounds__(256) void ln_kernel(
    const float* __restrict__ x, const float* __restrict__ w,
    const float* __restrict__ bias, float* __restrict__ out)
{
    int row = blockIdx.x;
    int tid = threadIdx.x;
    const float* xr = x + (size_t)row * C_;
    float4 v = *(const float4*)(xr + tid * 4);
    float s1 = v.x + v.y + v.z + v.w;
    float s2 = v.x*v.x + v.y*v.y + v.z*v.z + v.w*v.w;
#pragma unroll
    for (int o = 16; o; o >>= 1) {
        s1 += __shfl_xor_sync(0xffffffffu, s1, o);
        s2 += __shfl_xor_sync(0xffffffffu, s2, o);
    }
    __shared__ float sh1[8], sh2[8];
    int wi = tid >> 5;
    if ((tid & 31) == 0) { sh1[wi] = s1; sh2[wi] = s2; }
    __syncthreads();
    float t1 = 0.f, t2 = 0.f;
#pragma unroll
    for (int i = 0; i < 8; i++) { t1 += sh1[i]; t2 += sh2[i]; }
    float mean = t1 * (1.f / C_);
    float var  = t2 * (1.f / C_) - mean * mean;
    float inv  = rsqrtf(var + 1e-5f);
    float4 wv = *(const float4*)(w + tid * 4);
    float4 bv = *(const float4*)(bias + tid * 4);
    float4 o;
    o.x = (v.x - mean) * inv * wv.x + bv.x;
    o.y = (v.y - mean) * inv * wv.y + bv.y;
    o.z = (v.z - mean) * inv * wv.z + bv.z;
    o.w = (v.w - mean) * inv * wv.w + bv.w;
    *(float4*)(out + (size_t)row * C_ + tid * 4) = o;
}

// ---------------------------------------------------------------------------
// Tensor-core TF32 helpers
// ---------------------------------------------------------------------------
__device__ __forceinline__ uint32_t cvt_tf32(float x) {
    uint32_t r; asm("cvt.rna.tf32.f32 %0, %1;" : "=r"(r) : "f"(x)); return r;
}
__device__ __forceinline__ void mma_tf32(float* c,
    uint32_t a0, uint32_t a1, uint32_t a2, uint32_t a3,
    uint32_t b0, uint32_t b1)
{
    asm volatile(
        "mma.sync.aligned.m16n8k8.row.col.f32.tf32.tf32.f32 "
        "{%0,%1,%2,%3}, {%4,%5,%6,%7}, {%8,%9}, {%0,%1,%2,%3};"
        : "+f"(c[0]), "+f"(c[1]), "+f"(c[2]), "+f"(c[3])
        : "r"(a0), "r"(a1), "r"(a2), "r"(a3), "r"(b0), "r"(b1));
}

// ---------------------------------------------------------------------------
// TF32 tensor-core GEMM: Out[M,N] = A[M,K] @ W[N,K]^T (+bias, +epilogue)
// EPI 0: bias only | 1: +GELU | 2: (res+bias+acc)*rowmask | 3: res+bias+acc
// PREC 0: single TF32 | PREC 1: 3xTF32 split (~fp32 accuracy)
// 128x128 block, BK=32, 256 threads (8 warps). Static smem, sync loads.
// Ndim is the OUTPUT ROW STRIDE; column extent comes from gridDim.x.
// W/bias/Out may be pre-offset by the caller for column sub-ranges.
// ---------------------------------------------------------------------------
#define GSTRIDE 36

template<int EPI, int PREC>
__global__ __launch_bounds__(256) void gemm_tc(
    const float* __restrict__ A, const float* __restrict__ W,
    const float* __restrict__ bias, float* __restrict__ Out,
    int Ndim, int Kdim,
    const float* __restrict__ res, const float* __restrict__ rowmask)
{
    __shared__ __align__(16) float Sa[128 * GSTRIDE];
    __shared__ __align__(16) float Sw[128 * GSTRIDE];
    const int tid = threadIdx.x;
    const int row0 = blockIdx.y * 128, col0 = blockIdx.x * 128;

    const int wid  = tid >> 5, lane = tid & 31;
    const int g    = lane >> 2, tg = lane & 3;
    const int wr   = (wid >> 2) * 64;   // warp row offset: 0 / 64
    const int wc   = (wid & 3) * 32;    // warp col offset: 0/32/64/96

    float acc[4][4][4];
#pragma unroll
    for (int mt = 0; mt < 4; mt++)
#pragma unroll
        for (int nt = 0; nt < 4; nt++)
#pragma unroll
            for (int i = 0; i < 4; i++) acc[mt][nt][i] = 0.f;

    for (int k0 = 0; k0 < Kdim; k0 += 32) {
#pragma unroll
        for (int i = 0; i < 4; i++) {
            int slot = i * 256 + tid;          // 0..1023
            int r  = slot >> 3;                // 0..127
            int kg = (slot & 7) << 2;          // 0..28
            float4 va = *(const float4*)(A + (size_t)(row0 + r) * Kdim + k0 + kg);
            *(float4*)&Sa[r * GSTRIDE + kg] = va;
            float4 vw = *(const float4*)(W + (size_t)(col0 + r) * Kdim + k0 + kg);
            *(float4*)&Sw[r * GSTRIDE + kg] = vw;
        }
        __syncthreads();

#pragma unroll
        for (int ks = 0; ks < 4; ks++) {
            const int kk = ks * 8;
            uint32_t ah[4][4], bh[4][2];
            uint32_t al[4][4], bl[4][2];
#pragma unroll
            for (int mt = 0; mt < 4; mt++) {
                const float* p = Sa + (wr + mt * 16 + g) * GSTRIDE + kk + tg;
                float x0 = p[0];
                float x1 = p[8 * GSTRIDE];
                float x2 = p[4];
                float x3 = p[8 * GSTRIDE + 4];
                ah[mt][0] = cvt_tf32(x0); ah[mt][1] = cvt_tf32(x1);
                ah[mt][2] = cvt_tf32(x2); ah[mt][3] = cvt_tf32(x3);
                if (PREC == 1) {
                    al[mt][0] = __float_as_uint(x0 - __uint_as_float(ah[mt][0]));
                    al[mt][1] = __float_as_uint(x1 - __uint_as_float(ah[mt][1]));
                    al[mt][2] = __float_as_uint(x2 - __uint_as_float(ah[mt][2]));
                    al[mt][3] = __float_as_uint(x3 - __uint_as_float(ah[mt][3]));
                }
            }
#pragma unroll
            for (int nt = 0; nt < 4; nt++) {
                const float* p = Sw + (wc + nt * 8 + g) * GSTRIDE + kk + tg;
                float x0 = p[0];
                float x1 = p[4];
                bh[nt][0] = cvt_tf32(x0); bh[nt][1] = cvt_tf32(x1);
                if (PREC == 1) {
                    bl[nt][0] = __float_as_uint(x0 - __uint_as_float(bh[nt][0]));
                    bl[nt][1] = __float_as_uint(x1 - __uint_as_float(bh[nt][1]));
                }
            }
#pragma unroll
            for (int mt = 0; mt < 4; mt++)
#pragma unroll
                for (int nt = 0; nt < 4; nt++) {
                    if (PREC == 1) {
                        mma_tf32(acc[mt][nt], ah[mt][0], ah[mt][1], ah[mt][2], ah[mt][3],
                                 bl[nt][0], bl[nt][1]);
                        mma_tf32(acc[mt][nt], al[mt][0], al[mt][1], al[mt][2], al[mt][3],
                                 bh[nt][0], bh[nt][1]);
                    }
                    mma_tf32(acc[mt][nt], ah[mt][0], ah[mt][1], ah[mt][2], ah[mt][3],
                             bh[nt][0], bh[nt][1]);
                }
        }
        __syncthreads();
    }

    // Epilogue
#pragma unroll
    for (int mt = 0; mt < 4; mt++) {
#pragma unroll
        for (int half = 0; half < 2; half++) {
            int r = row0 + wr + mt * 16 + g + half * 8;
            float rmv = (EPI == 2) ? rowmask[r] : 0.f;
#pragma unroll
            for (int nt = 0; nt < 4; nt++) {
                int c = col0 + wc + nt * 8 + tg * 2;
                float o0 = acc[mt][nt][half * 2 + 0] + bias[c];
                float o1 = acc[mt][nt][half * 2 + 1] + bias[c + 1];
                if (EPI == 1) {
                    o0 = 0.5f * o0 * (1.f + erff(o0 * 0.7071067811865476f));
                    o1 = 0.5f * o1 * (1.f + erff(o1 * 0.7071067811865476f));
                } else if (EPI == 2) {
                    const float* rp = res + (size_t)r * Ndim + c;
                    o0 = (rp[0] + o0) * rmv;
                    o1 = (rp[1] + o1) * rmv;
                } else if (EPI == 3) {
                    const float* rp = res + (size_t)r * Ndim + c;
                    o0 += rp[0];
                    o1 += rp[1];
                }
                *(float2*)(Out + (size_t)r * Ndim + c) = make_float2(o0, o1);
            }
        }
    }
}

// ---------------------------------------------------------------------------
// Tile loaders for attention (64 rows x 64 dims)
// ---------------------------------------------------------------------------
__device__ __forceinline__ void load_tile_T(const float* __restrict__ g, int rowStride,
                                            float* __restrict__ sdst, int tid)
{
#pragma unroll
    for (int i = 0; i < 4; i++) {
        int e  = i * 256 + tid;
        int r  = e >> 4;
        int dg = (e & 15) << 2;
        float4 v = *(const float4*)(g + (size_t)r * rowStride + dg);
        sdst[(dg+0)*68 + r] = v.x;
        sdst[(dg+1)*68 + r] = v.y;
        sdst[(dg+2)*68 + r] = v.z;
        sdst[(dg+3)*68 + r] = v.w;
    }
}

// Row-major loader: [row][dim] with pad 68
__device__ __forceinline__ void load_tile_R(const float* __restrict__ g, int rowStride,
                                            float* __restrict__ sdst, int tid)
{
#pragma unroll
    for (int i = 0; i < 4; i++) {
        int e  = i * 256 + tid;
        int r  = e >> 4;
        int dg = (e & 15) << 2;
        *(float4*)&sdst[r * 68 + dg] = *(const float4*)(g + (size_t)r * rowStride + dg);
    }
}

// ---------------------------------------------------------------------------
// Flash attention (one pass) — fp32 (mask-flip safe).
// Stores y, per-row softmax max m, and per-row INVERSE denom (1/l) in gl.
// ---------------------------------------------------------------------------
__global__ __launch_bounds__(256) void attn_kernel(
    const float* __restrict__ qkv, const float* __restrict__ attmask,
    float* __restrict__ y, float* __restrict__ gm, float* __restrict__ gl)
{
    extern __shared__ __align__(16) float sm[];
    float* Qst = sm;
    float* Kst = sm + 64 * 68;
    float* Vs  = sm + 2 * 64 * 68;
    float* Ps  = sm + 3 * 64 * 68;

    const int bh = blockIdx.y, b = bh >> 4, h = bh & 15;
    const int qt = blockIdx.x;
    const int tid = threadIdx.x;
    const int tx = tid & 15, ty = tid >> 4;
    const float scale = 0.125f;

    const float* qbase = qkv + ((size_t)(b * T_ + qt * 64)) * (3 * C_) + h * 64;
    load_tile_T(qbase, 3 * C_, Qst, tid);

    float m_[4], l_[4], acc[4][4];
#pragma unroll
    for (int i = 0; i < 4; i++) {
        m_[i] = -INFINITY; l_[i] = 0.f;
#pragma unroll
        for (int j = 0; j < 4; j++) acc[i][j] = 0.f;
    }

    for (int kt = 0; kt <= qt; kt++) {
        __syncthreads();
        const float* kb = qkv + ((size_t)(b * T_ + kt * 64)) * (3 * C_) + C_ + h * 64;
        const float* vb = kb + C_;
        load_tile_T(kb, 3 * C_, Kst, tid);
#pragma unroll
        for (int i2 = 0; i2 < 4; i2++) {
            int e = i2 * 256 + tid; int r = e >> 4; int dg = (e & 15) << 2;
            *(float4*)&Vs[r * 68 + dg] = *(const float4*)(vb + (size_t)r * (3 * C_) + dg);
        }
        __syncthreads();

        float s[4][4];
#pragma unroll
        for (int i = 0; i < 4; i++)
#pragma unroll
            for (int j = 0; j < 4; j++) s[i][j] = 0.f;
#pragma unroll 8
        for (int d = 0; d < 64; d++) {
            float4 qv = *(const float4*)&Qst[d * 68 + ty * 4];
            float4 kv = *(const float4*)&Kst[d * 68 + tx * 4];
            float qa[4] = {qv.x, qv.y, qv.z, qv.w};
            float ka[4] = {kv.x, kv.y, kv.z, kv.w};
#pragma unroll
            for (int i = 0; i < 4; i++)
#pragma unroll
                for (int j = 0; j < 4; j++) s[i][j] += qa[i] * ka[j];
        }

        float am[4];
#pragma unroll
        for (int j = 0; j < 4; j++) am[j] = attmask[b * T_ + kt * 64 + tx * 4 + j];
#pragma unroll
        for (int i = 0; i < 4; i++) {
            int qg = qt * 64 + ty * 4 + i;
#pragma unroll
            for (int j = 0; j < 4; j++) {
                int kg = kt * 64 + tx * 4 + j;
                float sv = s[i][j] * scale;
                if (kg > qg || am[j] == 0.f) sv = -INFINITY;
                s[i][j] = sv;
            }
        }
#pragma unroll
        for (int i = 0; i < 4; i++) {
            float rm = fmaxf(fmaxf(s[i][0], s[i][1]), fmaxf(s[i][2], s[i][3]));
#pragma unroll
            for (int o = 1; o < 16; o <<= 1)
                rm = fmaxf(rm, __shfl_xor_sync(0xffffffffu, rm, o, 16));
            float mn = fmaxf(m_[i], rm);
            float alpha = (mn > m_[i]) ? __expf(m_[i] - mn) : 1.f;
            float psum = 0.f;
#pragma unroll
            for (int j = 0; j < 4; j++) {
                float p = (s[i][j] == -INFINITY) ? 0.f : __expf(s[i][j] - mn);
                Ps[(ty * 4 + i) * 65 + tx * 4 + j] = p;
                psum += p;
            }
#pragma unroll
            for (int o = 1; o < 16; o <<= 1)
                psum += __shfl_xor_sync(0xffffffffu, psum, o, 16);
            l_[i] = l_[i] * alpha + psum;
            m_[i] = mn;
#pragma unroll
            for (int j = 0; j < 4; j++) acc[i][j] *= alpha;
        }
        __syncthreads();

#pragma unroll 8
        for (int k = 0; k < 64; k++) {
            float4 vv = *(const float4*)&Vs[k * 68 + tx * 4];
#pragma unroll
            for (int i = 0; i < 4; i++) {
                float p = Ps[(ty * 4 + i) * 65 + k];
                acc[i][0] += p * vv.x; acc[i][1] += p * vv.y;
                acc[i][2] += p * vv.z; acc[i][3] += p * vv.w;
            }
        }
    }

#pragma unroll
    for (int i = 0; i < 4; i++) {
        int qg = qt * 64 + ty * 4 + i;
        float inv = 1.f / l_[i];
        float* yo = y + ((size_t)(b * T_ + qg)) * C_ + h * 64 + tx * 4;
        yo[0] = acc[i][0] * inv; yo[1] = acc[i][1] * inv;
        yo[2] = acc[i][2] * inv; yo[3] = acc[i][3] * inv;
        if (tx == 0) { gm[bh * T_ + qg] = m_[i]; gl[bh * T_ + qg] = inv; }
    }
}

// ---------------------------------------------------------------------------
// Importance pass — tensor-core 3xTF32 scores (error ~fp32, flip-safe),
// deterministic column sums. gl holds 1/l (inverse denominators).
// Block = (b,h,kt). 8 warps: (wid&3) -> 16-k-row slice, (wid>>2) -> 32-q half.
// Loop shape mirrors gemm_tc: per k-step load K frag, then 4 Q frags + 3 MMAs.
// ---------------------------------------------------------------------------
__global__ __launch_bounds__(256) void imp_kernel(
    const float* __restrict__ qkv, const float* __restrict__ attmask,
    const float* __restrict__ gm, const float* __restrict__ gl,
    float* __restrict__ impH)
{
    __shared__ __align__(16) float Ks[64 * 68];   // [k][d]
    __shared__ __align__(16) float Qs[64 * 68];   // [q][d]
    __shared__ float part[2][64];

    const int bh = blockIdx.y, b = bh >> 4, h = bh & 15;
    const int kt = blockIdx.x;
    const int tid = threadIdx.x;
    const int wid = tid >> 5, lane = tid & 31;
    const int g = lane >> 2, tg = lane & 3;
    const int kr0 = (wid & 3) * 16;     // warp's k-row base within tile
    const int qh  = wid >> 2;           // 0/1: q-column half
    const int qc0 = qh * 32;
    const float scale = 0.125f;
    const int bhT = bh * T_;

    // Load K tile row-major [k][d]
    const float* kb = qkv + ((size_t)(b * T_ + kt * 64)) * (3 * C_) + C_ + h * 64;
    load_tile_R(kb, 3 * C_, Ks, tid);

    const int kg0 = kt * 64 + kr0 + g;
    const int kg1 = kg0 + 8;
    const float amk0 = attmask[b * T_ + kt * 64 + kr0 + g];
    const float amk1 = attmask[b * T_ + kt * 64 + kr0 + g + 8];

    float imp0 = 0.f, imp1 = 0.f;

    for (int qt = kt; qt < NT_; qt++) {
        __syncthreads();
        load_tile_R(qkv + ((size_t)(b * T_ + qt * 64)) * (3 * C_) + h * 64, 3 * C_, Qs, tid);
        __syncthreads();

        float c[4][4];
#pragma unroll
        for (int nt = 0; nt < 4; nt++)
#pragma unroll
            for (int i = 0; i < 4; i++) c[nt][i] = 0.f;

#pragma unroll
        for (int s = 0; s < 8; s++) {
            // K fragment (A operand) for this k-step, hi/lo split
            const float* ap = Ks + (kr0 + g) * 68 + s * 8 + tg;
            float x0 = ap[0];
            float x1 = ap[8 * 68];
            float x2 = ap[4];
            float x3 = ap[8 * 68 + 4];
            uint32_t kh0 = cvt_tf32(x0), kh1 = cvt_tf32(x1);
            uint32_t kh2 = cvt_tf32(x2), kh3 = cvt_tf32(x3);
            uint32_t kl0 = __float_as_uint(x0 - __uint_as_float(kh0));
            uint32_t kl1 = __float_as_uint(x1 - __uint_as_float(kh1));
            uint32_t kl2 = __float_as_uint(x2 - __uint_as_float(kh2));
            uint32_t kl3 = __float_as_uint(x3 - __uint_as_float(kh3));
#pragma unroll
            for (int nt = 0; nt < 4; nt++) {
                const float* bp = Qs + (qc0 + nt * 8 + g) * 68 + s * 8 + tg;
                float y0 = bp[0], y1 = bp[4];
                uint32_t bh0 = cvt_tf32(y0), bh1 = cvt_tf32(y1);
                uint32_t bl0 = __float_as_uint(y0 - __uint_as_float(bh0));
                uint32_t bl1 = __float_as_uint(y1 - __uint_as_float(bh1));
                mma_tf32(c[nt], kh0, kh1, kh2, kh3, bl0, bl1);
                mma_tf32(c[nt], kl0, kl1, kl2, kl3, bh0, bh1);
                mma_tf32(c[nt], kh0, kh1, kh2, kh3, bh0, bh1);
            }
        }

#pragma unroll
        for (int nt = 0; nt < 4; nt++) {
            const int qg0 = qt * 64 + qc0 + nt * 8 + 2 * tg;
            const int qg1 = qg0 + 1;
            const float mq0 = gm[bhT + qg0], mq1 = gm[bhT + qg1];
            const float rq0 = gl[bhT + qg0], rq1 = gl[bhT + qg1];
            if (qg0 >= kg0) imp0 += amk0 * __expf(fmaf(c[nt][0], scale, -mq0)) * rq0;
            if (qg1 >= kg0) imp0 += amk0 * __expf(fmaf(c[nt][1], scale, -mq1)) * rq1;
            if (qg0 >= kg1) imp1 += amk1 * __expf(fmaf(c[nt][2], scale, -mq0)) * rq0;
            if (qg1 >= kg1) imp1 += amk1 * __expf(fmaf(c[nt][3], scale, -mq1)) * rq1;
        }
    }

    // Reduce across the 4 lanes (tg) sharing each k-row (deterministic)
    imp0 += __shfl_xor_sync(0xffffffffu, imp0, 1);
    imp0 += __shfl_xor_sync(0xffffffffu, imp0, 2);
    imp1 += __shfl_xor_sync(0xffffffffu, imp1, 1);
    imp1 += __shfl_xor_sync(0xffffffffu, imp1, 2);
    if (tg == 0) {
        part[qh][kr0 + g] = imp0;
        part[qh][kr0 + 8 + g] = imp1;
    }
    __syncthreads();
    if (tid < 64)
        impH[bhT + kt * 64 + tid] = part[0][tid] + part[1][tid];
}

// ---------------------------------------------------------------------------
// Finalize pruning mask
// ---------------------------------------------------------------------------
__global__ __launch_bounds__(256) void finalize_mask(
    const float* __restrict__ impH, const float* __restrict__ attmask,
    const float* __restrict__ prot, const float* __restrict__ thresh,
    float* __restrict__ cm, float* __restrict__ out_mask,
    float* __restrict__ out_loss)
{
    int i = blockIdx.x * 256 + threadIdx.x;
    int b = i / T_, t = i % T_;
    float s = 0.f;
#pragma unroll
    for (int h = 0; h < H_; h++) s += impH[(b * H_ + h) * T_ + t];
    float imp = s * (1.f / ((float)H_ * (float)T_));
    float pm = (imp >= thresh[0]) ? 1.f : 0.f;
    if (prot[i] > 0.f) pm = 1.f;
    float c = attmask[i] * pm;
    cm[i] = c;
    out_mask[i] = c;
    if (i == 0) out_loss[0] = 0.f;
}

// ---------------------------------------------------------------------------
// Launch
// ---------------------------------------------------------------------------
extern "C" void kernel_launch(void* const* d_in, const int* in_sizes, int n_in,
                              void* d_out, int out_size)
{
    const float* x              = (const float*)d_in[0];
    const float* attention_mask = (const float*)d_in[1];
    const float* protected_mask = (const float*)d_in[2];
    const float* ln1_w          = (const float*)d_in[3];
    const float* ln1_b          = (const float*)d_in[4];
    const float* c_attn_w       = (const float*)d_in[5];
    const float* c_attn_b       = (const float*)d_in[6];
    const float* c_proj_w       = (const float*)d_in[7];
    const float* c_proj_b       = (const float*)d_in[8];
    const float* ln2_w          = (const float*)d_in[9];
    const float* ln2_b          = (const float*)d_in[10];
    const float* fc_w           = (const float*)d_in[11];
    const float* fc_b           = (const float*)d_in[12];
    const float* fcproj_w       = (const float*)d_in[13];
    const float* fcproj_b       = (const float*)d_in[14];
    const float* threshold      = (const float*)d_in[15];

    float* out      = (float*)d_out;
    float* out_mask = out + (size_t)M_ * C_;
    float* out_loss = out_mask + M_;

    float *p_h, *p_qkv, *p_y, *p_m, *p_l, *p_imp, *p_cm, *p_xres, *p_fc;
    cudaGetSymbolAddress((void**)&p_h,    g_h);
    cudaGetSymbolAddress((void**)&p_qkv,  g_qkv);
    cudaGetSymbolAddress((void**)&p_y,    g_y);
    cudaGetSymbolAddress((void**)&p_m,    g_m);
    cudaGetSymbolAddress((void**)&p_l,    g_l);
    cudaGetSymbolAddress((void**)&p_imp,  g_impH);
    cudaGetSymbolAddress((void**)&p_cm,   g_cm);
    cudaGetSymbolAddress((void**)&p_xres, g_xres);
    cudaGetSymbolAddress((void**)&p_fc,   g_fc);

    const size_t attn_smem = (size_t)(3 * 64 * 68 + 64 * 65) * sizeof(float); // 68864B
    cudaFuncSetAttribute(attn_kernel, cudaFuncAttributeMaxDynamicSharedMemorySize,
                         (int)attn_smem);

    // 1. LN1
    ln_kernel<<<M_, 256>>>(x, ln1_w, ln1_b, p_h);
    // 2a. Q,K columns (0..2047): 3xTF32 (threshold-sensitive path, ~fp32 accuracy)
    gemm_tc<0,1><<<dim3(2 * C_ / 128, M_ / 128), 256>>>(
        p_h, c_attn_w, c_attn_b, p_qkv, 3 * C_, C_, nullptr, nullptr);
    // 2b. V columns (2048..3071): single TF32 (output-only path, budget 1e-3)
    gemm_tc<0,0><<<dim3(C_ / 128, M_ / 128), 256>>>(
        p_h, c_attn_w + (size_t)(2 * C_) * C_, c_attn_b + 2 * C_, p_qkv + 2 * C_,
        3 * C_, C_, nullptr, nullptr);
    // 3. Flash attention -> y, (m, 1/l)
    attn_kernel<<<dim3(NT_, B_ * H_), 256, attn_smem>>>(
        p_qkv, attention_mask, p_y, p_m, p_l);
    // 4. Importance column sums per head (tensor-core, deterministic)
    imp_kernel<<<dim3(NT_, B_ * H_), 256>>>(p_qkv, attention_mask, p_m, p_l, p_imp);
    // 5. Combined mask
    finalize_mask<<<M_ / 256, 256>>>(p_imp, attention_mask, protected_mask,
                                     threshold, p_cm, out_mask, out_loss);
    // 6. proj + residual + prune mask, TF32
    gemm_tc<2,0><<<dim3(C_ / 128, M_ / 128), 256>>>(
        p_y, c_proj_w, c_proj_b, p_xres, C_, C_, x, p_cm);
    // 7. LN2
    ln_kernel<<<M_, 256>>>(p_xres, ln2_w, ln2_b, p_h);
    // 8. fc + GELU  (8192 x 4096 x 1024), TF32
    gemm_tc<1,0><<<dim3(4 * C_ / 128, M_ / 128), 256>>>(
        p_h, fc_w, fc_b, p_fc, 4 * C_, C_, nullptr, nullptr);
    // 9. fcproj + residual -> d_out  (8192 x 1024 x 4096), TF32
    gemm_tc<3,0><<<dim3(C_ / 128, M_ / 128), 256>>>(
        p_fc, fcproj_w, fcproj_b, out, C_, 4 * C_, p_xres, nullptr);
}

// round 10
// speedup vs baseline: 1.9394x; 1.1116x over previous
#include <cuda_runtime.h>
#include <math.h>
#include <stdint.h>

// Problem constants
#define B_  4
#define T_  2048
#define C_  1024
#define H_  16
#define HS_ 64
#define M_  (B_*T_)      // 8192 rows
#define NT_ (T_/64)      // 32 tiles of 64

// ---------------------------------------------------------------------------
// Scratch (device globals; no runtime allocation allowed)
// ---------------------------------------------------------------------------
__device__ float g_h   [M_*C_];            // LN output (reused for LN1 and LN2)
__device__ float g_qkv [M_*3*C_];          // QKV
__device__ float g_y   [M_*C_];            // attention output (B,T,C)
__device__ float g_m   [B_*H_*T_];         // per-row softmax max (scaled scores)
__device__ float g_l   [B_*H_*T_];         // per-row 1/softmax-denominator
__device__ float g_impH[B_*H_*T_];         // per-head importance column sums
__device__ float g_cm  [M_];               // combined mask per token
__device__ float g_xres[M_*C_];            // x after attn residual + prune mask
__device__ float g_fc  [M_*4*C_];          // MLP hidden

// ---------------------------------------------------------------------------
// LayerNorm: one block (256 thr) per row of C=1024, 4 elems/thread
// ---------------------------------------------------------------------------
__global__ __launch_bounds__(256) void ln_kernel(
    const float* __restrict__ x, const float* __restrict__ w,
    const float* __restrict__ bias, float* __restrict__ out)
{
    int row = blockIdx.x;
    int tid = threadIdx.x;
    const float* xr = x + (size_t)row * C_;
    float4 v = *(const float4*)(xr + tid * 4);
    float s1 = v.x + v.y + v.z + v.w;
    float s2 = v.x*v.x + v.y*v.y + v.z*v.z + v.w*v.w;
#pragma unroll
    for (int o = 16; o; o >>= 1) {
        s1 += __shfl_xor_sync(0xffffffffu, s1, o);
        s2 += __shfl_xor_sync(0xffffffffu, s2, o);
    }
    __shared__ float sh1[8], sh2[8];
    int wi = tid >> 5;
    if ((tid & 31) == 0) { sh1[wi] = s1; sh2[wi] = s2; }
    __syncthreads();
    float t1 = 0.f, t2 = 0.f;
#pragma unroll
    for (int i = 0; i < 8; i++) { t1 += sh1[i]; t2 += sh2[i]; }
    float mean = t1 * (1.f / C_);
    float var  = t2 * (1.f / C_) - mean * mean;
    float inv  = rsqrtf(var + 1e-5f);
    float4 wv = *(const float4*)(w + tid * 4);
    float4 bv = *(const float4*)(bias + tid * 4);
    float4 o;
    o.x = (v.x - mean) * inv * wv.x + bv.x;
    o.y = (v.y - mean) * inv * wv.y + bv.y;
    o.z = (v.z - mean) * inv * wv.z + bv.z;
    o.w = (v.w - mean) * inv * wv.w + bv.w;
    *(float4*)(out + (size_t)row * C_ + tid * 4) = o;
}

// ---------------------------------------------------------------------------
// Tensor-core TF32 helpers
// ---------------------------------------------------------------------------
__device__ __forceinline__ uint32_t cvt_tf32(float x) {
    uint32_t r; asm("cvt.rna.tf32.f32 %0, %1;" : "=r"(r) : "f"(x)); return r;
}
__device__ __forceinline__ void mma_tf32(float* c,
    uint32_t a0, uint32_t a1, uint32_t a2, uint32_t a3,
    uint32_t b0, uint32_t b1)
{
    asm volatile(
        "mma.sync.aligned.m16n8k8.row.col.f32.tf32.tf32.f32 "
        "{%0,%1,%2,%3}, {%4,%5,%6,%7}, {%8,%9}, {%0,%1,%2,%3};"
        : "+f"(c[0]), "+f"(c[1]), "+f"(c[2]), "+f"(c[3])
        : "r"(a0), "r"(a1), "r"(a2), "r"(a3), "r"(b0), "r"(b1));
}

// ---------------------------------------------------------------------------
// TF32 tensor-core GEMM: Out[M,N] = A[M,K] @ W[N,K]^T (+bias, +epilogue)
// EPI 0: bias only | 1: +GELU | 2: (res+bias+acc)*rowmask | 3: res+bias+acc
// PREC 0: single TF32 | PREC 1: 3xTF32 split (~fp32 accuracy)
// ---------------------------------------------------------------------------
#define GSTRIDE 36

template<int EPI, int PREC>
__global__ __launch_bounds__(256) void gemm_tc(
    const float* __restrict__ A, const float* __restrict__ W,
    const float* __restrict__ bias, float* __restrict__ Out,
    int Ndim, int Kdim,
    const float* __restrict__ res, const float* __restrict__ rowmask)
{
    __shared__ __align__(16) float Sa[128 * GSTRIDE];
    __shared__ __align__(16) float Sw[128 * GSTRIDE];
    const int tid = threadIdx.x;
    const int row0 = blockIdx.y * 128, col0 = blockIdx.x * 128;

    const int wid  = tid >> 5, lane = tid & 31;
    const int g    = lane >> 2, tg = lane & 3;
    const int wr   = (wid >> 2) * 64;
    const int wc   = (wid & 3) * 32;

    float acc[4][4][4];
#pragma unroll
    for (int mt = 0; mt < 4; mt++)
#pragma unroll
        for (int nt = 0; nt < 4; nt++)
#pragma unroll
            for (int i = 0; i < 4; i++) acc[mt][nt][i] = 0.f;

    for (int k0 = 0; k0 < Kdim; k0 += 32) {
#pragma unroll
        for (int i = 0; i < 4; i++) {
            int slot = i * 256 + tid;
            int r  = slot >> 3;
            int kg = (slot & 7) << 2;
            float4 va = *(const float4*)(A + (size_t)(row0 + r) * Kdim + k0 + kg);
            *(float4*)&Sa[r * GSTRIDE + kg] = va;
            float4 vw = *(const float4*)(W + (size_t)(col0 + r) * Kdim + k0 + kg);
            *(float4*)&Sw[r * GSTRIDE + kg] = vw;
        }
        __syncthreads();

#pragma unroll
        for (int ks = 0; ks < 4; ks++) {
            const int kk = ks * 8;
            uint32_t ah[4][4], bh[4][2];
            uint32_t al[4][4], bl[4][2];
#pragma unroll
            for (int mt = 0; mt < 4; mt++) {
                const float* p = Sa + (wr + mt * 16 + g) * GSTRIDE + kk + tg;
                float x0 = p[0];
                float x1 = p[8 * GSTRIDE];
                float x2 = p[4];
                float x3 = p[8 * GSTRIDE + 4];
                ah[mt][0] = cvt_tf32(x0); ah[mt][1] = cvt_tf32(x1);
                ah[mt][2] = cvt_tf32(x2); ah[mt][3] = cvt_tf32(x3);
                if (PREC == 1) {
                    al[mt][0] = __float_as_uint(x0 - __uint_as_float(ah[mt][0]));
                    al[mt][1] = __float_as_uint(x1 - __uint_as_float(ah[mt][1]));
                    al[mt][2] = __float_as_uint(x2 - __uint_as_float(ah[mt][2]));
                    al[mt][3] = __float_as_uint(x3 - __uint_as_float(ah[mt][3]));
                }
            }
#pragma unroll
            for (int nt = 0; nt < 4; nt++) {
                const float* p = Sw + (wc + nt * 8 + g) * GSTRIDE + kk + tg;
                float x0 = p[0];
                float x1 = p[4];
                bh[nt][0] = cvt_tf32(x0); bh[nt][1] = cvt_tf32(x1);
                if (PREC == 1) {
                    bl[nt][0] = __float_as_uint(x0 - __uint_as_float(bh[nt][0]));
                    bl[nt][1] = __float_as_uint(x1 - __uint_as_float(bh[nt][1]));
                }
            }
#pragma unroll
            for (int mt = 0; mt < 4; mt++)
#pragma unroll
                for (int nt = 0; nt < 4; nt++) {
                    if (PREC == 1) {
                        mma_tf32(acc[mt][nt], ah[mt][0], ah[mt][1], ah[mt][2], ah[mt][3],
                                 bl[nt][0], bl[nt][1]);
                        mma_tf32(acc[mt][nt], al[mt][0], al[mt][1], al[mt][2], al[mt][3],
                                 bh[nt][0], bh[nt][1]);
                    }
                    mma_tf32(acc[mt][nt], ah[mt][0], ah[mt][1], ah[mt][2], ah[mt][3],
                             bh[nt][0], bh[nt][1]);
                }
        }
        __syncthreads();
    }

#pragma unroll
    for (int mt = 0; mt < 4; mt++) {
#pragma unroll
        for (int half = 0; half < 2; half++) {
            int r = row0 + wr + mt * 16 + g + half * 8;
            float rmv = (EPI == 2) ? rowmask[r] : 0.f;
#pragma unroll
            for (int nt = 0; nt < 4; nt++) {
                int c = col0 + wc + nt * 8 + tg * 2;
                float o0 = acc[mt][nt][half * 2 + 0] + bias[c];
                float o1 = acc[mt][nt][half * 2 + 1] + bias[c + 1];
                if (EPI == 1) {
                    o0 = 0.5f * o0 * (1.f + erff(o0 * 0.7071067811865476f));
                    o1 = 0.5f * o1 * (1.f + erff(o1 * 0.7071067811865476f));
                } else if (EPI == 2) {
                    const float* rp = res + (size_t)r * Ndim + c;
                    o0 = (rp[0] + o0) * rmv;
                    o1 = (rp[1] + o1) * rmv;
                } else if (EPI == 3) {
                    const float* rp = res + (size_t)r * Ndim + c;
                    o0 += rp[0];
                    o1 += rp[1];
                }
                *(float2*)(Out + (size_t)r * Ndim + c) = make_float2(o0, o1);
            }
        }
    }
}

// ---------------------------------------------------------------------------
// Tile loaders (64 rows x 64 dims), pad-68 smem
// ---------------------------------------------------------------------------
__device__ __forceinline__ void load_tile_T(const float* __restrict__ g, int rowStride,
                                            float* __restrict__ sdst, int tid)
{
#pragma unroll
    for (int i = 0; i < 4; i++) {
        int e  = i * 256 + tid;
        int r  = e >> 4;
        int dg = (e & 15) << 2;
        float4 v = *(const float4*)(g + (size_t)r * rowStride + dg);
        sdst[(dg+0)*68 + r] = v.x;
        sdst[(dg+1)*68 + r] = v.y;
        sdst[(dg+2)*68 + r] = v.z;
        sdst[(dg+3)*68 + r] = v.w;
    }
}

__device__ __forceinline__ void load_tile_R(const float* __restrict__ g, int rowStride,
                                            float* __restrict__ sdst, int tid)
{
#pragma unroll
    for (int i = 0; i < 4; i++) {
        int e  = i * 256 + tid;
        int r  = e >> 4;
        int dg = (e & 15) << 2;
        *(float4*)&sdst[r * 68 + dg] = *(const float4*)(g + (size_t)r * rowStride + dg);
    }
}

// ---------------------------------------------------------------------------
// Flash attention — tensor-core version.
// QK^T: 3xTF32 (scores ~fp32 accurate -> m, 1/l flip-safe for pruning path).
// P*V : single TF32 (y path only; within 1e-3 budget).
// Block = (b,h,qt), 256 thr / 8 warps.
//   QK:  warp (qw = wid&3 -> 16 q rows, wh = wid>>2 -> 32 k cols)
//   PV:  warp (qw -> 16 q rows, wh -> 32 d cols), accum persists across kt.
//   Softmax: thread (srow = tid>>2, scg = tid&3 -> 16 cols), m/l in regs.
// Stores y, m, and 1/l.
// ---------------------------------------------------------------------------
__global__ __launch_bounds__(256) void attn_kernel(
    const float* __restrict__ qkv, const float* __restrict__ attmask,
    float* __restrict__ y, float* __restrict__ gm, float* __restrict__ gl)
{
    extern __shared__ __align__(16) float sm[];
    float* Qs    = sm;                 // [q][d]  64x68
    float* Ks    = sm + 64 * 68;       // [k][d]  64x68
    float* Vt    = sm + 2 * 64 * 68;   // [d][k]  64x68 (transposed)
    float* Ss    = sm + 3 * 64 * 68;   // [q][k]  64x68 scores -> P
    float* Alpha = sm + 4 * 64 * 68;   // [64]
    float* Mrow  = Alpha + 64;         // [64]
    float* Lrow  = Mrow + 64;          // [64]
    float* Am    = Lrow + 64;          // [64] attention_mask tile

    const int bh = blockIdx.y, b = bh >> 4, h = bh & 15;
    const int qt = blockIdx.x;
    const int tid = threadIdx.x;
    const int wid = tid >> 5, lane = tid & 31;
    const int g = lane >> 2, tg = lane & 3;
    const int qr0 = (wid & 3) * 16;    // warp q-row base
    const int wh  = wid >> 2;          // 0/1: k-half (QK) or d-half (PV)
    const int srow = tid >> 2;         // softmax row
    const int scg  = tid & 3;          // softmax col group (16 cols)
    const float scale = 0.125f;
    const int bhT = bh * T_;

    const float* qbase = qkv + ((size_t)(b * T_ + qt * 64)) * (3 * C_) + h * 64;
    load_tile_R(qbase, 3 * C_, Qs, tid);

    float m_ = -INFINITY, l_ = 0.f;    // per softmax row (replicated x4)
    float cpv[4][4];
#pragma unroll
    for (int nt = 0; nt < 4; nt++)
#pragma unroll
        for (int i = 0; i < 4; i++) cpv[nt][i] = 0.f;

    const int qg_s = qt * 64 + srow;   // softmax row's global q index

    for (int kt = 0; kt <= qt; kt++) {
        __syncthreads();   // (A) previous PV reads done
        const float* kb = qkv + ((size_t)(b * T_ + kt * 64)) * (3 * C_) + C_ + h * 64;
        load_tile_R(kb, 3 * C_, Ks, tid);
        load_tile_T(kb + C_, 3 * C_, Vt, tid);
        if (tid < 64) Am[tid] = attmask[b * T_ + kt * 64 + tid];
        __syncthreads();   // (B) tiles ready

        // ---- QK^T (3xTF32) ----
        {
            float c[4][4];
#pragma unroll
            for (int nt = 0; nt < 4; nt++)
#pragma unroll
                for (int i = 0; i < 4; i++) c[nt][i] = 0.f;
#pragma unroll
            for (int s = 0; s < 8; s++) {
                const float* ap = Qs + (qr0 + g) * 68 + s * 8 + tg;
                float x0 = ap[0];
                float x1 = ap[8 * 68];
                float x2 = ap[4];
                float x3 = ap[8 * 68 + 4];
                uint32_t ah0 = cvt_tf32(x0), ah1 = cvt_tf32(x1);
                uint32_t ah2 = cvt_tf32(x2), ah3 = cvt_tf32(x3);
                uint32_t al0 = __float_as_uint(x0 - __uint_as_float(ah0));
                uint32_t al1 = __float_as_uint(x1 - __uint_as_float(ah1));
                uint32_t al2 = __float_as_uint(x2 - __uint_as_float(ah2));
                uint32_t al3 = __float_as_uint(x3 - __uint_as_float(ah3));
#pragma unroll
                for (int nt = 0; nt < 4; nt++) {
                    const float* bp = Ks + (wh * 32 + nt * 8 + g) * 68 + s * 8 + tg;
                    float y0 = bp[0], y1 = bp[4];
                    uint32_t bh0 = cvt_tf32(y0), bh1 = cvt_tf32(y1);
                    uint32_t bl0 = __float_as_uint(y0 - __uint_as_float(bh0));
                    uint32_t bl1 = __float_as_uint(y1 - __uint_as_float(bh1));
                    mma_tf32(c[nt], ah0, ah1, ah2, ah3, bl0, bl1);
                    mma_tf32(c[nt], al0, al1, al2, al3, bh0, bh1);
                    mma_tf32(c[nt], ah0, ah1, ah2, ah3, bh0, bh1);
                }
            }
            // scale + mask + store scores
            const int qg0 = qt * 64 + qr0 + g;
            const int qg8 = qg0 + 8;
#pragma unroll
            for (int nt = 0; nt < 4; nt++) {
                int kcol = wh * 32 + nt * 8 + 2 * tg;
                int kg0 = kt * 64 + kcol, kg1 = kg0 + 1;
                float a0 = Am[kcol], a1 = Am[kcol + 1];
                float s00 = (kg0 > qg0 || a0 == 0.f) ? -INFINITY : c[nt][0] * scale;
                float s01 = (kg1 > qg0 || a1 == 0.f) ? -INFINITY : c[nt][1] * scale;
                float s80 = (kg0 > qg8 || a0 == 0.f) ? -INFINITY : c[nt][2] * scale;
                float s81 = (kg1 > qg8 || a1 == 0.f) ? -INFINITY : c[nt][3] * scale;
                *(float2*)&Ss[(qr0 + g) * 68 + kcol]     = make_float2(s00, s01);
                *(float2*)&Ss[(qr0 + g + 8) * 68 + kcol] = make_float2(s80, s81);
            }
        }
        __syncthreads();   // (C) scores ready

        // ---- softmax (online, per row) ----
        {
            float sv[16];
            float lmax = -INFINITY;
            const int base = srow * 68 + scg * 16;
#pragma unroll
            for (int i = 0; i < 4; i++) {
                float4 v = *(const float4*)&Ss[base + i * 4];
                sv[i*4+0] = v.x; sv[i*4+1] = v.y; sv[i*4+2] = v.z; sv[i*4+3] = v.w;
                lmax = fmaxf(lmax, fmaxf(fmaxf(v.x, v.y), fmaxf(v.z, v.w)));
            }
            lmax = fmaxf(lmax, __shfl_xor_sync(0xffffffffu, lmax, 1));
            lmax = fmaxf(lmax, __shfl_xor_sync(0xffffffffu, lmax, 2));
            float mn = fmaxf(m_, lmax);
            float alpha = (mn > m_) ? __expf(m_ - mn) : 1.f;
            float lsum = 0.f;
#pragma unroll
            for (int i = 0; i < 16; i++) {
                float p = (sv[i] == -INFINITY) ? 0.f : __expf(sv[i] - mn);
                sv[i] = p;
                lsum += p;
            }
#pragma unroll
            for (int i = 0; i < 4; i++)
                *(float4*)&Ss[base + i * 4] = make_float4(sv[i*4+0], sv[i*4+1],
                                                          sv[i*4+2], sv[i*4+3]);
            lsum += __shfl_xor_sync(0xffffffffu, lsum, 1);
            lsum += __shfl_xor_sync(0xffffffffu, lsum, 2);
            l_ = l_ * alpha + lsum;
            m_ = mn;
            if (scg == 0) Alpha[srow] = alpha;
        }
        __syncthreads();   // (D) P + Alpha ready

        // ---- P*V (single TF32), accumulate with alpha rescale ----
        {
            float a0 = Alpha[qr0 + g];
            float a8 = Alpha[qr0 + g + 8];
#pragma unroll
            for (int nt = 0; nt < 4; nt++) {
                cpv[nt][0] *= a0; cpv[nt][1] *= a0;
                cpv[nt][2] *= a8; cpv[nt][3] *= a8;
            }
#pragma unroll
            for (int s = 0; s < 8; s++) {
                const float* ap = Ss + (qr0 + g) * 68 + s * 8 + tg;
                uint32_t pa0 = cvt_tf32(ap[0]);
                uint32_t pa1 = cvt_tf32(ap[8 * 68]);
                uint32_t pa2 = cvt_tf32(ap[4]);
                uint32_t pa3 = cvt_tf32(ap[8 * 68 + 4]);
#pragma unroll
                for (int nt = 0; nt < 4; nt++) {
                    const float* bp = Vt + (wh * 32 + nt * 8 + g) * 68 + s * 8 + tg;
                    mma_tf32(cpv[nt], pa0, pa1, pa2, pa3,
                             cvt_tf32(bp[0]), cvt_tf32(bp[4]));
                }
            }
        }
    }

    // publish m, l
    if (scg == 0) { Mrow[srow] = m_; Lrow[srow] = l_; }
    __syncthreads();

    // y = cpv / l
    {
        float inv0 = 1.f / Lrow[qr0 + g];
        float inv8 = 1.f / Lrow[qr0 + g + 8];
        float* y0 = y + ((size_t)(b * T_ + qt * 64 + qr0 + g)) * C_ + h * 64;
        float* y8 = y + ((size_t)(b * T_ + qt * 64 + qr0 + g + 8)) * C_ + h * 64;
#pragma unroll
        for (int nt = 0; nt < 4; nt++) {
            int col = wh * 32 + nt * 8 + 2 * tg;
            *(float2*)(y0 + col) = make_float2(cpv[nt][0] * inv0, cpv[nt][1] * inv0);
            *(float2*)(y8 + col) = make_float2(cpv[nt][2] * inv8, cpv[nt][3] * inv8);
        }
    }
    if (tid < 64) {
        gm[bhT + qt * 64 + tid] = Mrow[tid];
        gl[bhT + qt * 64 + tid] = 1.f / Lrow[tid];
    }
}

// ---------------------------------------------------------------------------
// Importance pass — tensor-core 3xTF32 scores, deterministic column sums.
// (unchanged from R9)
// ---------------------------------------------------------------------------
__global__ __launch_bounds__(256) void imp_kernel(
    const float* __restrict__ qkv, const float* __restrict__ attmask,
    const float* __restrict__ gm, const float* __restrict__ gl,
    float* __restrict__ impH)
{
    __shared__ __align__(16) float Ks[64 * 68];
    __shared__ __align__(16) float Qs[64 * 68];
    __shared__ float part[2][64];

    const int bh = blockIdx.y, b = bh >> 4, h = bh & 15;
    const int kt = blockIdx.x;
    const int tid = threadIdx.x;
    const int wid = tid >> 5, lane = tid & 31;
    const int g = lane >> 2, tg = lane & 3;
    const int kr0 = (wid & 3) * 16;
    const int qh  = wid >> 2;
    const int qc0 = qh * 32;
    const float scale = 0.125f;
    const int bhT = bh * T_;

    const float* kb = qkv + ((size_t)(b * T_ + kt * 64)) * (3 * C_) + C_ + h * 64;
    load_tile_R(kb, 3 * C_, Ks, tid);

    const int kg0 = kt * 64 + kr0 + g;
    const int kg1 = kg0 + 8;
    const float amk0 = attmask[b * T_ + kt * 64 + kr0 + g];
    const float amk1 = attmask[b * T_ + kt * 64 + kr0 + g + 8];

    float imp0 = 0.f, imp1 = 0.f;

    for (int qt = kt; qt < NT_; qt++) {
        __syncthreads();
        load_tile_R(qkv + ((size_t)(b * T_ + qt * 64)) * (3 * C_) + h * 64, 3 * C_, Qs, tid);
        __syncthreads();

        float c[4][4];
#pragma unroll
        for (int nt = 0; nt < 4; nt++)
#pragma unroll
            for (int i = 0; i < 4; i++) c[nt][i] = 0.f;

#pragma unroll
        for (int s = 0; s < 8; s++) {
            const float* ap = Ks + (kr0 + g) * 68 + s * 8 + tg;
            float x0 = ap[0];
            float x1 = ap[8 * 68];
            float x2 = ap[4];
            float x3 = ap[8 * 68 + 4];
            uint32_t kh0 = cvt_tf32(x0), kh1 = cvt_tf32(x1);
            uint32_t kh2 = cvt_tf32(x2), kh3 = cvt_tf32(x3);
            uint32_t kl0 = __float_as_uint(x0 - __uint_as_float(kh0));
            uint32_t kl1 = __float_as_uint(x1 - __uint_as_float(kh1));
            uint32_t kl2 = __float_as_uint(x2 - __uint_as_float(kh2));
            uint32_t kl3 = __float_as_uint(x3 - __uint_as_float(kh3));
#pragma unroll
            for (int nt = 0; nt < 4; nt++) {
                const float* bp = Qs + (qc0 + nt * 8 + g) * 68 + s * 8 + tg;
                float y0 = bp[0], y1 = bp[4];
                uint32_t bh0 = cvt_tf32(y0), bh1 = cvt_tf32(y1);
                uint32_t bl0 = __float_as_uint(y0 - __uint_as_float(bh0));
                uint32_t bl1 = __float_as_uint(y1 - __uint_as_float(bh1));
                mma_tf32(c[nt], kh0, kh1, kh2, kh3, bl0, bl1);
                mma_tf32(c[nt], kl0, kl1, kl2, kl3, bh0, bh1);
                mma_tf32(c[nt], kh0, kh1, kh2, kh3, bh0, bh1);
            }
        }

#pragma unroll
        for (int nt = 0; nt < 4; nt++) {
            const int qg0 = qt * 64 + qc0 + nt * 8 + 2 * tg;
            const int qg1 = qg0 + 1;
            const float mq0 = gm[bhT + qg0], mq1 = gm[bhT + qg1];
            const float rq0 = gl[bhT + qg0], rq1 = gl[bhT + qg1];
            if (qg0 >= kg0) imp0 += amk0 * __expf(fmaf(c[nt][0], scale, -mq0)) * rq0;
            if (qg1 >= kg0) imp0 += amk0 * __expf(fmaf(c[nt][1], scale, -mq1)) * rq1;
            if (qg0 >= kg1) imp1 += amk1 * __expf(fmaf(c[nt][2], scale, -mq0)) * rq0;
            if (qg1 >= kg1) imp1 += amk1 * __expf(fmaf(c[nt][3], scale, -mq1)) * rq1;
        }
    }

    imp0 += __shfl_xor_sync(0xffffffffu, imp0, 1);
    imp0 += __shfl_xor_sync(0xffffffffu, imp0, 2);
    imp1 += __shfl_xor_sync(0xffffffffu, imp1, 1);
    imp1 += __shfl_xor_sync(0xffffffffu, imp1, 2);
    if (tg == 0) {
        part[qh][kr0 + g] = imp0;
        part[qh][kr0 + 8 + g] = imp1;
    }
    __syncthreads();
    if (tid < 64)
        impH[bhT + kt * 64 + tid] = part[0][tid] + part[1][tid];
}

// ---------------------------------------------------------------------------
// Finalize pruning mask
// ---------------------------------------------------------------------------
__global__ __launch_bounds__(256) void finalize_mask(
    const float* __restrict__ impH, const float* __restrict__ attmask,
    const float* __restrict__ prot, const float* __restrict__ thresh,
    float* __restrict__ cm, float* __restrict__ out_mask,
    float* __restrict__ out_loss)
{
    int i = blockIdx.x * 256 + threadIdx.x;
    int b = i / T_, t = i % T_;
    float s = 0.f;
#pragma unroll
    for (int h = 0; h < H_; h++) s += impH[(b * H_ + h) * T_ + t];
    float imp = s * (1.f / ((float)H_ * (float)T_));
    float pm = (imp >= thresh[0]) ? 1.f : 0.f;
    if (prot[i] > 0.f) pm = 1.f;
    float c = attmask[i] * pm;
    cm[i] = c;
    out_mask[i] = c;
    if (i == 0) out_loss[0] = 0.f;
}

// ---------------------------------------------------------------------------
// Launch
// ---------------------------------------------------------------------------
extern "C" void kernel_launch(void* const* d_in, const int* in_sizes, int n_in,
                              void* d_out, int out_size)
{
    const float* x              = (const float*)d_in[0];
    const float* attention_mask = (const float*)d_in[1];
    const float* protected_mask = (const float*)d_in[2];
    const float* ln1_w          = (const float*)d_in[3];
    const float* ln1_b          = (const float*)d_in[4];
    const float* c_attn_w       = (const float*)d_in[5];
    const float* c_attn_b       = (const float*)d_in[6];
    const float* c_proj_w       = (const float*)d_in[7];
    const float* c_proj_b       = (const float*)d_in[8];
    const float* ln2_w          = (const float*)d_in[9];
    const float* ln2_b          = (const float*)d_in[10];
    const float* fc_w           = (const float*)d_in[11];
    const float* fc_b           = (const float*)d_in[12];
    const float* fcproj_w       = (const float*)d_in[13];
    const float* fcproj_b       = (const float*)d_in[14];
    const float* threshold      = (const float*)d_in[15];

    float* out      = (float*)d_out;
    float* out_mask = out + (size_t)M_ * C_;
    float* out_loss = out_mask + M_;

    float *p_h, *p_qkv, *p_y, *p_m, *p_l, *p_imp, *p_cm, *p_xres, *p_fc;
    cudaGetSymbolAddress((void**)&p_h,    g_h);
    cudaGetSymbolAddress((void**)&p_qkv,  g_qkv);
    cudaGetSymbolAddress((void**)&p_y,    g_y);
    cudaGetSymbolAddress((void**)&p_m,    g_m);
    cudaGetSymbolAddress((void**)&p_l,    g_l);
    cudaGetSymbolAddress((void**)&p_imp,  g_impH);
    cudaGetSymbolAddress((void**)&p_cm,   g_cm);
    cudaGetSymbolAddress((void**)&p_xres, g_xres);
    cudaGetSymbolAddress((void**)&p_fc,   g_fc);

    // Qs + Ks + Vt + Ss + Alpha/Mrow/Lrow/Am = 4*64*68 + 256 floats
    const size_t attn_smem = (size_t)(4 * 64 * 68 + 256) * sizeof(float); // 70656B
    cudaFuncSetAttribute(attn_kernel, cudaFuncAttributeMaxDynamicSharedMemorySize,
                         (int)attn_smem);

    // 1. LN1
    ln_kernel<<<M_, 256>>>(x, ln1_w, ln1_b, p_h);
    // 2a. Q,K columns: 3xTF32 (threshold-sensitive path)
    gemm_tc<0,1><<<dim3(2 * C_ / 128, M_ / 128), 256>>>(
        p_h, c_attn_w, c_attn_b, p_qkv, 3 * C_, C_, nullptr, nullptr);
    // 2b. V columns: single TF32
    gemm_tc<0,0><<<dim3(C_ / 128, M_ / 128), 256>>>(
        p_h, c_attn_w + (size_t)(2 * C_) * C_, c_attn_b + 2 * C_, p_qkv + 2 * C_,
        3 * C_, C_, nullptr, nullptr);
    // 3. Flash attention (tensor-core) -> y, (m, 1/l)
    attn_kernel<<<dim3(NT_, B_ * H_), 256, attn_smem>>>(
        p_qkv, attention_mask, p_y, p_m, p_l);
    // 4. Importance column sums per head (tensor-core, deterministic)
    imp_kernel<<<dim3(NT_, B_ * H_), 256>>>(p_qkv, attention_mask, p_m, p_l, p_imp);
    // 5. Combined mask
    finalize_mask<<<M_ / 256, 256>>>(p_imp, attention_mask, protected_mask,
                                     threshold, p_cm, out_mask, out_loss);
    // 6. proj + residual + prune mask, TF32
    gemm_tc<2,0><<<dim3(C_ / 128, M_ / 128), 256>>>(
        p_y, c_proj_w, c_proj_b, p_xres, C_, C_, x, p_cm);
    // 7. LN2
    ln_kernel<<<M_, 256>>>(p_xres, ln2_w, ln2_b, p_h);
    // 8. fc + GELU, TF32
    gemm_tc<1,0><<<dim3(4 * C_ / 128, M_ / 128), 256>>>(
        p_h, fc_w, fc_b, p_fc, 4 * C_, C_, nullptr, nullptr);
    // 9. fcproj + residual -> d_out, TF32
    gemm_tc<3,0><<<dim3(C_ / 128, M_ / 128), 256>>>(
        p_fc, fcproj_w, fcproj_b, out, C_, 4 * C_, p_xres, nullptr);
}

// round 13
// speedup vs baseline: 1.9583x; 1.0097x over previous
#include <cuda_runtime.h>
#include <math.h>
#include <stdint.h>

// Problem constants
#define B_  4
#define T_  2048
#define C_  1024
#define H_  16
#define HS_ 64
#define M_  (B_*T_)      // 8192 rows
#define NT_ (T_/64)      // 32 tiles of 64

// ---------------------------------------------------------------------------
// Scratch (device globals; no runtime allocation allowed)
// ---------------------------------------------------------------------------
__device__ float g_h   [M_*C_];            // LN output (reused for LN1 and LN2)
__device__ float g_qkv [M_*3*C_];          // QKV
__device__ float g_y   [M_*C_];            // attention output (B,T,C)
__device__ float g_m   [B_*H_*T_];         // per-row softmax max (scaled scores)
__device__ float g_l   [B_*H_*T_];         // per-row 1/softmax-denominator
__device__ float g_impH[B_*H_*T_];         // per-head importance column sums
__device__ float g_cm  [M_];               // combined mask per token
__device__ float g_xres[M_*C_];            // x after attn residual + prune mask
__device__ float g_fc  [M_*4*C_];          // MLP hidden

// ---------------------------------------------------------------------------
// LayerNorm: one block (256 thr) per row of C=1024, 4 elems/thread
// ---------------------------------------------------------------------------
__global__ __launch_bounds__(256) void ln_kernel(
    const float* __restrict__ x, const float* __restrict__ w,
    const float* __restrict__ bias, float* __restrict__ out)
{
    int row = blockIdx.x;
    int tid = threadIdx.x;
    const float* xr = x + (size_t)row * C_;
    float4 v = *(const float4*)(xr + tid * 4);
    float s1 = v.x + v.y + v.z + v.w;
    float s2 = v.x*v.x + v.y*v.y + v.z*v.z + v.w*v.w;
#pragma unroll
    for (int o = 16; o; o >>= 1) {
        s1 += __shfl_xor_sync(0xffffffffu, s1, o);
        s2 += __shfl_xor_sync(0xffffffffu, s2, o);
    }
    __shared__ float sh1[8], sh2[8];
    int wi = tid >> 5;
    if ((tid & 31) == 0) { sh1[wi] = s1; sh2[wi] = s2; }
    __syncthreads();
    float t1 = 0.f, t2 = 0.f;
#pragma unroll
    for (int i = 0; i < 8; i++) { t1 += sh1[i]; t2 += sh2[i]; }
    float mean = t1 * (1.f / C_);
    float var  = t2 * (1.f / C_) - mean * mean;
    float inv  = rsqrtf(var + 1e-5f);
    float4 wv = *(const float4*)(w + tid * 4);
    float4 bv = *(const float4*)(bias + tid * 4);
    float4 o;
    o.x = (v.x - mean) * inv * wv.x + bv.x;
    o.y = (v.y - mean) * inv * wv.y + bv.y;
    o.z = (v.z - mean) * inv * wv.z + bv.z;
    o.w = (v.w - mean) * inv * wv.w + bv.w;
    *(float4*)(out + (size_t)row * C_ + tid * 4) = o;
}

// ---------------------------------------------------------------------------
// Tensor-core TF32 helpers
// ---------------------------------------------------------------------------
__device__ __forceinline__ uint32_t cvt_tf32(float x) {
    uint32_t r; asm("cvt.rna.tf32.f32 %0, %1;" : "=r"(r) : "f"(x)); return r;
}
__device__ __forceinline__ void mma_tf32(float* c,
    uint32_t a0, uint32_t a1, uint32_t a2, uint32_t a3,
    uint32_t b0, uint32_t b1)
{
    asm volatile(
        "mma.sync.aligned.m16n8k8.row.col.f32.tf32.tf32.f32 "
        "{%0,%1,%2,%3}, {%4,%5,%6,%7}, {%8,%9}, {%0,%1,%2,%3};"
        : "+f"(c[0]), "+f"(c[1]), "+f"(c[2]), "+f"(c[3])
        : "r"(a0), "r"(a1), "r"(a2), "r"(a3), "r"(b0), "r"(b1));
}

// ---------------------------------------------------------------------------
// TF32 tensor-core GEMM: Out[M,N] = A[M,K] @ W[N,K]^T (+bias, +epilogue)
// EPI 0: bias only | 1: +GELU | 2: (res+bias+acc)*rowmask | 3: res+bias+acc
// PREC 0: single TF32 | PREC 1: 3xTF32 split (~fp32 accuracy)
// 128x128 block, BK=32, 256 threads. Static smem single buffer with
// REGISTER PREFETCH: next k-tile's LDGs issued before the current tile's
// MMA burst, landed into smem after a sync. Hides global latency without
// cp.async / dynamic smem.
// ---------------------------------------------------------------------------
#define GSTRIDE 36

template<int EPI, int PREC>
__global__ __launch_bounds__(256) void gemm_tc(
    const float* __restrict__ A, const float* __restrict__ W,
    const float* __restrict__ bias, float* __restrict__ Out,
    int Ndim, int Kdim,
    const float* __restrict__ res, const float* __restrict__ rowmask)
{
    __shared__ __align__(16) float Sa[128 * GSTRIDE];
    __shared__ __align__(16) float Sw[128 * GSTRIDE];
    const int tid = threadIdx.x;
    const int row0 = blockIdx.y * 128, col0 = blockIdx.x * 128;

    const int wid  = tid >> 5, lane = tid & 31;
    const int g    = lane >> 2, tg = lane & 3;
    const int wr   = (wid >> 2) * 64;
    const int wc   = (wid & 3) * 32;

    // Per-thread load slots (4 granules x (A,W))
    const int lr  = tid >> 3;             // 0..31 row step base (row = lr + i*32? no:)
    // slot mapping identical to previous rounds: slot = i*256+tid
    float4 pa[4], pw[4];

    auto issue_loads = [&](int k0) {
#pragma unroll
        for (int i = 0; i < 4; i++) {
            int slot = i * 256 + tid;
            int r  = slot >> 3;
            int kg = (slot & 7) << 2;
            pa[i] = *(const float4*)(A + (size_t)(row0 + r) * Kdim + k0 + kg);
            pw[i] = *(const float4*)(W + (size_t)(col0 + r) * Kdim + k0 + kg);
        }
    };
    auto store_stage = [&]() {
#pragma unroll
        for (int i = 0; i < 4; i++) {
            int slot = i * 256 + tid;
            int r  = slot >> 3;
            int kg = (slot & 7) << 2;
            *(float4*)&Sa[r * GSTRIDE + kg] = pa[i];
            *(float4*)&Sw[r * GSTRIDE + kg] = pw[i];
        }
    };

    float acc[4][4][4];
#pragma unroll
    for (int mt = 0; mt < 4; mt++)
#pragma unroll
        for (int nt = 0; nt < 4; nt++)
#pragma unroll
            for (int i = 0; i < 4; i++) acc[mt][nt][i] = 0.f;

    issue_loads(0);
    store_stage();
    __syncthreads();

    const int KT = Kdim >> 5;
    for (int kt = 0; kt < KT; kt++) {
        const bool has_next = (kt + 1) < KT;
        if (has_next) issue_loads((kt + 1) << 5);   // overlap with MMA below

#pragma unroll
        for (int ks = 0; ks < 4; ks++) {
            const int kk = ks * 8;
            uint32_t ah[4][4], bh[4][2];
            uint32_t al[4][4], bl[4][2];
#pragma unroll
            for (int mt = 0; mt < 4; mt++) {
                const float* p = Sa + (wr + mt * 16 + g) * GSTRIDE + kk + tg;
                float x0 = p[0];
                float x1 = p[8 * GSTRIDE];
                float x2 = p[4];
                float x3 = p[8 * GSTRIDE + 4];
                ah[mt][0] = cvt_tf32(x0); ah[mt][1] = cvt_tf32(x1);
                ah[mt][2] = cvt_tf32(x2); ah[mt][3] = cvt_tf32(x3);
                if (PREC == 1) {
                    al[mt][0] = __float_as_uint(x0 - __uint_as_float(ah[mt][0]));
                    al[mt][1] = __float_as_uint(x1 - __uint_as_float(ah[mt][1]));
                    al[mt][2] = __float_as_uint(x2 - __uint_as_float(ah[mt][2]));
                    al[mt][3] = __float_as_uint(x3 - __uint_as_float(ah[mt][3]));
                }
            }
#pragma unroll
            for (int nt = 0; nt < 4; nt++) {
                const float* p = Sw + (wc + nt * 8 + g) * GSTRIDE + kk + tg;
                float x0 = p[0];
                float x1 = p[4];
                bh[nt][0] = cvt_tf32(x0); bh[nt][1] = cvt_tf32(x1);
                if (PREC == 1) {
                    bl[nt][0] = __float_as_uint(x0 - __uint_as_float(bh[nt][0]));
                    bl[nt][1] = __float_as_uint(x1 - __uint_as_float(bh[nt][1]));
                }
            }
#pragma unroll
            for (int mt = 0; mt < 4; mt++)
#pragma unroll
                for (int nt = 0; nt < 4; nt++) {
                    if (PREC == 1) {
                        mma_tf32(acc[mt][nt], ah[mt][0], ah[mt][1], ah[mt][2], ah[mt][3],
                                 bl[nt][0], bl[nt][1]);
                        mma_tf32(acc[mt][nt], al[mt][0], al[mt][1], al[mt][2], al[mt][3],
                                 bh[nt][0], bh[nt][1]);
                    }
                    mma_tf32(acc[mt][nt], ah[mt][0], ah[mt][1], ah[mt][2], ah[mt][3],
                             bh[nt][0], bh[nt][1]);
                }
        }

        if (has_next) {
            __syncthreads();     // everyone done reading current stage
            store_stage();
            __syncthreads();     // new stage visible
        }
    }

#pragma unroll
    for (int mt = 0; mt < 4; mt++) {
#pragma unroll
        for (int half = 0; half < 2; half++) {
            int r = row0 + wr + mt * 16 + g + half * 8;
            float rmv = (EPI == 2) ? rowmask[r] : 0.f;
#pragma unroll
            for (int nt = 0; nt < 4; nt++) {
                int c = col0 + wc + nt * 8 + tg * 2;
                float o0 = acc[mt][nt][half * 2 + 0] + bias[c];
                float o1 = acc[mt][nt][half * 2 + 1] + bias[c + 1];
                if (EPI == 1) {
                    o0 = 0.5f * o0 * (1.f + erff(o0 * 0.7071067811865476f));
                    o1 = 0.5f * o1 * (1.f + erff(o1 * 0.7071067811865476f));
                } else if (EPI == 2) {
                    const float* rp = res + (size_t)r * Ndim + c;
                    o0 = (rp[0] + o0) * rmv;
                    o1 = (rp[1] + o1) * rmv;
                } else if (EPI == 3) {
                    const float* rp = res + (size_t)r * Ndim + c;
                    o0 += rp[0];
                    o1 += rp[1];
                }
                *(float2*)(Out + (size_t)r * Ndim + c) = make_float2(o0, o1);
            }
        }
    }
}

// ---------------------------------------------------------------------------
// Tile loaders (64 rows x 64 dims), pad-68 smem
// ---------------------------------------------------------------------------
__device__ __forceinline__ void load_tile_T(const float* __restrict__ g, int rowStride,
                                            float* __restrict__ sdst, int tid)
{
#pragma unroll
    for (int i = 0; i < 4; i++) {
        int e  = i * 256 + tid;
        int r  = e >> 4;
        int dg = (e & 15) << 2;
        float4 v = *(const float4*)(g + (size_t)r * rowStride + dg);
        sdst[(dg+0)*68 + r] = v.x;
        sdst[(dg+1)*68 + r] = v.y;
        sdst[(dg+2)*68 + r] = v.z;
        sdst[(dg+3)*68 + r] = v.w;
    }
}

__device__ __forceinline__ void load_tile_R(const float* __restrict__ g, int rowStride,
                                            float* __restrict__ sdst, int tid)
{
#pragma unroll
    for (int i = 0; i < 4; i++) {
        int e  = i * 256 + tid;
        int r  = e >> 4;
        int dg = (e & 15) << 2;
        *(float4*)&sdst[r * 68 + dg] = *(const float4*)(g + (size_t)r * rowStride + dg);
    }
}

// ---------------------------------------------------------------------------
// Flash attention — tensor-core (unchanged from R10).
// QK^T: 3xTF32 (flip-safe), P*V: single TF32.
// ---------------------------------------------------------------------------
__global__ __launch_bounds__(256) void attn_kernel(
    const float* __restrict__ qkv, const float* __restrict__ attmask,
    float* __restrict__ y, float* __restrict__ gm, float* __restrict__ gl)
{
    extern __shared__ __align__(16) float sm[];
    float* Qs    = sm;
    float* Ks    = sm + 64 * 68;
    float* Vt    = sm + 2 * 64 * 68;
    float* Ss    = sm + 3 * 64 * 68;
    float* Alpha = sm + 4 * 64 * 68;
    float* Mrow  = Alpha + 64;
    float* Lrow  = Mrow + 64;
    float* Am    = Lrow + 64;

    const int bh = blockIdx.y, b = bh >> 4, h = bh & 15;
    const int qt = blockIdx.x;
    const int tid = threadIdx.x;
    const int wid = tid >> 5, lane = tid & 31;
    const int g = lane >> 2, tg = lane & 3;
    const int qr0 = (wid & 3) * 16;
    const int wh  = wid >> 2;
    const int srow = tid >> 2;
    const int scg  = tid & 3;
    const float scale = 0.125f;
    const int bhT = bh * T_;

    const float* qbase = qkv + ((size_t)(b * T_ + qt * 64)) * (3 * C_) + h * 64;
    load_tile_R(qbase, 3 * C_, Qs, tid);

    float m_ = -INFINITY, l_ = 0.f;
    float cpv[4][4];
#pragma unroll
    for (int nt = 0; nt < 4; nt++)
#pragma unroll
        for (int i = 0; i < 4; i++) cpv[nt][i] = 0.f;

    for (int kt = 0; kt <= qt; kt++) {
        __syncthreads();
        const float* kb = qkv + ((size_t)(b * T_ + kt * 64)) * (3 * C_) + C_ + h * 64;
        load_tile_R(kb, 3 * C_, Ks, tid);
        load_tile_T(kb + C_, 3 * C_, Vt, tid);
        if (tid < 64) Am[tid] = attmask[b * T_ + kt * 64 + tid];
        __syncthreads();

        // ---- QK^T (3xTF32) ----
        {
            float c[4][4];
#pragma unroll
            for (int nt = 0; nt < 4; nt++)
#pragma unroll
                for (int i = 0; i < 4; i++) c[nt][i] = 0.f;
#pragma unroll
            for (int s = 0; s < 8; s++) {
                const float* ap = Qs + (qr0 + g) * 68 + s * 8 + tg;
                float x0 = ap[0];
                float x1 = ap[8 * 68];
                float x2 = ap[4];
                float x3 = ap[8 * 68 + 4];
                uint32_t ah0 = cvt_tf32(x0), ah1 = cvt_tf32(x1);
                uint32_t ah2 = cvt_tf32(x2), ah3 = cvt_tf32(x3);
                uint32_t al0 = __float_as_uint(x0 - __uint_as_float(ah0));
                uint32_t al1 = __float_as_uint(x1 - __uint_as_float(ah1));
                uint32_t al2 = __float_as_uint(x2 - __uint_as_float(ah2));
                uint32_t al3 = __float_as_uint(x3 - __uint_as_float(ah3));
#pragma unroll
                for (int nt = 0; nt < 4; nt++) {
                    const float* bp = Ks + (wh * 32 + nt * 8 + g) * 68 + s * 8 + tg;
                    float y0 = bp[0], y1 = bp[4];
                    uint32_t bh0 = cvt_tf32(y0), bh1 = cvt_tf32(y1);
                    uint32_t bl0 = __float_as_uint(y0 - __uint_as_float(bh0));
                    uint32_t bl1 = __float_as_uint(y1 - __uint_as_float(bh1));
                    mma_tf32(c[nt], ah0, ah1, ah2, ah3, bl0, bl1);
                    mma_tf32(c[nt], al0, al1, al2, al3, bh0, bh1);
                    mma_tf32(c[nt], ah0, ah1, ah2, ah3, bh0, bh1);
                }
            }
            const int qg0 = qt * 64 + qr0 + g;
            const int qg8 = qg0 + 8;
#pragma unroll
            for (int nt = 0; nt < 4; nt++) {
                int kcol = wh * 32 + nt * 8 + 2 * tg;
                int kg0 = kt * 64 + kcol, kg1 = kg0 + 1;
                float a0 = Am[kcol], a1 = Am[kcol + 1];
                float s00 = (kg0 > qg0 || a0 == 0.f) ? -INFINITY : c[nt][0] * scale;
                float s01 = (kg1 > qg0 || a1 == 0.f) ? -INFINITY : c[nt][1] * scale;
                float s80 = (kg0 > qg8 || a0 == 0.f) ? -INFINITY : c[nt][2] * scale;
                float s81 = (kg1 > qg8 || a1 == 0.f) ? -INFINITY : c[nt][3] * scale;
                *(float2*)&Ss[(qr0 + g) * 68 + kcol]     = make_float2(s00, s01);
                *(float2*)&Ss[(qr0 + g + 8) * 68 + kcol] = make_float2(s80, s81);
            }
        }
        __syncthreads();

        // ---- softmax (online, per row) ----
        {
            float sv[16];
            float lmax = -INFINITY;
            const int base = srow * 68 + scg * 16;
#pragma unroll
            for (int i = 0; i < 4; i++) {
                float4 v = *(const float4*)&Ss[base + i * 4];
                sv[i*4+0] = v.x; sv[i*4+1] = v.y; sv[i*4+2] = v.z; sv[i*4+3] = v.w;
                lmax = fmaxf(lmax, fmaxf(fmaxf(v.x, v.y), fmaxf(v.z, v.w)));
            }
            lmax = fmaxf(lmax, __shfl_xor_sync(0xffffffffu, lmax, 1));
            lmax = fmaxf(lmax, __shfl_xor_sync(0xffffffffu, lmax, 2));
            float mn = fmaxf(m_, lmax);
            float alpha = (mn > m_) ? __expf(m_ - mn) : 1.f;
            float lsum = 0.f;
#pragma unroll
            for (int i = 0; i < 16; i++) {
                float p = (sv[i] == -INFINITY) ? 0.f : __expf(sv[i] - mn);
                sv[i] = p;
                lsum += p;
            }
#pragma unroll
            for (int i = 0; i < 4; i++)
                *(float4*)&Ss[base + i * 4] = make_float4(sv[i*4+0], sv[i*4+1],
                                                          sv[i*4+2], sv[i*4+3]);
            lsum += __shfl_xor_sync(0xffffffffu, lsum, 1);
            lsum += __shfl_xor_sync(0xffffffffu, lsum, 2);
            l_ = l_ * alpha + lsum;
            m_ = mn;
            if (scg == 0) Alpha[srow] = alpha;
        }
        __syncthreads();

        // ---- P*V (single TF32) ----
        {
            float a0 = Alpha[qr0 + g];
            float a8 = Alpha[qr0 + g + 8];
#pragma unroll
            for (int nt = 0; nt < 4; nt++) {
                cpv[nt][0] *= a0; cpv[nt][1] *= a0;
                cpv[nt][2] *= a8; cpv[nt][3] *= a8;
            }
#pragma unroll
            for (int s = 0; s < 8; s++) {
                const float* ap = Ss + (qr0 + g) * 68 + s * 8 + tg;
                uint32_t pa0 = cvt_tf32(ap[0]);
                uint32_t pa1 = cvt_tf32(ap[8 * 68]);
                uint32_t pa2 = cvt_tf32(ap[4]);
                uint32_t pa3 = cvt_tf32(ap[8 * 68 + 4]);
#pragma unroll
                for (int nt = 0; nt < 4; nt++) {
                    const float* bp = Vt + (wh * 32 + nt * 8 + g) * 68 + s * 8 + tg;
                    mma_tf32(cpv[nt], pa0, pa1, pa2, pa3,
                             cvt_tf32(bp[0]), cvt_tf32(bp[4]));
                }
            }
        }
    }

    if (scg == 0) { Mrow[srow] = m_; Lrow[srow] = l_; }
    __syncthreads();

    {
        float inv0 = 1.f / Lrow[qr0 + g];
        float inv8 = 1.f / Lrow[qr0 + g + 8];
        float* y0 = y + ((size_t)(b * T_ + qt * 64 + qr0 + g)) * C_ + h * 64;
        float* y8 = y + ((size_t)(b * T_ + qt * 64 + qr0 + g + 8)) * C_ + h * 64;
#pragma unroll
        for (int nt = 0; nt < 4; nt++) {
            int col = wh * 32 + nt * 8 + 2 * tg;
            *(float2*)(y0 + col) = make_float2(cpv[nt][0] * inv0, cpv[nt][1] * inv0);
            *(float2*)(y8 + col) = make_float2(cpv[nt][2] * inv8, cpv[nt][3] * inv8);
        }
    }
    if (tid < 64) {
        gm[bhT + qt * 64 + tid] = Mrow[tid];
        gl[bhT + qt * 64 + tid] = 1.f / Lrow[tid];
    }
}

// ---------------------------------------------------------------------------
// Importance pass — tensor-core 3xTF32 scores (unchanged from R9)
// ---------------------------------------------------------------------------
__global__ __launch_bounds__(256) void imp_kernel(
    const float* __restrict__ qkv, const float* __restrict__ attmask,
    const float* __restrict__ gm, const float* __restrict__ gl,
    float* __restrict__ impH)
{
    __shared__ __align__(16) float Ks[64 * 68];
    __shared__ __align__(16) float Qs[64 * 68];
    __shared__ float part[2][64];

    const int bh = blockIdx.y, b = bh >> 4, h = bh & 15;
    const int kt = blockIdx.x;
    const int tid = threadIdx.x;
    const int wid = tid >> 5, lane = tid & 31;
    const int g = lane >> 2, tg = lane & 3;
    const int kr0 = (wid & 3) * 16;
    const int qh  = wid >> 2;
    const int qc0 = qh * 32;
    const float scale = 0.125f;
    const int bhT = bh * T_;

    const float* kb = qkv + ((size_t)(b * T_ + kt * 64)) * (3 * C_) + C_ + h * 64;
    load_tile_R(kb, 3 * C_, Ks, tid);

    const int kg0 = kt * 64 + kr0 + g;
    const int kg1 = kg0 + 8;
    const float amk0 = attmask[b * T_ + kt * 64 + kr0 + g];
    const float amk1 = attmask[b * T_ + kt * 64 + kr0 + g + 8];

    float imp0 = 0.f, imp1 = 0.f;

    for (int qt = kt; qt < NT_; qt++) {
        __syncthreads();
        load_tile_R(qkv + ((size_t)(b * T_ + qt * 64)) * (3 * C_) + h * 64, 3 * C_, Qs, tid);
        __syncthreads();

        float c[4][4];
#pragma unroll
        for (int nt = 0; nt < 4; nt++)
#pragma unroll
            for (int i = 0; i < 4; i++) c[nt][i] = 0.f;

#pragma unroll
        for (int s = 0; s < 8; s++) {
            const float* ap = Ks + (kr0 + g) * 68 + s * 8 + tg;
            float x0 = ap[0];
            float x1 = ap[8 * 68];
            float x2 = ap[4];
            float x3 = ap[8 * 68 + 4];
            uint32_t kh0 = cvt_tf32(x0), kh1 = cvt_tf32(x1);
            uint32_t kh2 = cvt_tf32(x2), kh3 = cvt_tf32(x3);
            uint32_t kl0 = __float_as_uint(x0 - __uint_as_float(kh0));
            uint32_t kl1 = __float_as_uint(x1 - __uint_as_float(kh1));
            uint32_t kl2 = __float_as_uint(x2 - __uint_as_float(kh2));
            uint32_t kl3 = __float_as_uint(x3 - __uint_as_float(kh3));
#pragma unroll
            for (int nt = 0; nt < 4; nt++) {
                const float* bp = Qs + (qc0 + nt * 8 + g) * 68 + s * 8 + tg;
                float y0 = bp[0], y1 = bp[4];
                uint32_t bh0 = cvt_tf32(y0), bh1 = cvt_tf32(y1);
                uint32_t bl0 = __float_as_uint(y0 - __uint_as_float(bh0));
                uint32_t bl1 = __float_as_uint(y1 - __uint_as_float(bh1));
                mma_tf32(c[nt], kh0, kh1, kh2, kh3, bl0, bl1);
                mma_tf32(c[nt], kl0, kl1, kl2, kl3, bh0, bh1);
                mma_tf32(c[nt], kh0, kh1, kh2, kh3, bh0, bh1);
            }
        }

#pragma unroll
        for (int nt = 0; nt < 4; nt++) {
            const int qg0 = qt * 64 + qc0 + nt * 8 + 2 * tg;
            const int qg1 = qg0 + 1;
            const float mq0 = gm[bhT + qg0], mq1 = gm[bhT + qg1];
            const float rq0 = gl[bhT + qg0], rq1 = gl[bhT + qg1];
            if (qg0 >= kg0) imp0 += amk0 * __expf(fmaf(c[nt][0], scale, -mq0)) * rq0;
            if (qg1 >= kg0) imp0 += amk0 * __expf(fmaf(c[nt][1], scale, -mq1)) * rq1;
            if (qg0 >= kg1) imp1 += amk1 * __expf(fmaf(c[nt][2], scale, -mq0)) * rq0;
            if (qg1 >= kg1) imp1 += amk1 * __expf(fmaf(c[nt][3], scale, -mq1)) * rq1;
        }
    }

    imp0 += __shfl_xor_sync(0xffffffffu, imp0, 1);
    imp0 += __shfl_xor_sync(0xffffffffu, imp0, 2);
    imp1 += __shfl_xor_sync(0xffffffffu, imp1, 1);
    imp1 += __shfl_xor_sync(0xffffffffu, imp1, 2);
    if (tg == 0) {
        part[qh][kr0 + g] = imp0;
        part[qh][kr0 + 8 + g] = imp1;
    }
    __syncthreads();
    if (tid < 64)
        impH[bhT + kt * 64 + tid] = part[0][tid] + part[1][tid];
}

// ---------------------------------------------------------------------------
// Finalize pruning mask
// ---------------------------------------------------------------------------
__global__ __launch_bounds__(256) void finalize_mask(
    const float* __restrict__ impH, const float* __restrict__ attmask,
    const float* __restrict__ prot, const float* __restrict__ thresh,
    float* __restrict__ cm, float* __restrict__ out_mask,
    float* __restrict__ out_loss)
{
    int i = blockIdx.x * 256 + threadIdx.x;
    int b = i / T_, t = i % T_;
    float s = 0.f;
#pragma unroll
    for (int h = 0; h < H_; h++) s += impH[(b * H_ + h) * T_ + t];
    float imp = s * (1.f / ((float)H_ * (float)T_));
    float pm = (imp >= thresh[0]) ? 1.f : 0.f;
    if (prot[i] > 0.f) pm = 1.f;
    float c = attmask[i] * pm;
    cm[i] = c;
    out_mask[i] = c;
    if (i == 0) out_loss[0] = 0.f;
}

// ---------------------------------------------------------------------------
// Launch
// ---------------------------------------------------------------------------
extern "C" void kernel_launch(void* const* d_in, const int* in_sizes, int n_in,
                              void* d_out, int out_size)
{
    const float* x              = (const float*)d_in[0];
    const float* attention_mask = (const float*)d_in[1];
    const float* protected_mask = (const float*)d_in[2];
    const float* ln1_w          = (const float*)d_in[3];
    const float* ln1_b          = (const float*)d_in[4];
    const float* c_attn_w       = (const float*)d_in[5];
    const float* c_attn_b       = (const float*)d_in[6];
    const float* c_proj_w       = (const float*)d_in[7];
    const float* c_proj_b       = (const float*)d_in[8];
    const float* ln2_w          = (const float*)d_in[9];
    const float* ln2_b          = (const float*)d_in[10];
    const float* fc_w           = (const float*)d_in[11];
    const float* fc_b           = (const float*)d_in[12];
    const float* fcproj_w       = (const float*)d_in[13];
    const float* fcproj_b       = (const float*)d_in[14];
    const float* threshold      = (const float*)d_in[15];

    float* out      = (float*)d_out;
    float* out_mask = out + (size_t)M_ * C_;
    float* out_loss = out_mask + M_;

    float *p_h, *p_qkv, *p_y, *p_m, *p_l, *p_imp, *p_cm, *p_xres, *p_fc;
    cudaGetSymbolAddress((void**)&p_h,    g_h);
    cudaGetSymbolAddress((void**)&p_qkv,  g_qkv);
    cudaGetSymbolAddress((void**)&p_y,    g_y);
    cudaGetSymbolAddress((void**)&p_m,    g_m);
    cudaGetSymbolAddress((void**)&p_l,    g_l);
    cudaGetSymbolAddress((void**)&p_imp,  g_impH);
    cudaGetSymbolAddress((void**)&p_cm,   g_cm);
    cudaGetSymbolAddress((void**)&p_xres, g_xres);
    cudaGetSymbolAddress((void**)&p_fc,   g_fc);

    const size_t attn_smem = (size_t)(4 * 64 * 68 + 256) * sizeof(float); // 70656B
    cudaFuncSetAttribute(attn_kernel, cudaFuncAttributeMaxDynamicSharedMemorySize,
                         (int)attn_smem);

    // 1. LN1
    ln_kernel<<<M_, 256>>>(x, ln1_w, ln1_b, p_h);
    // 2a. Q,K columns: 3xTF32 (threshold-sensitive path)
    gemm_tc<0,1><<<dim3(2 * C_ / 128, M_ / 128), 256>>>(
        p_h, c_attn_w, c_attn_b, p_qkv, 3 * C_, C_, nullptr, nullptr);
    // 2b. V columns: single TF32
    gemm_tc<0,0><<<dim3(C_ / 128, M_ / 128), 256>>>(
        p_h, c_attn_w + (size_t)(2 * C_) * C_, c_attn_b + 2 * C_, p_qkv + 2 * C_,
        3 * C_, C_, nullptr, nullptr);
    // 3. Flash attention (tensor-core) -> y, (m, 1/l)
    attn_kernel<<<dim3(NT_, B_ * H_), 256, attn_smem>>>(
        p_qkv, attention_mask, p_y, p_m, p_l);
    // 4. Importance column sums per head (tensor-core, deterministic)
    imp_kernel<<<dim3(NT_, B_ * H_), 256>>>(p_qkv, attention_mask, p_m, p_l, p_imp);
    // 5. Combined mask
    finalize_mask<<<M_ / 256, 256>>>(p_imp, attention_mask, protected_mask,
                                     threshold, p_cm, out_mask, out_loss);
    // 6. proj + residual + prune mask, TF32
    gemm_tc<2,0><<<dim3(C_ / 128, M_ / 128), 256>>>(
        p_y, c_proj_w, c_proj_b, p_xres, C_, C_, x, p_cm);
    // 7. LN2
    ln_kernel<<<M_, 256>>>(p_xres, ln2_w, ln2_b, p_h);
    // 8. fc + GELU, TF32
    gemm_tc<1,0><<<dim3(4 * C_ / 128, M_ / 128), 256>>>(
        p_h, fc_w, fc_b, p_fc, 4 * C_, C_, nullptr, nullptr);
    // 9. fcproj + residual -> d_out, TF32
    gemm_tc<3,0><<<dim3(C_ / 128, M_ / 128), 256>>>(
        p_fc, fcproj_w, fcproj_b, out, C_, 4 * C_, p_xres, nullptr);
}

// round 14
// speedup vs baseline: 2.1582x; 1.1021x over previous
#include <cuda_runtime.h>
#include <cuda_bf16.h>
#include <math.h>
#include <stdint.h>

// Problem constants
#define B_  4
#define T_  2048
#define C_  1024
#define H_  16
#define HS_ 64
#define M_  (B_*T_)      // 8192 rows
#define NT_ (T_/64)      // 32 tiles of 64

// ---------------------------------------------------------------------------
// Scratch (device globals; no runtime allocation allowed)
// ---------------------------------------------------------------------------
__device__ float g_h   [M_*C_];
__device__ float g_qkv [M_*3*C_];
__device__ float g_y   [M_*C_];
__device__ float g_m   [B_*H_*T_];
__device__ float g_l   [B_*H_*T_];         // 1/softmax-denominator
__device__ float g_impH[B_*H_*T_];
__device__ float g_cm  [M_];
__device__ float g_xres[M_*C_];
__device__ float g_fc  [M_*4*C_];

// ---------------------------------------------------------------------------
// LayerNorm
// ---------------------------------------------------------------------------
__global__ __launch_bounds__(256) void ln_kernel(
    const float* __restrict__ x, const float* __restrict__ w,
    const float* __restrict__ bias, float* __restrict__ out)
{
    int row = blockIdx.x;
    int tid = threadIdx.x;
    const float* xr = x + (size_t)row * C_;
    float4 v = *(const float4*)(xr + tid * 4);
    float s1 = v.x + v.y + v.z + v.w;
    float s2 = v.x*v.x + v.y*v.y + v.z*v.z + v.w*v.w;
#pragma unroll
    for (int o = 16; o; o >>= 1) {
        s1 += __shfl_xor_sync(0xffffffffu, s1, o);
        s2 += __shfl_xor_sync(0xffffffffu, s2, o);
    }
    __shared__ float sh1[8], sh2[8];
    int wi = tid >> 5;
    if ((tid & 31) == 0) { sh1[wi] = s1; sh2[wi] = s2; }
    __syncthreads();
    float t1 = 0.f, t2 = 0.f;
#pragma unroll
    for (int i = 0; i < 8; i++) { t1 += sh1[i]; t2 += sh2[i]; }
    float mean = t1 * (1.f / C_);
    float var  = t2 * (1.f / C_) - mean * mean;
    float inv  = rsqrtf(var + 1e-5f);
    float4 wv = *(const float4*)(w + tid * 4);
    float4 bv = *(const float4*)(bias + tid * 4);
    float4 o;
    o.x = (v.x - mean) * inv * wv.x + bv.x;
    o.y = (v.y - mean) * inv * wv.y + bv.y;
    o.z = (v.z - mean) * inv * wv.z + bv.z;
    o.w = (v.w - mean) * inv * wv.w + bv.w;
    *(float4*)(out + (size_t)row * C_ + tid * 4) = o;
}

// ---------------------------------------------------------------------------
// Tensor-core helpers
// ---------------------------------------------------------------------------
__device__ __forceinline__ uint32_t cvt_tf32(float x) {
    uint32_t r; asm("cvt.rna.tf32.f32 %0, %1;" : "=r"(r) : "f"(x)); return r;
}
__device__ __forceinline__ void mma_tf32(float* c,
    uint32_t a0, uint32_t a1, uint32_t a2, uint32_t a3,
    uint32_t b0, uint32_t b1)
{
    asm volatile(
        "mma.sync.aligned.m16n8k8.row.col.f32.tf32.tf32.f32 "
        "{%0,%1,%2,%3}, {%4,%5,%6,%7}, {%8,%9}, {%0,%1,%2,%3};"
        : "+f"(c[0]), "+f"(c[1]), "+f"(c[2]), "+f"(c[3])
        : "r"(a0), "r"(a1), "r"(a2), "r"(a3), "r"(b0), "r"(b1));
}
__device__ __forceinline__ void mma_bf16(float* c,
    uint32_t a0, uint32_t a1, uint32_t a2, uint32_t a3,
    uint32_t b0, uint32_t b1)
{
    asm volatile(
        "mma.sync.aligned.m16n8k16.row.col.f32.bf16.bf16.f32 "
        "{%0,%1,%2,%3}, {%4,%5,%6,%7}, {%8,%9}, {%0,%1,%2,%3};"
        : "+f"(c[0]), "+f"(c[1]), "+f"(c[2]), "+f"(c[3])
        : "r"(a0), "r"(a1), "r"(a2), "r"(a3), "r"(b0), "r"(b1));
}
// Split (x0,x1) into packed bf16x2 hi + lo (lo = residual), lower half = x0.
__device__ __forceinline__ void bf16_split2(float x0, float x1,
                                            uint32_t &hi, uint32_t &lo)
{
    __nv_bfloat162 h = __floats2bfloat162_rn(x0, x1);
    float h0 = __bfloat162float(h.x);
    float h1 = __bfloat162float(h.y);
    __nv_bfloat162 l = __floats2bfloat162_rn(x0 - h0, x1 - h1);
    hi = *(uint32_t*)&h;
    lo = *(uint32_t*)&l;
}

// ---------------------------------------------------------------------------
// Tensor-core GEMM: Out[M,N] = A[M,K] @ W[N,K]^T (+bias, +epilogue)
// EPI 0: bias | 1: +GELU | 2: (res+bias+acc)*rowmask | 3: res+bias+acc
// PREC 0: single TF32 (m16n8k8) | PREC 1: 3-term bf16 split (m16n8k16,
//         ~4e-6 relative error; replaces 3xTF32 at HALF the instructions)
// 128x128 block, BK=32, 256 threads, register prefetch.
// ---------------------------------------------------------------------------
#define GSTRIDE 36

template<int EPI, int PREC>
__global__ __launch_bounds__(256) void gemm_tc(
    const float* __restrict__ A, const float* __restrict__ W,
    const float* __restrict__ bias, float* __restrict__ Out,
    int Ndim, int Kdim,
    const float* __restrict__ res, const float* __restrict__ rowmask)
{
    __shared__ __align__(16) float Sa[128 * GSTRIDE];
    __shared__ __align__(16) float Sw[128 * GSTRIDE];
    const int tid = threadIdx.x;
    const int row0 = blockIdx.y * 128, col0 = blockIdx.x * 128;

    const int wid  = tid >> 5, lane = tid & 31;
    const int g    = lane >> 2, tg = lane & 3;
    const int wr   = (wid >> 2) * 64;
    const int wc   = (wid & 3) * 32;

    float4 pa[4], pw[4];
    auto issue_loads = [&](int k0) {
#pragma unroll
        for (int i = 0; i < 4; i++) {
            int slot = i * 256 + tid;
            int r  = slot >> 3;
            int kg = (slot & 7) << 2;
            pa[i] = *(const float4*)(A + (size_t)(row0 + r) * Kdim + k0 + kg);
            pw[i] = *(const float4*)(W + (size_t)(col0 + r) * Kdim + k0 + kg);
        }
    };
    auto store_stage = [&]() {
#pragma unroll
        for (int i = 0; i < 4; i++) {
            int slot = i * 256 + tid;
            int r  = slot >> 3;
            int kg = (slot & 7) << 2;
            *(float4*)&Sa[r * GSTRIDE + kg] = pa[i];
            *(float4*)&Sw[r * GSTRIDE + kg] = pw[i];
        }
    };

    float acc[4][4][4];
#pragma unroll
    for (int mt = 0; mt < 4; mt++)
#pragma unroll
        for (int nt = 0; nt < 4; nt++)
#pragma unroll
            for (int i = 0; i < 4; i++) acc[mt][nt][i] = 0.f;

    issue_loads(0);
    store_stage();
    __syncthreads();

    const int KT = Kdim >> 5;
    for (int kt = 0; kt < KT; kt++) {
        const bool has_next = (kt + 1) < KT;
        if (has_next) issue_loads((kt + 1) << 5);

        if (PREC == 1) {
            // 3-term bf16 split, two k16 steps per tile
#pragma unroll
            for (int s2 = 0; s2 < 2; s2++) {
                const int kk = s2 * 16;
                uint32_t ah[4][4], al[4][4], bh4[4][2], bl4[4][2];
#pragma unroll
                for (int mt = 0; mt < 4; mt++) {
                    const float* p0 = Sa + (wr + mt * 16 + g) * GSTRIDE + kk + 2 * tg;
                    float2 xa0 = *(const float2*)p0;
                    float2 xa1 = *(const float2*)(p0 + 8 * GSTRIDE);
                    float2 xa2 = *(const float2*)(p0 + 8);
                    float2 xa3 = *(const float2*)(p0 + 8 * GSTRIDE + 8);
                    bf16_split2(xa0.x, xa0.y, ah[mt][0], al[mt][0]);
                    bf16_split2(xa1.x, xa1.y, ah[mt][1], al[mt][1]);
                    bf16_split2(xa2.x, xa2.y, ah[mt][2], al[mt][2]);
                    bf16_split2(xa3.x, xa3.y, ah[mt][3], al[mt][3]);
                }
#pragma unroll
                for (int nt = 0; nt < 4; nt++) {
                    const float* p = Sw + (wc + nt * 8 + g) * GSTRIDE + kk + 2 * tg;
                    float2 xb0 = *(const float2*)p;
                    float2 xb1 = *(const float2*)(p + 8);
                    bf16_split2(xb0.x, xb0.y, bh4[nt][0], bl4[nt][0]);
                    bf16_split2(xb1.x, xb1.y, bh4[nt][1], bl4[nt][1]);
                }
#pragma unroll
                for (int mt = 0; mt < 4; mt++)
#pragma unroll
                    for (int nt = 0; nt < 4; nt++) {
                        mma_bf16(acc[mt][nt], ah[mt][0], ah[mt][1], ah[mt][2], ah[mt][3],
                                 bl4[nt][0], bl4[nt][1]);
                        mma_bf16(acc[mt][nt], al[mt][0], al[mt][1], al[mt][2], al[mt][3],
                                 bh4[nt][0], bh4[nt][1]);
                        mma_bf16(acc[mt][nt], ah[mt][0], ah[mt][1], ah[mt][2], ah[mt][3],
                                 bh4[nt][0], bh4[nt][1]);
                    }
            }
        } else {
            // single TF32, four k8 steps per tile
#pragma unroll
            for (int ks = 0; ks < 4; ks++) {
                const int kk = ks * 8;
                uint32_t ah[4][4], bh[4][2];
#pragma unroll
                for (int mt = 0; mt < 4; mt++) {
                    const float* p = Sa + (wr + mt * 16 + g) * GSTRIDE + kk + tg;
                    ah[mt][0] = cvt_tf32(p[0]);
                    ah[mt][1] = cvt_tf32(p[8 * GSTRIDE]);
                    ah[mt][2] = cvt_tf32(p[4]);
                    ah[mt][3] = cvt_tf32(p[8 * GSTRIDE + 4]);
                }
#pragma unroll
                for (int nt = 0; nt < 4; nt++) {
                    const float* p = Sw + (wc + nt * 8 + g) * GSTRIDE + kk + tg;
                    bh[nt][0] = cvt_tf32(p[0]);
                    bh[nt][1] = cvt_tf32(p[4]);
                }
#pragma unroll
                for (int mt = 0; mt < 4; mt++)
#pragma unroll
                    for (int nt = 0; nt < 4; nt++)
                        mma_tf32(acc[mt][nt], ah[mt][0], ah[mt][1], ah[mt][2], ah[mt][3],
                                 bh[nt][0], bh[nt][1]);
            }
        }

        if (has_next) {
            __syncthreads();
            store_stage();
            __syncthreads();
        }
    }

#pragma unroll
    for (int mt = 0; mt < 4; mt++) {
#pragma unroll
        for (int half = 0; half < 2; half++) {
            int r = row0 + wr + mt * 16 + g + half * 8;
            float rmv = (EPI == 2) ? rowmask[r] : 0.f;
#pragma unroll
            for (int nt = 0; nt < 4; nt++) {
                int c = col0 + wc + nt * 8 + tg * 2;
                float o0 = acc[mt][nt][half * 2 + 0] + bias[c];
                float o1 = acc[mt][nt][half * 2 + 1] + bias[c + 1];
                if (EPI == 1) {
                    o0 = 0.5f * o0 * (1.f + erff(o0 * 0.7071067811865476f));
                    o1 = 0.5f * o1 * (1.f + erff(o1 * 0.7071067811865476f));
                } else if (EPI == 2) {
                    const float* rp = res + (size_t)r * Ndim + c;
                    o0 = (rp[0] + o0) * rmv;
                    o1 = (rp[1] + o1) * rmv;
                } else if (EPI == 3) {
                    const float* rp = res + (size_t)r * Ndim + c;
                    o0 += rp[0];
                    o1 += rp[1];
                }
                *(float2*)(Out + (size_t)r * Ndim + c) = make_float2(o0, o1);
            }
        }
    }
}

// ---------------------------------------------------------------------------
// Tile loaders (64 rows x 64 dims), pad-68 smem
// ---------------------------------------------------------------------------
__device__ __forceinline__ void load_tile_T(const float* __restrict__ g, int rowStride,
                                            float* __restrict__ sdst, int tid)
{
#pragma unroll
    for (int i = 0; i < 4; i++) {
        int e  = i * 256 + tid;
        int r  = e >> 4;
        int dg = (e & 15) << 2;
        float4 v = *(const float4*)(g + (size_t)r * rowStride + dg);
        sdst[(dg+0)*68 + r] = v.x;
        sdst[(dg+1)*68 + r] = v.y;
        sdst[(dg+2)*68 + r] = v.z;
        sdst[(dg+3)*68 + r] = v.w;
    }
}

__device__ __forceinline__ void load_tile_R(const float* __restrict__ g, int rowStride,
                                            float* __restrict__ sdst, int tid)
{
#pragma unroll
    for (int i = 0; i < 4; i++) {
        int e  = i * 256 + tid;
        int r  = e >> 4;
        int dg = (e & 15) << 2;
        *(float4*)&sdst[r * 68 + dg] = *(const float4*)(g + (size_t)r * rowStride + dg);
    }
}

// ---------------------------------------------------------------------------
// Flash attention — tensor-core.
// QK^T: 3-term bf16 (~4e-6, flip-safe), P*V: single TF32.
// ---------------------------------------------------------------------------
__global__ __launch_bounds__(256) void attn_kernel(
    const float* __restrict__ qkv, const float* __restrict__ attmask,
    float* __restrict__ y, float* __restrict__ gm, float* __restrict__ gl)
{
    extern __shared__ __align__(16) float sm[];
    float* Qs    = sm;
    float* Ks    = sm + 64 * 68;
    float* Vt    = sm + 2 * 64 * 68;
    float* Ss    = sm + 3 * 64 * 68;
    float* Alpha = sm + 4 * 64 * 68;
    float* Mrow  = Alpha + 64;
    float* Lrow  = Mrow + 64;
    float* Am    = Lrow + 64;

    const int bh = blockIdx.y, b = bh >> 4, h = bh & 15;
    const int qt = blockIdx.x;
    const int tid = threadIdx.x;
    const int wid = tid >> 5, lane = tid & 31;
    const int g = lane >> 2, tg = lane & 3;
    const int qr0 = (wid & 3) * 16;
    const int wh  = wid >> 2;
    const int srow = tid >> 2;
    const int scg  = tid & 3;
    const float scale = 0.125f;
    const int bhT = bh * T_;

    const float* qbase = qkv + ((size_t)(b * T_ + qt * 64)) * (3 * C_) + h * 64;
    load_tile_R(qbase, 3 * C_, Qs, tid);

    float m_ = -INFINITY, l_ = 0.f;
    float cpv[4][4];
#pragma unroll
    for (int nt = 0; nt < 4; nt++)
#pragma unroll
        for (int i = 0; i < 4; i++) cpv[nt][i] = 0.f;

    for (int kt = 0; kt <= qt; kt++) {
        __syncthreads();
        const float* kb = qkv + ((size_t)(b * T_ + kt * 64)) * (3 * C_) + C_ + h * 64;
        load_tile_R(kb, 3 * C_, Ks, tid);
        load_tile_T(kb + C_, 3 * C_, Vt, tid);
        if (tid < 64) Am[tid] = attmask[b * T_ + kt * 64 + tid];
        __syncthreads();

        // ---- QK^T (3-term bf16, k16 steps) ----
        {
            float c[4][4];
#pragma unroll
            for (int nt = 0; nt < 4; nt++)
#pragma unroll
                for (int i = 0; i < 4; i++) c[nt][i] = 0.f;
#pragma unroll
            for (int s2 = 0; s2 < 4; s2++) {
                const int kk = s2 * 16;
                const float* ap = Qs + (qr0 + g) * 68 + kk + 2 * tg;
                float2 xa0 = *(const float2*)ap;
                float2 xa1 = *(const float2*)(ap + 8 * 68);
                float2 xa2 = *(const float2*)(ap + 8);
                float2 xa3 = *(const float2*)(ap + 8 * 68 + 8);
                uint32_t ah0, ah1, ah2, ah3, al0, al1, al2, al3;
                bf16_split2(xa0.x, xa0.y, ah0, al0);
                bf16_split2(xa1.x, xa1.y, ah1, al1);
                bf16_split2(xa2.x, xa2.y, ah2, al2);
                bf16_split2(xa3.x, xa3.y, ah3, al3);
#pragma unroll
                for (int nt = 0; nt < 4; nt++) {
                    const float* bp = Ks + (wh * 32 + nt * 8 + g) * 68 + kk + 2 * tg;
                    float2 xb0 = *(const float2*)bp;
                    float2 xb1 = *(const float2*)(bp + 8);
                    uint32_t bh0, bh1, bl0, bl1;
                    bf16_split2(xb0.x, xb0.y, bh0, bl0);
                    bf16_split2(xb1.x, xb1.y, bh1, bl1);
                    mma_bf16(c[nt], ah0, ah1, ah2, ah3, bl0, bl1);
                    mma_bf16(c[nt], al0, al1, al2, al3, bh0, bh1);
                    mma_bf16(c[nt], ah0, ah1, ah2, ah3, bh0, bh1);
                }
            }
            const int qg0 = qt * 64 + qr0 + g;
            const int qg8 = qg0 + 8;
#pragma unroll
            for (int nt = 0; nt < 4; nt++) {
                int kcol = wh * 32 + nt * 8 + 2 * tg;
                int kg0 = kt * 64 + kcol, kg1 = kg0 + 1;
                float a0 = Am[kcol], a1 = Am[kcol + 1];
                float s00 = (kg0 > qg0 || a0 == 0.f) ? -INFINITY : c[nt][0] * scale;
                float s01 = (kg1 > qg0 || a1 == 0.f) ? -INFINITY : c[nt][1] * scale;
                float s80 = (kg0 > qg8 || a0 == 0.f) ? -INFINITY : c[nt][2] * scale;
                float s81 = (kg1 > qg8 || a1 == 0.f) ? -INFINITY : c[nt][3] * scale;
                *(float2*)&Ss[(qr0 + g) * 68 + kcol]     = make_float2(s00, s01);
                *(float2*)&Ss[(qr0 + g + 8) * 68 + kcol] = make_float2(s80, s81);
            }
        }
        __syncthreads();

        // ---- softmax (online, per row) ----
        {
            float sv[16];
            float lmax = -INFINITY;
            const int base = srow * 68 + scg * 16;
#pragma unroll
            for (int i = 0; i < 4; i++) {
                float4 v = *(const float4*)&Ss[base + i * 4];
                sv[i*4+0] = v.x; sv[i*4+1] = v.y; sv[i*4+2] = v.z; sv[i*4+3] = v.w;
                lmax = fmaxf(lmax, fmaxf(fmaxf(v.x, v.y), fmaxf(v.z, v.w)));
            }
            lmax = fmaxf(lmax, __shfl_xor_sync(0xffffffffu, lmax, 1));
            lmax = fmaxf(lmax, __shfl_xor_sync(0xffffffffu, lmax, 2));
            float mn = fmaxf(m_, lmax);
            float alpha = (mn > m_) ? __expf(m_ - mn) : 1.f;
            float lsum = 0.f;
#pragma unroll
            for (int i = 0; i < 16; i++) {
                float p = (sv[i] == -INFINITY) ? 0.f : __expf(sv[i] - mn);
                sv[i] = p;
                lsum += p;
            }
#pragma unroll
            for (int i = 0; i < 4; i++)
                *(float4*)&Ss[base + i * 4] = make_float4(sv[i*4+0], sv[i*4+1],
                                                          sv[i*4+2], sv[i*4+3]);
            lsum += __shfl_xor_sync(0xffffffffu, lsum, 1);
            lsum += __shfl_xor_sync(0xffffffffu, lsum, 2);
            l_ = l_ * alpha + lsum;
            m_ = mn;
            if (scg == 0) Alpha[srow] = alpha;
        }
        __syncthreads();

        // ---- P*V (single TF32) ----
        {
            float a0 = Alpha[qr0 + g];
            float a8 = Alpha[qr0 + g + 8];
#pragma unroll
            for (int nt = 0; nt < 4; nt++) {
                cpv[nt][0] *= a0; cpv[nt][1] *= a0;
                cpv[nt][2] *= a8; cpv[nt][3] *= a8;
            }
#pragma unroll
            for (int s = 0; s < 8; s++) {
                const float* ap = Ss + (qr0 + g) * 68 + s * 8 + tg;
                uint32_t pa0 = cvt_tf32(ap[0]);
                uint32_t pa1 = cvt_tf32(ap[8 * 68]);
                uint32_t pa2 = cvt_tf32(ap[4]);
                uint32_t pa3 = cvt_tf32(ap[8 * 68 + 4]);
#pragma unroll
                for (int nt = 0; nt < 4; nt++) {
                    const float* bp = Vt + (wh * 32 + nt * 8 + g) * 68 + s * 8 + tg;
                    mma_tf32(cpv[nt], pa0, pa1, pa2, pa3,
                             cvt_tf32(bp[0]), cvt_tf32(bp[4]));
                }
            }
        }
    }

    if (scg == 0) { Mrow[srow] = m_; Lrow[srow] = l_; }
    __syncthreads();

    {
        float inv0 = 1.f / Lrow[qr0 + g];
        float inv8 = 1.f / Lrow[qr0 + g + 8];
        float* y0 = y + ((size_t)(b * T_ + qt * 64 + qr0 + g)) * C_ + h * 64;
        float* y8 = y + ((size_t)(b * T_ + qt * 64 + qr0 + g + 8)) * C_ + h * 64;
#pragma unroll
        for (int nt = 0; nt < 4; nt++) {
            int col = wh * 32 + nt * 8 + 2 * tg;
            *(float2*)(y0 + col) = make_float2(cpv[nt][0] * inv0, cpv[nt][1] * inv0);
            *(float2*)(y8 + col) = make_float2(cpv[nt][2] * inv8, cpv[nt][3] * inv8);
        }
    }
    if (tid < 64) {
        gm[bhT + qt * 64 + tid] = Mrow[tid];
        gl[bhT + qt * 64 + tid] = 1.f / Lrow[tid];
    }
}

// ---------------------------------------------------------------------------
// Importance pass — 3-term bf16 scores, deterministic column sums.
// ---------------------------------------------------------------------------
__global__ __launch_bounds__(256) void imp_kernel(
    const float* __restrict__ qkv, const float* __restrict__ attmask,
    const float* __restrict__ gm, const float* __restrict__ gl,
    float* __restrict__ impH)
{
    __shared__ __align__(16) float Ks[64 * 68];
    __shared__ __align__(16) float Qs[64 * 68];
    __shared__ float part[2][64];

    const int bh = blockIdx.y, b = bh >> 4, h = bh & 15;
    const int kt = blockIdx.x;
    const int tid = threadIdx.x;
    const int wid = tid >> 5, lane = tid & 31;
    const int g = lane >> 2, tg = lane & 3;
    const int kr0 = (wid & 3) * 16;
    const int qh  = wid >> 2;
    const int qc0 = qh * 32;
    const float scale = 0.125f;
    const int bhT = bh * T_;

    const float* kb = qkv + ((size_t)(b * T_ + kt * 64)) * (3 * C_) + C_ + h * 64;
    load_tile_R(kb, 3 * C_, Ks, tid);

    const int kg0 = kt * 64 + kr0 + g;
    const int kg1 = kg0 + 8;
    const float amk0 = attmask[b * T_ + kt * 64 + kr0 + g];
    const float amk1 = attmask[b * T_ + kt * 64 + kr0 + g + 8];

    float imp0 = 0.f, imp1 = 0.f;

    for (int qt = kt; qt < NT_; qt++) {
        __syncthreads();
        load_tile_R(qkv + ((size_t)(b * T_ + qt * 64)) * (3 * C_) + h * 64, 3 * C_, Qs, tid);
        __syncthreads();

        float c[4][4];
#pragma unroll
        for (int nt = 0; nt < 4; nt++)
#pragma unroll
            for (int i = 0; i < 4; i++) c[nt][i] = 0.f;

#pragma unroll
        for (int s2 = 0; s2 < 4; s2++) {
            const int kk = s2 * 16;
            const float* ap = Ks + (kr0 + g) * 68 + kk + 2 * tg;
            float2 xa0 = *(const float2*)ap;
            float2 xa1 = *(const float2*)(ap + 8 * 68);
            float2 xa2 = *(const float2*)(ap + 8);
            float2 xa3 = *(const float2*)(ap + 8 * 68 + 8);
            uint32_t kh0, kh1, kh2, kh3, kl0, kl1, kl2, kl3;
            bf16_split2(xa0.x, xa0.y, kh0, kl0);
            bf16_split2(xa1.x, xa1.y, kh1, kl1);
            bf16_split2(xa2.x, xa2.y, kh2, kl2);
            bf16_split2(xa3.x, xa3.y, kh3, kl3);
#pragma unroll
            for (int nt = 0; nt < 4; nt++) {
                const float* bp = Qs + (qc0 + nt * 8 + g) * 68 + kk + 2 * tg;
                float2 xb0 = *(const float2*)bp;
                float2 xb1 = *(const float2*)(bp + 8);
                uint32_t bh0, bh1, bl0, bl1;
                bf16_split2(xb0.x, xb0.y, bh0, bl0);
                bf16_split2(xb1.x, xb1.y, bh1, bl1);
                mma_bf16(c[nt], kh0, kh1, kh2, kh3, bl0, bl1);
                mma_bf16(c[nt], kl0, kl1, kl2, kl3, bh0, bh1);
                mma_bf16(c[nt], kh0, kh1, kh2, kh3, bh0, bh1);
            }
        }

#pragma unroll
        for (int nt = 0; nt < 4; nt++) {
            const int qg0 = qt * 64 + qc0 + nt * 8 + 2 * tg;
            const int qg1 = qg0 + 1;
            const float mq0 = gm[bhT + qg0], mq1 = gm[bhT + qg1];
            const float rq0 = gl[bhT + qg0], rq1 = gl[bhT + qg1];
            if (qg0 >= kg0) imp0 += amk0 * __expf(fmaf(c[nt][0], scale, -mq0)) * rq0;
            if (qg1 >= kg0) imp0 += amk0 * __expf(fmaf(c[nt][1], scale, -mq1)) * rq1;
            if (qg0 >= kg1) imp1 += amk1 * __expf(fmaf(c[nt][2], scale, -mq0)) * rq0;
            if (qg1 >= kg1) imp1 += amk1 * __expf(fmaf(c[nt][3], scale, -mq1)) * rq1;
        }
    }

    imp0 += __shfl_xor_sync(0xffffffffu, imp0, 1);
    imp0 += __shfl_xor_sync(0xffffffffu, imp0, 2);
    imp1 += __shfl_xor_sync(0xffffffffu, imp1, 1);
    imp1 += __shfl_xor_sync(0xffffffffu, imp1, 2);
    if (tg == 0) {
        part[qh][kr0 + g] = imp0;
        part[qh][kr0 + 8 + g] = imp1;
    }
    __syncthreads();
    if (tid < 64)
        impH[bhT + kt * 64 + tid] = part[0][tid] + part[1][tid];
}

// ---------------------------------------------------------------------------
// Finalize pruning mask
// ---------------------------------------------------------------------------
__global__ __launch_bounds__(256) void finalize_mask(
    const float* __restrict__ impH, const float* __restrict__ attmask,
    const float* __restrict__ prot, const float* __restrict__ thresh,
    float* __restrict__ cm, float* __restrict__ out_mask,
    float* __restrict__ out_loss)
{
    int i = blockIdx.x * 256 + threadIdx.x;
    int b = i / T_, t = i % T_;
    float s = 0.f;
#pragma unroll
    for (int h = 0; h < H_; h++) s += impH[(b * H_ + h) * T_ + t];
    float imp = s * (1.f / ((float)H_ * (float)T_));
    float pm = (imp >= thresh[0]) ? 1.f : 0.f;
    if (prot[i] > 0.f) pm = 1.f;
    float c = attmask[i] * pm;
    cm[i] = c;
    out_mask[i] = c;
    if (i == 0) out_loss[0] = 0.f;
}

// ---------------------------------------------------------------------------
// Launch
// ---------------------------------------------------------------------------
extern "C" void kernel_launch(void* const* d_in, const int* in_sizes, int n_in,
                              void* d_out, int out_size)
{
    const float* x              = (const float*)d_in[0];
    const float* attention_mask = (const float*)d_in[1];
    const float* protected_mask = (const float*)d_in[2];
    const float* ln1_w          = (const float*)d_in[3];
    const float* ln1_b          = (const float*)d_in[4];
    const float* c_attn_w       = (const float*)d_in[5];
    const float* c_attn_b       = (const float*)d_in[6];
    const float* c_proj_w       = (const float*)d_in[7];
    const float* c_proj_b       = (const float*)d_in[8];
    const float* ln2_w          = (const float*)d_in[9];
    const float* ln2_b          = (const float*)d_in[10];
    const float* fc_w           = (const float*)d_in[11];
    const float* fc_b           = (const float*)d_in[12];
    const float* fcproj_w       = (const float*)d_in[13];
    const float* fcproj_b       = (const float*)d_in[14];
    const float* threshold      = (const float*)d_in[15];

    float* out      = (float*)d_out;
    float* out_mask = out + (size_t)M_ * C_;
    float* out_loss = out_mask + M_;

    float *p_h, *p_qkv, *p_y, *p_m, *p_l, *p_imp, *p_cm, *p_xres, *p_fc;
    cudaGetSymbolAddress((void**)&p_h,    g_h);
    cudaGetSymbolAddress((void**)&p_qkv,  g_qkv);
    cudaGetSymbolAddress((void**)&p_y,    g_y);
    cudaGetSymbolAddress((void**)&p_m,    g_m);
    cudaGetSymbolAddress((void**)&p_l,    g_l);
    cudaGetSymbolAddress((void**)&p_imp,  g_impH);
    cudaGetSymbolAddress((void**)&p_cm,   g_cm);
    cudaGetSymbolAddress((void**)&p_xres, g_xres);
    cudaGetSymbolAddress((void**)&p_fc,   g_fc);

    const size_t attn_smem = (size_t)(4 * 64 * 68 + 256) * sizeof(float); // 70656B
    cudaFuncSetAttribute(attn_kernel, cudaFuncAttributeMaxDynamicSharedMemorySize,
                         (int)attn_smem);

    // 1. LN1
    ln_kernel<<<M_, 256>>>(x, ln1_w, ln1_b, p_h);
    // 2a. Q,K columns: 3-term bf16 (threshold-sensitive path, ~4e-6)
    gemm_tc<0,1><<<dim3(2 * C_ / 128, M_ / 128), 256>>>(
        p_h, c_attn_w, c_attn_b, p_qkv, 3 * C_, C_, nullptr, nullptr);
    // 2b. V columns: single TF32
    gemm_tc<0,0><<<dim3(C_ / 128, M_ / 128), 256>>>(
        p_h, c_attn_w + (size_t)(2 * C_) * C_, c_attn_b + 2 * C_, p_qkv + 2 * C_,
        3 * C_, C_, nullptr, nullptr);
    // 3. Flash attention (tensor-core) -> y, (m, 1/l)
    attn_kernel<<<dim3(NT_, B_ * H_), 256, attn_smem>>>(
        p_qkv, attention_mask, p_y, p_m, p_l);
    // 4. Importance column sums per head (tensor-core, deterministic)
    imp_kernel<<<dim3(NT_, B_ * H_), 256>>>(p_qkv, attention_mask, p_m, p_l, p_imp);
    // 5. Combined mask
    finalize_mask<<<M_ / 256, 256>>>(p_imp, attention_mask, protected_mask,
                                     threshold, p_cm, out_mask, out_loss);
    // 6. proj + residual + prune mask, TF32
    gemm_tc<2,0><<<dim3(C_ / 128, M_ / 128), 256>>>(
        p_y, c_proj_w, c_proj_b, p_xres, C_, C_, x, p_cm);
    // 7. LN2
    ln_kernel<<<M_, 256>>>(p_xres, ln2_w, ln2_b, p_h);
    // 8. fc + GELU, TF32
    gemm_tc<1,0><<<dim3(4 * C_ / 128, M_ / 128), 256>>>(
        p_h, fc_w, fc_b, p_fc, 4 * C_, C_, nullptr, nullptr);
    // 9. fcproj + residual -> d_out, TF32
    gemm_tc<3,0><<<dim3(C_ / 128, M_ / 128), 256>>>(
        p_fc, fcproj_w, fcproj_b, out, C_, 4 * C_, p_xres, nullptr);
}

// round 15
// speedup vs baseline: 2.3108x; 1.0707x over previous
#include <cuda_runtime.h>
#include <cuda_bf16.h>
#include <math.h>
#include <stdint.h>

// Problem constants
#define B_  4
#define T_  2048
#define C_  1024
#define H_  16
#define HS_ 64
#define M_  (B_*T_)      // 8192 rows
#define NT_ (T_/64)      // 32 tiles of 64

// ---------------------------------------------------------------------------
// Scratch (device globals; no runtime allocation allowed)
// ---------------------------------------------------------------------------
__device__ float    g_h   [M_*C_];         // LN output
__device__ uint32_t g_qkH [M_*C_];         // Q,K packed bf16x2 HI (Q:512, K:512 u32/row)
__device__ uint32_t g_qkL [M_*C_];         // Q,K packed bf16x2 LO
__device__ float    g_v   [M_*C_];         // V (float)
__device__ float    g_y   [M_*C_];         // attention output
__device__ float    g_m   [B_*H_*T_];      // per-row softmax max
__device__ float    g_l   [B_*H_*T_];      // per-row 1/denominator
__device__ float    g_impH[B_*H_*T_];      // per-head importance sums
__device__ float    g_cm  [M_];            // combined mask
__device__ float    g_xres[M_*C_];         // attn residual + prune mask
__device__ float    g_fc  [M_*4*C_];       // MLP hidden

// ---------------------------------------------------------------------------
// LayerNorm
// ---------------------------------------------------------------------------
__global__ __launch_bounds__(256) void ln_kernel(
    const float* __restrict__ x, const float* __restrict__ w,
    const float* __restrict__ bias, float* __restrict__ out)
{
    int row = blockIdx.x;
    int tid = threadIdx.x;
    const float* xr = x + (size_t)row * C_;
    float4 v = *(const float4*)(xr + tid * 4);
    float s1 = v.x + v.y + v.z + v.w;
    float s2 = v.x*v.x + v.y*v.y + v.z*v.z + v.w*v.w;
#pragma unroll
    for (int o = 16; o; o >>= 1) {
        s1 += __shfl_xor_sync(0xffffffffu, s1, o);
        s2 += __shfl_xor_sync(0xffffffffu, s2, o);
    }
    __shared__ float sh1[8], sh2[8];
    int wi = tid >> 5;
    if ((tid & 31) == 0) { sh1[wi] = s1; sh2[wi] = s2; }
    __syncthreads();
    float t1 = 0.f, t2 = 0.f;
#pragma unroll
    for (int i = 0; i < 8; i++) { t1 += sh1[i]; t2 += sh2[i]; }
    float mean = t1 * (1.f / C_);
    float var  = t2 * (1.f / C_) - mean * mean;
    float inv  = rsqrtf(var + 1e-5f);
    float4 wv = *(const float4*)(w + tid * 4);
    float4 bv = *(const float4*)(bias + tid * 4);
    float4 o;
    o.x = (v.x - mean) * inv * wv.x + bv.x;
    o.y = (v.y - mean) * inv * wv.y + bv.y;
    o.z = (v.z - mean) * inv * wv.z + bv.z;
    o.w = (v.w - mean) * inv * wv.w + bv.w;
    *(float4*)(out + (size_t)row * C_ + tid * 4) = o;
}

// ---------------------------------------------------------------------------
// Tensor-core helpers
// ---------------------------------------------------------------------------
__device__ __forceinline__ uint32_t cvt_tf32(float x) {
    uint32_t r; asm("cvt.rna.tf32.f32 %0, %1;" : "=r"(r) : "f"(x)); return r;
}
__device__ __forceinline__ void mma_tf32(float* c,
    uint32_t a0, uint32_t a1, uint32_t a2, uint32_t a3,
    uint32_t b0, uint32_t b1)
{
    asm volatile(
        "mma.sync.aligned.m16n8k8.row.col.f32.tf32.tf32.f32 "
        "{%0,%1,%2,%3}, {%4,%5,%6,%7}, {%8,%9}, {%0,%1,%2,%3};"
        : "+f"(c[0]), "+f"(c[1]), "+f"(c[2]), "+f"(c[3])
        : "r"(a0), "r"(a1), "r"(a2), "r"(a3), "r"(b0), "r"(b1));
}
__device__ __forceinline__ void mma_bf16(float* c,
    uint32_t a0, uint32_t a1, uint32_t a2, uint32_t a3,
    uint32_t b0, uint32_t b1)
{
    asm volatile(
        "mma.sync.aligned.m16n8k16.row.col.f32.bf16.bf16.f32 "
        "{%0,%1,%2,%3}, {%4,%5,%6,%7}, {%8,%9}, {%0,%1,%2,%3};"
        : "+f"(c[0]), "+f"(c[1]), "+f"(c[2]), "+f"(c[3])
        : "r"(a0), "r"(a1), "r"(a2), "r"(a3), "r"(b0), "r"(b1));
}
__device__ __forceinline__ void bf16_split2(float x0, float x1,
                                            uint32_t &hi, uint32_t &lo)
{
    __nv_bfloat162 h = __floats2bfloat162_rn(x0, x1);
    float h0 = __bfloat162float(h.x);
    float h1 = __bfloat162float(h.y);
    __nv_bfloat162 l = __floats2bfloat162_rn(x0 - h0, x1 - h1);
    hi = *(uint32_t*)&h;
    lo = *(uint32_t*)&l;
}

// ---------------------------------------------------------------------------
// Tensor-core GEMM: Out[M,N] = A[M,K] @ W[N,K]^T (+bias, +epilogue)
// EPI 0: bias | 1: +GELU | 2: (res+bias+acc)*rowmask | 3: res+bias+acc
// EPI 4: bias, then bf16 hi/lo split packed into OutH/OutL (u32 per 2 cols,
//        packed row stride = Ndim/2). Out unused for EPI 4.
// PREC 0: single TF32 (m16n8k8) | PREC 1: 3-term bf16 split (m16n8k16)
// 128x128 block, BK=32, 256 threads, register prefetch.
// ---------------------------------------------------------------------------
#define GSTRIDE 36

template<int EPI, int PREC>
__global__ __launch_bounds__(256) void gemm_tc(
    const float* __restrict__ A, const float* __restrict__ W,
    const float* __restrict__ bias, float* __restrict__ Out,
    int Ndim, int Kdim,
    const float* __restrict__ res, const float* __restrict__ rowmask,
    uint32_t* __restrict__ OutH, uint32_t* __restrict__ OutL)
{
    __shared__ __align__(16) float Sa[128 * GSTRIDE];
    __shared__ __align__(16) float Sw[128 * GSTRIDE];
    const int tid = threadIdx.x;
    const int row0 = blockIdx.y * 128, col0 = blockIdx.x * 128;

    const int wid  = tid >> 5, lane = tid & 31;
    const int g    = lane >> 2, tg = lane & 3;
    const int wr   = (wid >> 2) * 64;
    const int wc   = (wid & 3) * 32;

    float4 pa[4], pw[4];
    auto issue_loads = [&](int k0) {
#pragma unroll
        for (int i = 0; i < 4; i++) {
            int slot = i * 256 + tid;
            int r  = slot >> 3;
            int kg = (slot & 7) << 2;
            pa[i] = *(const float4*)(A + (size_t)(row0 + r) * Kdim + k0 + kg);
            pw[i] = *(const float4*)(W + (size_t)(col0 + r) * Kdim + k0 + kg);
        }
    };
    auto store_stage = [&]() {
#pragma unroll
        for (int i = 0; i < 4; i++) {
            int slot = i * 256 + tid;
            int r  = slot >> 3;
            int kg = (slot & 7) << 2;
            *(float4*)&Sa[r * GSTRIDE + kg] = pa[i];
            *(float4*)&Sw[r * GSTRIDE + kg] = pw[i];
        }
    };

    float acc[4][4][4];
#pragma unroll
    for (int mt = 0; mt < 4; mt++)
#pragma unroll
        for (int nt = 0; nt < 4; nt++)
#pragma unroll
            for (int i = 0; i < 4; i++) acc[mt][nt][i] = 0.f;

    issue_loads(0);
    store_stage();
    __syncthreads();

    const int KT = Kdim >> 5;
    for (int kt = 0; kt < KT; kt++) {
        const bool has_next = (kt + 1) < KT;
        if (has_next) issue_loads((kt + 1) << 5);

        if (PREC == 1) {
#pragma unroll
            for (int s2 = 0; s2 < 2; s2++) {
                const int kk = s2 * 16;
                uint32_t ah[4][4], al[4][4], bh4[4][2], bl4[4][2];
#pragma unroll
                for (int mt = 0; mt < 4; mt++) {
                    const float* p0 = Sa + (wr + mt * 16 + g) * GSTRIDE + kk + 2 * tg;
                    float2 xa0 = *(const float2*)p0;
                    float2 xa1 = *(const float2*)(p0 + 8 * GSTRIDE);
                    float2 xa2 = *(const float2*)(p0 + 8);
                    float2 xa3 = *(const float2*)(p0 + 8 * GSTRIDE + 8);
                    bf16_split2(xa0.x, xa0.y, ah[mt][0], al[mt][0]);
                    bf16_split2(xa1.x, xa1.y, ah[mt][1], al[mt][1]);
                    bf16_split2(xa2.x, xa2.y, ah[mt][2], al[mt][2]);
                    bf16_split2(xa3.x, xa3.y, ah[mt][3], al[mt][3]);
                }
#pragma unroll
                for (int nt = 0; nt < 4; nt++) {
                    const float* p = Sw + (wc + nt * 8 + g) * GSTRIDE + kk + 2 * tg;
                    float2 xb0 = *(const float2*)p;
                    float2 xb1 = *(const float2*)(p + 8);
                    bf16_split2(xb0.x, xb0.y, bh4[nt][0], bl4[nt][0]);
                    bf16_split2(xb1.x, xb1.y, bh4[nt][1], bl4[nt][1]);
                }
#pragma unroll
                for (int mt = 0; mt < 4; mt++)
#pragma unroll
                    for (int nt = 0; nt < 4; nt++) {
                        mma_bf16(acc[mt][nt], ah[mt][0], ah[mt][1], ah[mt][2], ah[mt][3],
                                 bl4[nt][0], bl4[nt][1]);
                        mma_bf16(acc[mt][nt], al[mt][0], al[mt][1], al[mt][2], al[mt][3],
                                 bh4[nt][0], bh4[nt][1]);
                        mma_bf16(acc[mt][nt], ah[mt][0], ah[mt][1], ah[mt][2], ah[mt][3],
                                 bh4[nt][0], bh4[nt][1]);
                    }
            }
        } else {
#pragma unroll
            for (int ks = 0; ks < 4; ks++) {
                const int kk = ks * 8;
                uint32_t ah[4][4], bh[4][2];
#pragma unroll
                for (int mt = 0; mt < 4; mt++) {
                    const float* p = Sa + (wr + mt * 16 + g) * GSTRIDE + kk + tg;
                    ah[mt][0] = cvt_tf32(p[0]);
                    ah[mt][1] = cvt_tf32(p[8 * GSTRIDE]);
                    ah[mt][2] = cvt_tf32(p[4]);
                    ah[mt][3] = cvt_tf32(p[8 * GSTRIDE + 4]);
                }
#pragma unroll
                for (int nt = 0; nt < 4; nt++) {
                    const float* p = Sw + (wc + nt * 8 + g) * GSTRIDE + kk + tg;
                    bh[nt][0] = cvt_tf32(p[0]);
                    bh[nt][1] = cvt_tf32(p[4]);
                }
#pragma unroll
                for (int mt = 0; mt < 4; mt++)
#pragma unroll
                    for (int nt = 0; nt < 4; nt++)
                        mma_tf32(acc[mt][nt], ah[mt][0], ah[mt][1], ah[mt][2], ah[mt][3],
                                 bh[nt][0], bh[nt][1]);
            }
        }

        if (has_next) {
            __syncthreads();
            store_stage();
            __syncthreads();
        }
    }

#pragma unroll
    for (int mt = 0; mt < 4; mt++) {
#pragma unroll
        for (int half = 0; half < 2; half++) {
            int r = row0 + wr + mt * 16 + g + half * 8;
            float rmv = (EPI == 2) ? rowmask[r] : 0.f;
#pragma unroll
            for (int nt = 0; nt < 4; nt++) {
                int c = col0 + wc + nt * 8 + tg * 2;
                float o0 = acc[mt][nt][half * 2 + 0] + bias[c];
                float o1 = acc[mt][nt][half * 2 + 1] + bias[c + 1];
                if (EPI == 1) {
                    o0 = 0.5f * o0 * (1.f + erff(o0 * 0.7071067811865476f));
                    o1 = 0.5f * o1 * (1.f + erff(o1 * 0.7071067811865476f));
                } else if (EPI == 2) {
                    const float* rp = res + (size_t)r * Ndim + c;
                    o0 = (rp[0] + o0) * rmv;
                    o1 = (rp[1] + o1) * rmv;
                } else if (EPI == 3) {
                    const float* rp = res + (size_t)r * Ndim + c;
                    o0 += rp[0];
                    o1 += rp[1];
                }
                if (EPI == 4) {
                    uint32_t hi, lo;
                    bf16_split2(o0, o1, hi, lo);
                    size_t idx = (size_t)r * (Ndim >> 1) + (c >> 1);
                    OutH[idx] = hi;
                    OutL[idx] = lo;
                } else {
                    *(float2*)(Out + (size_t)r * Ndim + c) = make_float2(o0, o1);
                }
            }
        }
    }
}

// ---------------------------------------------------------------------------
// Tile loaders
// ---------------------------------------------------------------------------
// transposed float loader: [d][row], pad 68
__device__ __forceinline__ void load_tile_T(const float* __restrict__ g, int rowStride,
                                            float* __restrict__ sdst, int tid)
{
#pragma unroll
    for (int i = 0; i < 4; i++) {
        int e  = i * 256 + tid;
        int r  = e >> 4;
        int dg = (e & 15) << 2;
        float4 v = *(const float4*)(g + (size_t)r * rowStride + dg);
        sdst[(dg+0)*68 + r] = v.x;
        sdst[(dg+1)*68 + r] = v.y;
        sdst[(dg+2)*68 + r] = v.z;
        sdst[(dg+3)*68 + r] = v.w;
    }
}
// packed u32 loader: 64 rows x 32 u32, smem stride 36
__device__ __forceinline__ void load_tile_P(const uint32_t* __restrict__ g, int rowStride,
                                            uint32_t* __restrict__ sdst, int tid)
{
#pragma unroll
    for (int i = 0; i < 2; i++) {
        int e  = i * 256 + tid;        // 0..511
        int r  = e >> 3;               // 0..63
        int cg = (e & 7) << 2;         // 0,4..28
        uint4 v = *(const uint4*)(g + (size_t)r * rowStride + cg);
        *(uint4*)&sdst[r * 36 + cg] = v;
    }
}

// ---------------------------------------------------------------------------
// Flash attention — tensor-core, precomputed bf16 hi/lo Q,K (no in-loop splits).
// QK^T: 3-term bf16 (bit-identical to computing splits in-loop), P*V: TF32.
// ---------------------------------------------------------------------------
__global__ __launch_bounds__(256) void attn_kernel(
    const uint32_t* __restrict__ qkH, const uint32_t* __restrict__ qkL,
    const float* __restrict__ vsrc, const float* __restrict__ attmask,
    float* __restrict__ y, float* __restrict__ gm, float* __restrict__ gl)
{
    extern __shared__ __align__(16) float sm[];
    uint32_t* Qh = (uint32_t*)sm;              // [64][36]
    uint32_t* Ql = Qh + 64 * 36;
    uint32_t* Kh = Ql + 64 * 36;
    uint32_t* Kl = Kh + 64 * 36;
    float* Vt    = (float*)(Kl + 64 * 36);     // [d][k] 64x68
    float* Ss    = Vt + 64 * 68;               // [q][k] 64x68
    float* Alpha = Ss + 64 * 68;               // [64]
    float* Mrow  = Alpha + 64;
    float* Lrow  = Mrow + 64;
    float* Am    = Lrow + 64;

    const int bh = blockIdx.y, b = bh >> 4, h = bh & 15;
    const int qt = blockIdx.x;
    const int tid = threadIdx.x;
    const int wid = tid >> 5, lane = tid & 31;
    const int g = lane >> 2, tg = lane & 3;
    const int qr0 = (wid & 3) * 16;
    const int wh  = wid >> 2;
    const int srow = tid >> 2;
    const int scg  = tid & 3;
    const float scale = 0.125f;
    const int bhT = bh * T_;

    // Q packed tiles (loop-invariant)
    {
        const uint32_t* qb = qkH + (size_t)(b * T_ + qt * 64) * C_ + h * 32;
        load_tile_P(qb, C_, Qh, tid);
        const uint32_t* ql = qkL + (size_t)(b * T_ + qt * 64) * C_ + h * 32;
        load_tile_P(ql, C_, Ql, tid);
    }

    float m_ = -INFINITY, l_ = 0.f;
    float cpv[4][4];
#pragma unroll
    for (int nt = 0; nt < 4; nt++)
#pragma unroll
        for (int i = 0; i < 4; i++) cpv[nt][i] = 0.f;

    for (int kt = 0; kt <= qt; kt++) {
        __syncthreads();
        {
            const uint32_t* kbh = qkH + (size_t)(b * T_ + kt * 64) * C_ + 512 + h * 32;
            load_tile_P(kbh, C_, Kh, tid);
            const uint32_t* kbl = qkL + (size_t)(b * T_ + kt * 64) * C_ + 512 + h * 32;
            load_tile_P(kbl, C_, Kl, tid);
            load_tile_T(vsrc + (size_t)(b * T_ + kt * 64) * C_ + h * 64, C_, Vt, tid);
            if (tid < 64) Am[tid] = attmask[b * T_ + kt * 64 + tid];
        }
        __syncthreads();

        // ---- QK^T (3-term bf16, fragments straight from packed smem) ----
        {
            float c[4][4];
#pragma unroll
            for (int nt = 0; nt < 4; nt++)
#pragma unroll
                for (int i = 0; i < 4; i++) c[nt][i] = 0.f;
#pragma unroll
            for (int s2 = 0; s2 < 4; s2++) {
                const int kk2 = s2 * 8;
                const uint32_t* qa = Qh + (qr0 + g) * 36 + kk2 + tg;
                const uint32_t* qa_l = Ql + (qr0 + g) * 36 + kk2 + tg;
                uint32_t ah0 = qa[0], ah1 = qa[8 * 36], ah2 = qa[4], ah3 = qa[8 * 36 + 4];
                uint32_t al0 = qa_l[0], al1 = qa_l[8 * 36], al2 = qa_l[4], al3 = qa_l[8 * 36 + 4];
#pragma unroll
                for (int nt = 0; nt < 4; nt++) {
                    const int brow = (wh * 32 + nt * 8 + g) * 36 + kk2 + tg;
                    uint32_t bh0 = Kh[brow], bh1 = Kh[brow + 4];
                    uint32_t bl0 = Kl[brow], bl1 = Kl[brow + 4];
                    mma_bf16(c[nt], ah0, ah1, ah2, ah3, bl0, bl1);
                    mma_bf16(c[nt], al0, al1, al2, al3, bh0, bh1);
                    mma_bf16(c[nt], ah0, ah1, ah2, ah3, bh0, bh1);
                }
            }
            const int qg0 = qt * 64 + qr0 + g;
            const int qg8 = qg0 + 8;
#pragma unroll
            for (int nt = 0; nt < 4; nt++) {
                int kcol = wh * 32 + nt * 8 + 2 * tg;
                int kg0 = kt * 64 + kcol, kg1 = kg0 + 1;
                float a0 = Am[kcol], a1 = Am[kcol + 1];
                float s00 = (kg0 > qg0 || a0 == 0.f) ? -INFINITY : c[nt][0] * scale;
                float s01 = (kg1 > qg0 || a1 == 0.f) ? -INFINITY : c[nt][1] * scale;
                float s80 = (kg0 > qg8 || a0 == 0.f) ? -INFINITY : c[nt][2] * scale;
                float s81 = (kg1 > qg8 || a1 == 0.f) ? -INFINITY : c[nt][3] * scale;
                *(float2*)&Ss[(qr0 + g) * 68 + kcol]     = make_float2(s00, s01);
                *(float2*)&Ss[(qr0 + g + 8) * 68 + kcol] = make_float2(s80, s81);
            }
        }
        __syncthreads();

        // ---- softmax (online, per row) ----
        {
            float sv[16];
            float lmax = -INFINITY;
            const int base = srow * 68 + scg * 16;
#pragma unroll
            for (int i = 0; i < 4; i++) {
                float4 v = *(const float4*)&Ss[base + i * 4];
                sv[i*4+0] = v.x; sv[i*4+1] = v.y; sv[i*4+2] = v.z; sv[i*4+3] = v.w;
                lmax = fmaxf(lmax, fmaxf(fmaxf(v.x, v.y), fmaxf(v.z, v.w)));
            }
            lmax = fmaxf(lmax, __shfl_xor_sync(0xffffffffu, lmax, 1));
            lmax = fmaxf(lmax, __shfl_xor_sync(0xffffffffu, lmax, 2));
            float mn = fmaxf(m_, lmax);
            float alpha = (mn > m_) ? __expf(m_ - mn) : 1.f;
            float lsum = 0.f;
#pragma unroll
            for (int i = 0; i < 16; i++) {
                float p = (sv[i] == -INFINITY) ? 0.f : __expf(sv[i] - mn);
                sv[i] = p;
                lsum += p;
            }
#pragma unroll
            for (int i = 0; i < 4; i++)
                *(float4*)&Ss[base + i * 4] = make_float4(sv[i*4+0], sv[i*4+1],
                                                          sv[i*4+2], sv[i*4+3]);
            lsum += __shfl_xor_sync(0xffffffffu, lsum, 1);
            lsum += __shfl_xor_sync(0xffffffffu, lsum, 2);
            l_ = l_ * alpha + lsum;
            m_ = mn;
            if (scg == 0) Alpha[srow] = alpha;
        }
        __syncthreads();

        // ---- P*V (single TF32) ----
        {
            float a0 = Alpha[qr0 + g];
            float a8 = Alpha[qr0 + g + 8];
#pragma unroll
            for (int nt = 0; nt < 4; nt++) {
                cpv[nt][0] *= a0; cpv[nt][1] *= a0;
                cpv[nt][2] *= a8; cpv[nt][3] *= a8;
            }
#pragma unroll
            for (int s = 0; s < 8; s++) {
                const float* ap = Ss + (qr0 + g) * 68 + s * 8 + tg;
                uint32_t pa0 = cvt_tf32(ap[0]);
                uint32_t pa1 = cvt_tf32(ap[8 * 68]);
                uint32_t pa2 = cvt_tf32(ap[4]);
                uint32_t pa3 = cvt_tf32(ap[8 * 68 + 4]);
#pragma unroll
                for (int nt = 0; nt < 4; nt++) {
                    const float* bp = Vt + (wh * 32 + nt * 8 + g) * 68 + s * 8 + tg;
                    mma_tf32(cpv[nt], pa0, pa1, pa2, pa3,
                             cvt_tf32(bp[0]), cvt_tf32(bp[4]));
                }
            }
        }
    }

    if (scg == 0) { Mrow[srow] = m_; Lrow[srow] = l_; }
    __syncthreads();

    {
        float inv0 = 1.f / Lrow[qr0 + g];
        float inv8 = 1.f / Lrow[qr0 + g + 8];
        float* y0 = y + ((size_t)(b * T_ + qt * 64 + qr0 + g)) * C_ + h * 64;
        float* y8 = y + ((size_t)(b * T_ + qt * 64 + qr0 + g + 8)) * C_ + h * 64;
#pragma unroll
        for (int nt = 0; nt < 4; nt++) {
            int col = wh * 32 + nt * 8 + 2 * tg;
            *(float2*)(y0 + col) = make_float2(cpv[nt][0] * inv0, cpv[nt][1] * inv0);
            *(float2*)(y8 + col) = make_float2(cpv[nt][2] * inv8, cpv[nt][3] * inv8);
        }
    }
    if (tid < 64) {
        gm[bhT + qt * 64 + tid] = Mrow[tid];
        gl[bhT + qt * 64 + tid] = 1.f / Lrow[tid];
    }
}

// ---------------------------------------------------------------------------
// Importance pass — precomputed bf16 hi/lo Q,K, deterministic column sums.
// ---------------------------------------------------------------------------
__global__ __launch_bounds__(256) void imp_kernel(
    const uint32_t* __restrict__ qkH, const uint32_t* __restrict__ qkL,
    const float* __restrict__ attmask,
    const float* __restrict__ gm, const float* __restrict__ gl,
    float* __restrict__ impH)
{
    __shared__ __align__(16) uint32_t Kh[64 * 36];
    __shared__ __align__(16) uint32_t Kl[64 * 36];
    __shared__ __align__(16) uint32_t Qh[64 * 36];
    __shared__ __align__(16) uint32_t Ql[64 * 36];
    __shared__ float part[2][64];

    const int bh = blockIdx.y, b = bh >> 4, h = bh & 15;
    const int kt = blockIdx.x;
    const int tid = threadIdx.x;
    const int wid = tid >> 5, lane = tid & 31;
    const int g = lane >> 2, tg = lane & 3;
    const int kr0 = (wid & 3) * 16;
    const int qh_ = wid >> 2;
    const int qc0 = qh_ * 32;
    const float scale = 0.125f;
    const int bhT = bh * T_;

    load_tile_P(qkH + (size_t)(b * T_ + kt * 64) * C_ + 512 + h * 32, C_, Kh, tid);
    load_tile_P(qkL + (size_t)(b * T_ + kt * 64) * C_ + 512 + h * 32, C_, Kl, tid);

    const int kg0 = kt * 64 + kr0 + g;
    const int kg1 = kg0 + 8;
    const float amk0 = attmask[b * T_ + kt * 64 + kr0 + g];
    const float amk1 = attmask[b * T_ + kt * 64 + kr0 + g + 8];

    float imp0 = 0.f, imp1 = 0.f;

    for (int qt = kt; qt < NT_; qt++) {
        __syncthreads();
        load_tile_P(qkH + (size_t)(b * T_ + qt * 64) * C_ + h * 32, C_, Qh, tid);
        load_tile_P(qkL + (size_t)(b * T_ + qt * 64) * C_ + h * 32, C_, Ql, tid);
        __syncthreads();

        float c[4][4];
#pragma unroll
        for (int nt = 0; nt < 4; nt++)
#pragma unroll
            for (int i = 0; i < 4; i++) c[nt][i] = 0.f;

#pragma unroll
        for (int s2 = 0; s2 < 4; s2++) {
            const int kk2 = s2 * 8;
            const uint32_t* ka = Kh + (kr0 + g) * 36 + kk2 + tg;
            const uint32_t* ka_l = Kl + (kr0 + g) * 36 + kk2 + tg;
            uint32_t kh0 = ka[0], kh1 = ka[8 * 36], kh2 = ka[4], kh3 = ka[8 * 36 + 4];
            uint32_t kl0 = ka_l[0], kl1 = ka_l[8 * 36], kl2 = ka_l[4], kl3 = ka_l[8 * 36 + 4];
#pragma unroll
            for (int nt = 0; nt < 4; nt++) {
                const int brow = (qc0 + nt * 8 + g) * 36 + kk2 + tg;
                uint32_t bh0 = Qh[brow], bh1 = Qh[brow + 4];
                uint32_t bl0 = Ql[brow], bl1 = Ql[brow + 4];
                mma_bf16(c[nt], kh0, kh1, kh2, kh3, bl0, bl1);
                mma_bf16(c[nt], kl0, kl1, kl2, kl3, bh0, bh1);
                mma_bf16(c[nt], kh0, kh1, kh2, kh3, bh0, bh1);
            }
        }

#pragma unroll
        for (int nt = 0; nt < 4; nt++) {
            const int qg0 = qt * 64 + qc0 + nt * 8 + 2 * tg;
            const int qg1 = qg0 + 1;
            const float mq0 = gm[bhT + qg0], mq1 = gm[bhT + qg1];
            const float rq0 = gl[bhT + qg0], rq1 = gl[bhT + qg1];
            if (qg0 >= kg0) imp0 += amk0 * __expf(fmaf(c[nt][0], scale, -mq0)) * rq0;
            if (qg1 >= kg0) imp0 += amk0 * __expf(fmaf(c[nt][1], scale, -mq1)) * rq1;
            if (qg0 >= kg1) imp1 += amk1 * __expf(fmaf(c[nt][2], scale, -mq0)) * rq0;
            if (qg1 >= kg1) imp1 += amk1 * __expf(fmaf(c[nt][3], scale, -mq1)) * rq1;
        }
    }

    imp0 += __shfl_xor_sync(0xffffffffu, imp0, 1);
    imp0 += __shfl_xor_sync(0xffffffffu, imp0, 2);
    imp1 += __shfl_xor_sync(0xffffffffu, imp1, 1);
    imp1 += __shfl_xor_sync(0xffffffffu, imp1, 2);
    if (tg == 0) {
        part[qh_][kr0 + g] = imp0;
        part[qh_][kr0 + 8 + g] = imp1;
    }
    __syncthreads();
    if (tid < 64)
        impH[bhT + kt * 64 + tid] = part[0][tid] + part[1][tid];
}

// ---------------------------------------------------------------------------
// Finalize pruning mask
// ---------------------------------------------------------------------------
__global__ __launch_bounds__(256) void finalize_mask(
    const float* __restrict__ impH, const float* __restrict__ attmask,
    const float* __restrict__ prot, const float* __restrict__ thresh,
    float* __restrict__ cm, float* __restrict__ out_mask,
    float* __restrict__ out_loss)
{
    int i = blockIdx.x * 256 + threadIdx.x;
    int b = i / T_, t = i % T_;
    float s = 0.f;
#pragma unroll
    for (int h = 0; h < H_; h++) s += impH[(b * H_ + h) * T_ + t];
    float imp = s * (1.f / ((float)H_ * (float)T_));
    float pm = (imp >= thresh[0]) ? 1.f : 0.f;
    if (prot[i] > 0.f) pm = 1.f;
    float c = attmask[i] * pm;
    cm[i] = c;
    out_mask[i] = c;
    if (i == 0) out_loss[0] = 0.f;
}

// ---------------------------------------------------------------------------
// Launch
// ---------------------------------------------------------------------------
extern "C" void kernel_launch(void* const* d_in, const int* in_sizes, int n_in,
                              void* d_out, int out_size)
{
    const float* x              = (const float*)d_in[0];
    const float* attention_mask = (const float*)d_in[1];
    const float* protected_mask = (const float*)d_in[2];
    const float* ln1_w          = (const float*)d_in[3];
    const float* ln1_b          = (const float*)d_in[4];
    const float* c_attn_w       = (const float*)d_in[5];
    const float* c_attn_b       = (const float*)d_in[6];
    const float* c_proj_w       = (const float*)d_in[7];
    const float* c_proj_b       = (const float*)d_in[8];
    const float* ln2_w          = (const float*)d_in[9];
    const float* ln2_b          = (const float*)d_in[10];
    const float* fc_w           = (const float*)d_in[11];
    const float* fc_b           = (const float*)d_in[12];
    const float* fcproj_w       = (const float*)d_in[13];
    const float* fcproj_b       = (const float*)d_in[14];
    const float* threshold      = (const float*)d_in[15];

    float* out      = (float*)d_out;
    float* out_mask = out + (size_t)M_ * C_;
    float* out_loss = out_mask + M_;

    float *p_h, *p_v, *p_y, *p_m, *p_l, *p_imp, *p_cm, *p_xres, *p_fc;
    uint32_t *p_qkH, *p_qkL;
    cudaGetSymbolAddress((void**)&p_h,    g_h);
    cudaGetSymbolAddress((void**)&p_qkH,  g_qkH);
    cudaGetSymbolAddress((void**)&p_qkL,  g_qkL);
    cudaGetSymbolAddress((void**)&p_v,    g_v);
    cudaGetSymbolAddress((void**)&p_y,    g_y);
    cudaGetSymbolAddress((void**)&p_m,    g_m);
    cudaGetSymbolAddress((void**)&p_l,    g_l);
    cudaGetSymbolAddress((void**)&p_imp,  g_impH);
    cudaGetSymbolAddress((void**)&p_cm,   g_cm);
    cudaGetSymbolAddress((void**)&p_xres, g_xres);
    cudaGetSymbolAddress((void**)&p_fc,   g_fc);

    // 4 packed tiles (64x36 u32) + Vt + Ss (64x68 f32) + 256 f32
    const size_t attn_smem = (size_t)(4 * 64 * 36 + 2 * 64 * 68 + 256) * 4; // 72704B
    cudaFuncSetAttribute(attn_kernel, cudaFuncAttributeMaxDynamicSharedMemorySize,
                         (int)attn_smem);

    // 1. LN1
    ln_kernel<<<M_, 256>>>(x, ln1_w, ln1_b, p_h);
    // 2a. Q,K columns: 3-term bf16 GEMM; epilogue packs hi/lo bf16x2
    gemm_tc<4,1><<<dim3(2 * C_ / 128, M_ / 128), 256>>>(
        p_h, c_attn_w, c_attn_b, nullptr, 2 * C_, C_, nullptr, nullptr,
        p_qkH, p_qkL);
    // 2b. V columns: single TF32 -> g_v (row stride C)
    gemm_tc<0,0><<<dim3(C_ / 128, M_ / 128), 256>>>(
        p_h, c_attn_w + (size_t)(2 * C_) * C_, c_attn_b + 2 * C_, p_v,
        C_, C_, nullptr, nullptr, nullptr, nullptr);
    // 3. Flash attention -> y, (m, 1/l)
    attn_kernel<<<dim3(NT_, B_ * H_), 256, attn_smem>>>(
        p_qkH, p_qkL, p_v, attention_mask, p_y, p_m, p_l);
    // 4. Importance column sums (deterministic)
    imp_kernel<<<dim3(NT_, B_ * H_), 256>>>(
        p_qkH, p_qkL, attention_mask, p_m, p_l, p_imp);
    // 5. Combined mask
    finalize_mask<<<M_ / 256, 256>>>(p_imp, attention_mask, protected_mask,
                                     threshold, p_cm, out_mask, out_loss);
    // 6. proj + residual + prune mask, TF32
    gemm_tc<2,0><<<dim3(C_ / 128, M_ / 128), 256>>>(
        p_y, c_proj_w, c_proj_b, p_xres, C_, C_, x, p_cm, nullptr, nullptr);
    // 7. LN2
    ln_kernel<<<M_, 256>>>(p_xres, ln2_w, ln2_b, p_h);
    // 8. fc + GELU, TF32
    gemm_tc<1,0><<<dim3(4 * C_ / 128, M_ / 128), 256>>>(
        p_h, fc_w, fc_b, p_fc, 4 * C_, C_, nullptr, nullptr, nullptr, nullptr);
    // 9. fcproj + residual -> d_out, TF32
    gemm_tc<3,0><<<dim3(C_ / 128, M_ / 128), 256>>>(
        p_fc, fcproj_w, fcproj_b, out, C_, 4 * C_, p_xres, nullptr, nullptr, nullptr);
}

// round 17
// speedup vs baseline: 2.3172x; 1.0028x over previous
#include <cuda_runtime.h>
#include <cuda_bf16.h>
#include <cuda_fp16.h>
#include <math.h>
#include <stdint.h>

// Problem constants
#define B_  4
#define T_  2048
#define C_  1024
#define H_  16
#define HS_ 64
#define M_  (B_*T_)      // 8192 rows
#define NT_ (T_/64)      // 32 tiles of 64

// ---------------------------------------------------------------------------
// Scratch (device globals; no runtime allocation allowed)
// ---------------------------------------------------------------------------
__device__ float    g_h   [M_*C_];         // LN output
__device__ uint32_t g_qkH [M_*C_];         // Q,K packed bf16x2 HI
__device__ uint32_t g_qkL [M_*C_];         // Q,K packed bf16x2 LO
__device__ float    g_v   [M_*C_];         // V (float)
__device__ float    g_y   [M_*C_];         // attention output
__device__ float    g_m   [B_*H_*T_];      // per-row softmax max
__device__ float    g_l   [B_*H_*T_];      // per-row 1/denominator
__device__ float    g_impH[B_*H_*T_];      // per-head importance sums
__device__ float    g_cm  [M_];            // combined mask
__device__ float    g_xres[M_*C_];         // attn residual + prune mask
__device__ float    g_fc  [M_*4*C_];       // MLP hidden

// ---------------------------------------------------------------------------
// LayerNorm
// ---------------------------------------------------------------------------
__global__ __launch_bounds__(256) void ln_kernel(
    const float* __restrict__ x, const float* __restrict__ w,
    const float* __restrict__ bias, float* __restrict__ out)
{
    int row = blockIdx.x;
    int tid = threadIdx.x;
    const float* xr = x + (size_t)row * C_;
    float4 v = *(const float4*)(xr + tid * 4);
    float s1 = v.x + v.y + v.z + v.w;
    float s2 = v.x*v.x + v.y*v.y + v.z*v.z + v.w*v.w;
#pragma unroll
    for (int o = 16; o; o >>= 1) {
        s1 += __shfl_xor_sync(0xffffffffu, s1, o);
        s2 += __shfl_xor_sync(0xffffffffu, s2, o);
    }
    __shared__ float sh1[8], sh2[8];
    int wi = tid >> 5;
    if ((tid & 31) == 0) { sh1[wi] = s1; sh2[wi] = s2; }
    __syncthreads();
    float t1 = 0.f, t2 = 0.f;
#pragma unroll
    for (int i = 0; i < 8; i++) { t1 += sh1[i]; t2 += sh2[i]; }
    float mean = t1 * (1.f / C_);
    float var  = t2 * (1.f / C_) - mean * mean;
    float inv  = rsqrtf(var + 1e-5f);
    float4 wv = *(const float4*)(w + tid * 4);
    float4 bv = *(const float4*)(bias + tid * 4);
    float4 o;
    o.x = (v.x - mean) * inv * wv.x + bv.x;
    o.y = (v.y - mean) * inv * wv.y + bv.y;
    o.z = (v.z - mean) * inv * wv.z + bv.z;
    o.w = (v.w - mean) * inv * wv.w + bv.w;
    *(float4*)(out + (size_t)row * C_ + tid * 4) = o;
}

// ---------------------------------------------------------------------------
// Tensor-core helpers
// ---------------------------------------------------------------------------
__device__ __forceinline__ void mma_bf16(float* c,
    uint32_t a0, uint32_t a1, uint32_t a2, uint32_t a3,
    uint32_t b0, uint32_t b1)
{
    asm volatile(
        "mma.sync.aligned.m16n8k16.row.col.f32.bf16.bf16.f32 "
        "{%0,%1,%2,%3}, {%4,%5,%6,%7}, {%8,%9}, {%0,%1,%2,%3};"
        : "+f"(c[0]), "+f"(c[1]), "+f"(c[2]), "+f"(c[3])
        : "r"(a0), "r"(a1), "r"(a2), "r"(a3), "r"(b0), "r"(b1));
}
__device__ __forceinline__ void mma_f16(float* c,
    uint32_t a0, uint32_t a1, uint32_t a2, uint32_t a3,
    uint32_t b0, uint32_t b1)
{
    asm volatile(
        "mma.sync.aligned.m16n8k16.row.col.f32.f16.f16.f32 "
        "{%0,%1,%2,%3}, {%4,%5,%6,%7}, {%8,%9}, {%0,%1,%2,%3};"
        : "+f"(c[0]), "+f"(c[1]), "+f"(c[2]), "+f"(c[3])
        : "r"(a0), "r"(a1), "r"(a2), "r"(a3), "r"(b0), "r"(b1));
}
__device__ __forceinline__ uint32_t h2pack(float x0, float x1) {
    __half2 h = __floats2half2_rn(x0, x1);
    return *(uint32_t*)&h;
}
__device__ __forceinline__ void bf16_split2(float x0, float x1,
                                            uint32_t &hi, uint32_t &lo)
{
    __nv_bfloat162 h = __floats2bfloat162_rn(x0, x1);
    float h0 = __bfloat162float(h.x);
    float h1 = __bfloat162float(h.y);
    __nv_bfloat162 l = __floats2bfloat162_rn(x0 - h0, x1 - h1);
    hi = *(uint32_t*)&h;
    lo = *(uint32_t*)&l;
}

// ---------------------------------------------------------------------------
// Tensor-core GEMM: Out[M,N] = A[M,K] @ W[N,K]^T (+bias, +epilogue)
// EPI 0: bias | 1: +GELU | 2: (res+bias+acc)*rowmask | 3: res+bias+acc
// EPI 4: bias, then bf16 hi/lo split packed into OutH/OutL
// PREC 1: 3-term bf16 split (~4e-6) | PREC 2: single fp16 (~5e-4, m16n8k16)
// 128x128 block, BK=32, 256 threads, register prefetch.
// ---------------------------------------------------------------------------
#define GSTRIDE 36

template<int EPI, int PREC>
__global__ __launch_bounds__(256) void gemm_tc(
    const float* __restrict__ A, const float* __restrict__ W,
    const float* __restrict__ bias, float* __restrict__ Out,
    int Ndim, int Kdim,
    const float* __restrict__ res, const float* __restrict__ rowmask,
    uint32_t* __restrict__ OutH, uint32_t* __restrict__ OutL)
{
    __shared__ __align__(16) float Sa[128 * GSTRIDE];
    __shared__ __align__(16) float Sw[128 * GSTRIDE];
    const int tid = threadIdx.x;
    const int row0 = blockIdx.y * 128, col0 = blockIdx.x * 128;

    const int wid  = tid >> 5, lane = tid & 31;
    const int g    = lane >> 2, tg = lane & 3;
    const int wr   = (wid >> 2) * 64;
    const int wc   = (wid & 3) * 32;

    float4 pa[4], pw[4];
    auto issue_loads = [&](int k0) {
#pragma unroll
        for (int i = 0; i < 4; i++) {
            int slot = i * 256 + tid;
            int r  = slot >> 3;
            int kg = (slot & 7) << 2;
            pa[i] = *(const float4*)(A + (size_t)(row0 + r) * Kdim + k0 + kg);
            pw[i] = *(const float4*)(W + (size_t)(col0 + r) * Kdim + k0 + kg);
        }
    };
    auto store_stage = [&]() {
#pragma unroll
        for (int i = 0; i < 4; i++) {
            int slot = i * 256 + tid;
            int r  = slot >> 3;
            int kg = (slot & 7) << 2;
            *(float4*)&Sa[r * GSTRIDE + kg] = pa[i];
            *(float4*)&Sw[r * GSTRIDE + kg] = pw[i];
        }
    };

    float acc[4][4][4];
#pragma unroll
    for (int mt = 0; mt < 4; mt++)
#pragma unroll
        for (int nt = 0; nt < 4; nt++)
#pragma unroll
            for (int i = 0; i < 4; i++) acc[mt][nt][i] = 0.f;

    issue_loads(0);
    store_stage();
    __syncthreads();

    const int KT = Kdim >> 5;
    for (int kt = 0; kt < KT; kt++) {
        const bool has_next = (kt + 1) < KT;
        if (has_next) issue_loads((kt + 1) << 5);

        if (PREC == 1) {
#pragma unroll
            for (int s2 = 0; s2 < 2; s2++) {
                const int kk = s2 * 16;
                uint32_t ah[4][4], al[4][4], bh4[4][2], bl4[4][2];
#pragma unroll
                for (int mt = 0; mt < 4; mt++) {
                    const float* p0 = Sa + (wr + mt * 16 + g) * GSTRIDE + kk + 2 * tg;
                    float2 xa0 = *(const float2*)p0;
                    float2 xa1 = *(const float2*)(p0 + 8 * GSTRIDE);
                    float2 xa2 = *(const float2*)(p0 + 8);
                    float2 xa3 = *(const float2*)(p0 + 8 * GSTRIDE + 8);
                    bf16_split2(xa0.x, xa0.y, ah[mt][0], al[mt][0]);
                    bf16_split2(xa1.x, xa1.y, ah[mt][1], al[mt][1]);
                    bf16_split2(xa2.x, xa2.y, ah[mt][2], al[mt][2]);
                    bf16_split2(xa3.x, xa3.y, ah[mt][3], al[mt][3]);
                }
#pragma unroll
                for (int nt = 0; nt < 4; nt++) {
                    const float* p = Sw + (wc + nt * 8 + g) * GSTRIDE + kk + 2 * tg;
                    float2 xb0 = *(const float2*)p;
                    float2 xb1 = *(const float2*)(p + 8);
                    bf16_split2(xb0.x, xb0.y, bh4[nt][0], bl4[nt][0]);
                    bf16_split2(xb1.x, xb1.y, bh4[nt][1], bl4[nt][1]);
                }
#pragma unroll
                for (int mt = 0; mt < 4; mt++)
#pragma unroll
                    for (int nt = 0; nt < 4; nt++) {
                        mma_bf16(acc[mt][nt], ah[mt][0], ah[mt][1], ah[mt][2], ah[mt][3],
                                 bl4[nt][0], bl4[nt][1]);
                        mma_bf16(acc[mt][nt], al[mt][0], al[mt][1], al[mt][2], al[mt][3],
                                 bh4[nt][0], bh4[nt][1]);
                        mma_bf16(acc[mt][nt], ah[mt][0], ah[mt][1], ah[mt][2], ah[mt][3],
                                 bh4[nt][0], bh4[nt][1]);
                    }
            }
        } else {
            // single fp16, two k16 steps per tile
#pragma unroll
            for (int s2 = 0; s2 < 2; s2++) {
                const int kk = s2 * 16;
                uint32_t ah[4][4], bh4[4][2];
#pragma unroll
                for (int mt = 0; mt < 4; mt++) {
                    const float* p0 = Sa + (wr + mt * 16 + g) * GSTRIDE + kk + 2 * tg;
                    float2 xa0 = *(const float2*)p0;
                    float2 xa1 = *(const float2*)(p0 + 8 * GSTRIDE);
                    float2 xa2 = *(const float2*)(p0 + 8);
                    float2 xa3 = *(const float2*)(p0 + 8 * GSTRIDE + 8);
                    ah[mt][0] = h2pack(xa0.x, xa0.y);
                    ah[mt][1] = h2pack(xa1.x, xa1.y);
                    ah[mt][2] = h2pack(xa2.x, xa2.y);
                    ah[mt][3] = h2pack(xa3.x, xa3.y);
                }
#pragma unroll
                for (int nt = 0; nt < 4; nt++) {
                    const float* p = Sw + (wc + nt * 8 + g) * GSTRIDE + kk + 2 * tg;
                    float2 xb0 = *(const float2*)p;
                    float2 xb1 = *(const float2*)(p + 8);
                    bh4[nt][0] = h2pack(xb0.x, xb0.y);
                    bh4[nt][1] = h2pack(xb1.x, xb1.y);
                }
#pragma unroll
                for (int mt = 0; mt < 4; mt++)
#pragma unroll
                    for (int nt = 0; nt < 4; nt++)
                        mma_f16(acc[mt][nt], ah[mt][0], ah[mt][1], ah[mt][2], ah[mt][3],
                                bh4[nt][0], bh4[nt][1]);
            }
        }

        if (has_next) {
            __syncthreads();
            store_stage();
            __syncthreads();
        }
    }

#pragma unroll
    for (int mt = 0; mt < 4; mt++) {
#pragma unroll
        for (int half = 0; half < 2; half++) {
            int r = row0 + wr + mt * 16 + g + half * 8;
            float rmv = (EPI == 2) ? rowmask[r] : 0.f;
#pragma unroll
            for (int nt = 0; nt < 4; nt++) {
                int c = col0 + wc + nt * 8 + tg * 2;
                float o0 = acc[mt][nt][half * 2 + 0] + bias[c];
                float o1 = acc[mt][nt][half * 2 + 1] + bias[c + 1];
                if (EPI == 1) {
                    o0 = 0.5f * o0 * (1.f + erff(o0 * 0.7071067811865476f));
                    o1 = 0.5f * o1 * (1.f + erff(o1 * 0.7071067811865476f));
                } else if (EPI == 2) {
                    const float* rp = res + (size_t)r * Ndim + c;
                    o0 = (rp[0] + o0) * rmv;
                    o1 = (rp[1] + o1) * rmv;
                } else if (EPI == 3) {
                    const float* rp = res + (size_t)r * Ndim + c;
                    o0 += rp[0];
                    o1 += rp[1];
                }
                if (EPI == 4) {
                    uint32_t hi, lo;
                    bf16_split2(o0, o1, hi, lo);
                    size_t idx = (size_t)r * (Ndim >> 1) + (c >> 1);
                    OutH[idx] = hi;
                    OutL[idx] = lo;
                } else {
                    *(float2*)(Out + (size_t)r * Ndim + c) = make_float2(o0, o1);
                }
            }
        }
    }
}

// ---------------------------------------------------------------------------
// Tile loaders
// ---------------------------------------------------------------------------
__device__ __forceinline__ void load_tile_T(const float* __restrict__ g, int rowStride,
                                            float* __restrict__ sdst, int tid)
{
#pragma unroll
    for (int i = 0; i < 4; i++) {
        int e  = i * 256 + tid;
        int r  = e >> 4;
        int dg = (e & 15) << 2;
        float4 v = *(const float4*)(g + (size_t)r * rowStride + dg);
        sdst[(dg+0)*68 + r] = v.x;
        sdst[(dg+1)*68 + r] = v.y;
        sdst[(dg+2)*68 + r] = v.z;
        sdst[(dg+3)*68 + r] = v.w;
    }
}
__device__ __forceinline__ void load_tile_P(const uint32_t* __restrict__ g, int rowStride,
                                            uint32_t* __restrict__ sdst, int tid)
{
#pragma unroll
    for (int i = 0; i < 2; i++) {
        int e  = i * 256 + tid;
        int r  = e >> 3;
        int cg = (e & 7) << 2;
        uint4 v = *(const uint4*)(g + (size_t)r * rowStride + cg);
        *(uint4*)&sdst[r * 36 + cg] = v;
    }
}

// ---------------------------------------------------------------------------
// Flash attention — tensor-core.
// QK^T: 3-term bf16 from precomputed packed hi/lo (flip-safe).
// Softmax packs P to fp16x2 in-place (aliases Ss; warp-local rows, safe).
// P*V: fp16 m16n8k16 (A = packed P, B = Vt converted in-loop).
// ---------------------------------------------------------------------------
__global__ __launch_bounds__(256) void attn_kernel(
    const uint32_t* __restrict__ qkH, const uint32_t* __restrict__ qkL,
    const float* __restrict__ vsrc, const float* __restrict__ attmask,
    float* __restrict__ y, float* __restrict__ gm, float* __restrict__ gl)
{
    extern __shared__ __align__(16) float sm[];
    uint32_t* Qh = (uint32_t*)sm;              // [64][36]
    uint32_t* Ql = Qh + 64 * 36;
    uint32_t* Kh = Ql + 64 * 36;
    uint32_t* Kl = Kh + 64 * 36;
    float* Vt    = (float*)(Kl + 64 * 36);     // [d][k] 64x68
    float* Ss    = Vt + 64 * 68;               // [q][k] 64x68 scores; packed P aliases
    float* Alpha = Ss + 64 * 68;
    float* Mrow  = Alpha + 64;
    float* Lrow  = Mrow + 64;
    float* Am    = Lrow + 64;
    uint32_t* Pp = (uint32_t*)Ss;              // packed fp16 P, stride 68 u32

    const int bh = blockIdx.y, b = bh >> 4, h = bh & 15;
    const int qt = blockIdx.x;
    const int tid = threadIdx.x;
    const int wid = tid >> 5, lane = tid & 31;
    const int g = lane >> 2, tg = lane & 3;
    const int qr0 = (wid & 3) * 16;
    const int wh  = wid >> 2;
    const int srow = tid >> 2;
    const int scg  = tid & 3;
    const float scale = 0.125f;
    const int bhT = bh * T_;

    {
        const uint32_t* qb = qkH + (size_t)(b * T_ + qt * 64) * C_ + h * 32;
        load_tile_P(qb, C_, Qh, tid);
        const uint32_t* ql = qkL + (size_t)(b * T_ + qt * 64) * C_ + h * 32;
        load_tile_P(ql, C_, Ql, tid);
    }

    float m_ = -INFINITY, l_ = 0.f;
    float cpv[4][4];
#pragma unroll
    for (int nt = 0; nt < 4; nt++)
#pragma unroll
        for (int i = 0; i < 4; i++) cpv[nt][i] = 0.f;

    for (int kt = 0; kt <= qt; kt++) {
        __syncthreads();
        {
            const uint32_t* kbh = qkH + (size_t)(b * T_ + kt * 64) * C_ + 512 + h * 32;
            load_tile_P(kbh, C_, Kh, tid);
            const uint32_t* kbl = qkL + (size_t)(b * T_ + kt * 64) * C_ + 512 + h * 32;
            load_tile_P(kbl, C_, Kl, tid);
            load_tile_T(vsrc + (size_t)(b * T_ + kt * 64) * C_ + h * 64, C_, Vt, tid);
            if (tid < 64) Am[tid] = attmask[b * T_ + kt * 64 + tid];
        }
        __syncthreads();

        // ---- QK^T (3-term bf16) ----
        {
            float c[4][4];
#pragma unroll
            for (int nt = 0; nt < 4; nt++)
#pragma unroll
                for (int i = 0; i < 4; i++) c[nt][i] = 0.f;
#pragma unroll
            for (int s2 = 0; s2 < 4; s2++) {
                const int kk2 = s2 * 8;
                const uint32_t* qa = Qh + (qr0 + g) * 36 + kk2 + tg;
                const uint32_t* qa_l = Ql + (qr0 + g) * 36 + kk2 + tg;
                uint32_t ah0 = qa[0], ah1 = qa[8 * 36], ah2 = qa[4], ah3 = qa[8 * 36 + 4];
                uint32_t al0 = qa_l[0], al1 = qa_l[8 * 36], al2 = qa_l[4], al3 = qa_l[8 * 36 + 4];
#pragma unroll
                for (int nt = 0; nt < 4; nt++) {
                    const int brow = (wh * 32 + nt * 8 + g) * 36 + kk2 + tg;
                    uint32_t bh0 = Kh[brow], bh1 = Kh[brow + 4];
                    uint32_t bl0 = Kl[brow], bl1 = Kl[brow + 4];
                    mma_bf16(c[nt], ah0, ah1, ah2, ah3, bl0, bl1);
                    mma_bf16(c[nt], al0, al1, al2, al3, bh0, bh1);
                    mma_bf16(c[nt], ah0, ah1, ah2, ah3, bh0, bh1);
                }
            }
            const int qg0 = qt * 64 + qr0 + g;
            const int qg8 = qg0 + 8;
#pragma unroll
            for (int nt = 0; nt < 4; nt++) {
                int kcol = wh * 32 + nt * 8 + 2 * tg;
                int kg0 = kt * 64 + kcol, kg1 = kg0 + 1;
                float a0 = Am[kcol], a1 = Am[kcol + 1];
                float s00 = (kg0 > qg0 || a0 == 0.f) ? -INFINITY : c[nt][0] * scale;
                float s01 = (kg1 > qg0 || a1 == 0.f) ? -INFINITY : c[nt][1] * scale;
                float s80 = (kg0 > qg8 || a0 == 0.f) ? -INFINITY : c[nt][2] * scale;
                float s81 = (kg1 > qg8 || a1 == 0.f) ? -INFINITY : c[nt][3] * scale;
                *(float2*)&Ss[(qr0 + g) * 68 + kcol]     = make_float2(s00, s01);
                *(float2*)&Ss[(qr0 + g + 8) * 68 + kcol] = make_float2(s80, s81);
            }
        }
        __syncthreads();

        // ---- softmax; pack P to fp16x2 in place ----
        {
            float sv[16];
            float lmax = -INFINITY;
            const int base = srow * 68 + scg * 16;
#pragma unroll
            for (int i = 0; i < 4; i++) {
                float4 v = *(const float4*)&Ss[base + i * 4];
                sv[i*4+0] = v.x; sv[i*4+1] = v.y; sv[i*4+2] = v.z; sv[i*4+3] = v.w;
                lmax = fmaxf(lmax, fmaxf(fmaxf(v.x, v.y), fmaxf(v.z, v.w)));
            }
            lmax = fmaxf(lmax, __shfl_xor_sync(0xffffffffu, lmax, 1));
            lmax = fmaxf(lmax, __shfl_xor_sync(0xffffffffu, lmax, 2));
            float mn = fmaxf(m_, lmax);
            float alpha = (mn > m_) ? __expf(m_ - mn) : 1.f;
            float lsum = 0.f;
#pragma unroll
            for (int i = 0; i < 16; i++) {
                float p = (sv[i] == -INFINITY) ? 0.f : __expf(sv[i] - mn);
                sv[i] = p;
                lsum += p;
            }
            // pack 16 floats -> 8 u32 fp16x2 (same-warp row; reads done above)
#pragma unroll
            for (int i = 0; i < 8; i++)
                Pp[srow * 68 + scg * 8 + i] = h2pack(sv[2*i], sv[2*i+1]);
            lsum += __shfl_xor_sync(0xffffffffu, lsum, 1);
            lsum += __shfl_xor_sync(0xffffffffu, lsum, 2);
            l_ = l_ * alpha + lsum;
            m_ = mn;
            if (scg == 0) Alpha[srow] = alpha;
        }
        __syncthreads();

        // ---- P*V (fp16 m16n8k16) ----
        {
            float a0 = Alpha[qr0 + g];
            float a8 = Alpha[qr0 + g + 8];
#pragma unroll
            for (int nt = 0; nt < 4; nt++) {
                cpv[nt][0] *= a0; cpv[nt][1] *= a0;
                cpv[nt][2] *= a8; cpv[nt][3] *= a8;
            }
#pragma unroll
            for (int s2 = 0; s2 < 2; s2++) {
                const int base = (qr0 + g) * 68 + s2 * 8 + tg;
                uint32_t pa0 = Pp[base];
                uint32_t pa1 = Pp[base + 8 * 68];
                uint32_t pa2 = Pp[base + 4];
                uint32_t pa3 = Pp[base + 8 * 68 + 4];
#pragma unroll
                for (int nt = 0; nt < 4; nt++) {
                    const float* bp = Vt + (wh * 32 + nt * 8 + g) * 68 + s2 * 16 + 2 * tg;
                    uint32_t b0 = h2pack(bp[0], bp[1]);
                    uint32_t b1 = h2pack(bp[8], bp[9]);
                    mma_f16(cpv[nt], pa0, pa1, pa2, pa3, b0, b1);
                }
            }
        }
    }

    if (scg == 0) { Mrow[srow] = m_; Lrow[srow] = l_; }
    __syncthreads();

    {
        float inv0 = 1.f / Lrow[qr0 + g];
        float inv8 = 1.f / Lrow[qr0 + g + 8];
        float* y0 = y + ((size_t)(b * T_ + qt * 64 + qr0 + g)) * C_ + h * 64;
        float* y8 = y + ((size_t)(b * T_ + qt * 64 + qr0 + g + 8)) * C_ + h * 64;
#pragma unroll
        for (int nt = 0; nt < 4; nt++) {
            int col = wh * 32 + nt * 8 + 2 * tg;
            *(float2*)(y0 + col) = make_float2(cpv[nt][0] * inv0, cpv[nt][1] * inv0);
            *(float2*)(y8 + col) = make_float2(cpv[nt][2] * inv8, cpv[nt][3] * inv8);
        }
    }
    if (tid < 64) {
        gm[bhT + qt * 64 + tid] = Mrow[tid];
        gl[bhT + qt * 64 + tid] = 1.f / Lrow[tid];
    }
}

// ---------------------------------------------------------------------------
// Importance pass — precomputed bf16 hi/lo Q,K, deterministic column sums.
// ---------------------------------------------------------------------------
__global__ __launch_bounds__(256) void imp_kernel(
    const uint32_t* __restrict__ qkH, const uint32_t* __restrict__ qkL,
    const float* __restrict__ attmask,
    const float* __restrict__ gm, const float* __restrict__ gl,
    float* __restrict__ impH)
{
    __shared__ __align__(16) uint32_t Kh[64 * 36];
    __shared__ __align__(16) uint32_t Kl[64 * 36];
    __shared__ __align__(16) uint32_t Qh[64 * 36];
    __shared__ __align__(16) uint32_t Ql[64 * 36];
    __shared__ float part[2][64];

    const int bh = blockIdx.y, b = bh >> 4, h = bh & 15;
    const int kt = blockIdx.x;
    const int tid = threadIdx.x;
    const int wid = tid >> 5, lane = tid & 31;
    const int g = lane >> 2, tg = lane & 3;
    const int kr0 = (wid & 3) * 16;
    const int qh_ = wid >> 2;
    const int qc0 = qh_ * 32;
    const float scale = 0.125f;
    const int bhT = bh * T_;

    load_tile_P(qkH + (size_t)(b * T_ + kt * 64) * C_ + 512 + h * 32, C_, Kh, tid);
    load_tile_P(qkL + (size_t)(b * T_ + kt * 64) * C_ + 512 + h * 32, C_, Kl, tid);

    const int kg0 = kt * 64 + kr0 + g;
    const int kg1 = kg0 + 8;
    const float amk0 = attmask[b * T_ + kt * 64 + kr0 + g];
    const float amk1 = attmask[b * T_ + kt * 64 + kr0 + g + 8];

    float imp0 = 0.f, imp1 = 0.f;

    for (int qt = kt; qt < NT_; qt++) {
        __syncthreads();
        load_tile_P(qkH + (size_t)(b * T_ + qt * 64) * C_ + h * 32, C_, Qh, tid);
        load_tile_P(qkL + (size_t)(b * T_ + qt * 64) * C_ + h * 32, C_, Ql, tid);
        __syncthreads();

        float c[4][4];
#pragma unroll
        for (int nt = 0; nt < 4; nt++)
#pragma unroll
            for (int i = 0; i < 4; i++) c[nt][i] = 0.f;

#pragma unroll
        for (int s2 = 0; s2 < 4; s2++) {
            const int kk2 = s2 * 8;
            const uint32_t* ka = Kh + (kr0 + g) * 36 + kk2 + tg;
            const uint32_t* ka_l = Kl + (kr0 + g) * 36 + kk2 + tg;
            uint32_t kh0 = ka[0], kh1 = ka[8 * 36], kh2 = ka[4], kh3 = ka[8 * 36 + 4];
            uint32_t kl0 = ka_l[0], kl1 = ka_l[8 * 36], kl2 = ka_l[4], kl3 = ka_l[8 * 36 + 4];
#pragma unroll
            for (int nt = 0; nt < 4; nt++) {
                const int brow = (qc0 + nt * 8 + g) * 36 + kk2 + tg;
                uint32_t bh0 = Qh[brow], bh1 = Qh[brow + 4];
                uint32_t bl0 = Ql[brow], bl1 = Ql[brow + 4];
                mma_bf16(c[nt], kh0, kh1, kh2, kh3, bl0, bl1);
                mma_bf16(c[nt], kl0, kl1, kl2, kl3, bh0, bh1);
                mma_bf16(c[nt], kh0, kh1, kh2, kh3, bh0, bh1);
            }
        }

#pragma unroll
        for (int nt = 0; nt < 4; nt++) {
            const int qg0 = qt * 64 + qc0 + nt * 8 + 2 * tg;
            const int qg1 = qg0 + 1;
            const float mq0 = gm[bhT + qg0], mq1 = gm[bhT + qg1];
            const float rq0 = gl[bhT + qg0], rq1 = gl[bhT + qg1];
            if (qg0 >= kg0) imp0 += amk0 * __expf(fmaf(c[nt][0], scale, -mq0)) * rq0;
            if (qg1 >= kg0) imp0 += amk0 * __expf(fmaf(c[nt][1], scale, -mq1)) * rq1;
            if (qg0 >= kg1) imp1 += amk1 * __expf(fmaf(c[nt][2], scale, -mq0)) * rq0;
            if (qg1 >= kg1) imp1 += amk1 * __expf(fmaf(c[nt][3], scale, -mq1)) * rq1;
        }
    }

    imp0 += __shfl_xor_sync(0xffffffffu, imp0, 1);
    imp0 += __shfl_xor_sync(0xffffffffu, imp0, 2);
    imp1 += __shfl_xor_sync(0xffffffffu, imp1, 1);
    imp1 += __shfl_xor_sync(0xffffffffu, imp1, 2);
    if (tg == 0) {
        part[qh_][kr0 + g] = imp0;
        part[qh_][kr0 + 8 + g] = imp1;
    }
    __syncthreads();
    if (tid < 64)
        impH[bhT + kt * 64 + tid] = part[0][tid] + part[1][tid];
}

// ---------------------------------------------------------------------------
// Finalize pruning mask
// ---------------------------------------------------------------------------
__global__ __launch_bounds__(256) void finalize_mask(
    const float* __restrict__ impH, const float* __restrict__ attmask,
    const float* __restrict__ prot, const float* __restrict__ thresh,
    float* __restrict__ cm, float* __restrict__ out_mask,
    float* __restrict__ out_loss)
{
    int i = blockIdx.x * 256 + threadIdx.x;
    int b = i / T_, t = i % T_;
    float s = 0.f;
#pragma unroll
    for (int h = 0; h < H_; h++) s += impH[(b * H_ + h) * T_ + t];
    float imp = s * (1.f / ((float)H_ * (float)T_));
    float pm = (imp >= thresh[0]) ? 1.f : 0.f;
    if (prot[i] > 0.f) pm = 1.f;
    float c = attmask[i] * pm;
    cm[i] = c;
    out_mask[i] = c;
    if (i == 0) out_loss[0] = 0.f;
}

// ---------------------------------------------------------------------------
// Launch
// ---------------------------------------------------------------------------
extern "C" void kernel_launch(void* const* d_in, const int* in_sizes, int n_in,
                              void* d_out, int out_size)
{
    const float* x              = (const float*)d_in[0];
    const float* attention_mask = (const float*)d_in[1];
    const float* protected_mask = (const float*)d_in[2];
    const float* ln1_w          = (const float*)d_in[3];
    const float* ln1_b          = (const float*)d_in[4];
    const float* c_attn_w       = (const float*)d_in[5];
    const float* c_attn_b       = (const float*)d_in[6];
    const float* c_proj_w       = (const float*)d_in[7];
    const float* c_proj_b       = (const float*)d_in[8];
    const float* ln2_w          = (const float*)d_in[9];
    const float* ln2_b          = (const float*)d_in[10];
    const float* fc_w           = (const float*)d_in[11];
    const float* fc_b           = (const float*)d_in[12];
    const float* fcproj_w       = (const float*)d_in[13];
    const float* fcproj_b       = (const float*)d_in[14];
    const float* threshold      = (const float*)d_in[15];

    float* out      = (float*)d_out;
    float* out_mask = out + (size_t)M_ * C_;
    float* out_loss = out_mask + M_;

    float *p_h, *p_v, *p_y, *p_m, *p_l, *p_imp, *p_cm, *p_xres, *p_fc;
    uint32_t *p_qkH, *p_qkL;
    cudaGetSymbolAddress((void**)&p_h,    g_h);
    cudaGetSymbolAddress((void**)&p_qkH,  g_qkH);
    cudaGetSymbolAddress((void**)&p_qkL,  g_qkL);
    cudaGetSymbolAddress((void**)&p_v,    g_v);
    cudaGetSymbolAddress((void**)&p_y,    g_y);
    cudaGetSymbolAddress((void**)&p_m,    g_m);
    cudaGetSymbolAddress((void**)&p_l,    g_l);
    cudaGetSymbolAddress((void**)&p_imp,  g_impH);
    cudaGetSymbolAddress((void**)&p_cm,   g_cm);
    cudaGetSymbolAddress((void**)&p_xres, g_xres);
    cudaGetSymbolAddress((void**)&p_fc,   g_fc);

    const size_t attn_smem = (size_t)(4 * 64 * 36 + 2 * 64 * 68 + 256) * 4; // 72704B
    cudaFuncSetAttribute(attn_kernel, cudaFuncAttributeMaxDynamicSharedMemorySize,
                         (int)attn_smem);

    // 1. LN1
    ln_kernel<<<M_, 256>>>(x, ln1_w, ln1_b, p_h);
    // 2a. Q,K columns: 3-term bf16 GEMM; epilogue packs hi/lo bf16x2
    gemm_tc<4,1><<<dim3(2 * C_ / 128, M_ / 128), 256>>>(
        p_h, c_attn_w, c_attn_b, nullptr, 2 * C_, C_, nullptr, nullptr,
        p_qkH, p_qkL);
    // 2b. V columns: fp16 -> g_v (float out)
    gemm_tc<0,2><<<dim3(C_ / 128, M_ / 128), 256>>>(
        p_h, c_attn_w + (size_t)(2 * C_) * C_, c_attn_b + 2 * C_, p_v,
        C_, C_, nullptr, nullptr, nullptr, nullptr);
    // 3. Flash attention -> y, (m, 1/l)
    attn_kernel<<<dim3(NT_, B_ * H_), 256, attn_smem>>>(
        p_qkH, p_qkL, p_v, attention_mask, p_y, p_m, p_l);
    // 4. Importance column sums (deterministic)
    imp_kernel<<<dim3(NT_, B_ * H_), 256>>>(
        p_qkH, p_qkL, attention_mask, p_m, p_l, p_imp);
    // 5. Combined mask
    finalize_mask<<<M_ / 256, 256>>>(p_imp, attention_mask, protected_mask,
                                     threshold, p_cm, out_mask, out_loss);
    // 6. proj + residual + prune mask, fp16
    gemm_tc<2,2><<<dim3(C_ / 128, M_ / 128), 256>>>(
        p_y, c_proj_w, c_proj_b, p_xres, C_, C_, x, p_cm, nullptr, nullptr);
    // 7. LN2
    ln_kernel<<<M_, 256>>>(p_xres, ln2_w, ln2_b, p_h);
    // 8. fc + GELU, fp16
    gemm_tc<1,2><<<dim3(4 * C_ / 128, M_ / 128), 256>>>(
        p_h, fc_w, fc_b, p_fc, 4 * C_, C_, nullptr, nullptr, nullptr, nullptr);
    // 9. fcproj + residual -> d_out, fp16
    gemm_tc<3,2><<<dim3(C_ / 128, M_ / 128), 256>>>(
        p_fc, fcproj_w, fcproj_b, out, C_, 4 * C_, p_xres, nullptr, nullptr, nullptr);
}